// round 1
// baseline (speedup 1.0000x reference)
#include <cuda_runtime.h>
#include <cstddef>

// Problem constants
#define Sq 1024
#define Bb 4
#define Dm 1024
#define Hh 16
#define DK 64
#define NR 65            // 2*MAX_REL+1
#define BH (Bb*Hh)       // 64
#define Mrows (Bb*Sq)    // 4096

// ---------------- scratch (device globals; no allocation) ----------------
__device__ float g_Q[Mrows * Dm];
__device__ float g_K[Mrows * Dm];
__device__ float g_V[Mrows * Dm];
__device__ float g_ctx[Mrows * Dm];
__device__ float g_R[BH * Sq * NR];     // Q . rel_k[r]
__device__ float g_W[BH * Sq * NR];     // bucketed attn sums
__device__ float g_attn[(size_t)BH * Sq * Sq]; // 256 MB

// ---------------- generic fp32 SGEMM: C = A[M,K] @ W[K,N] (+bias) ----------------
// 64x64 block tile, 256 threads, 4x4 per thread, BK=16
__global__ __launch_bounds__(256) void sgemm_kernel(
    const float* __restrict__ A, const float* __restrict__ Wt,
    const float* __restrict__ bias, float* __restrict__ C,
    int Mdim, int Ndim, int Kdim)
{
    __shared__ float As[16][64];   // [k][m]
    __shared__ float Bs[16][64];   // [k][n]
    const int tid = threadIdx.x;
    const int tx = tid % 16, ty = tid / 16;
    const int row0 = blockIdx.y * 64, col0 = blockIdx.x * 64;

    const int aRow = tid / 4,  aCol = (tid % 4) * 4;   // loads A (64x16) as float4 along K
    const int bRow = tid / 16, bCol = (tid % 16) * 4;  // loads W (16x64) as float4 along N

    float acc[4][4] = {};
    for (int kk = 0; kk < Kdim; kk += 16) {
        float4 av = *(const float4*)&A[(size_t)(row0 + aRow) * Kdim + kk + aCol];
        As[aCol + 0][aRow] = av.x; As[aCol + 1][aRow] = av.y;
        As[aCol + 2][aRow] = av.z; As[aCol + 3][aRow] = av.w;
        float4 bv = *(const float4*)&Wt[(size_t)(kk + bRow) * Ndim + col0 + bCol];
        *(float4*)&Bs[bRow][bCol] = bv;
        __syncthreads();
        #pragma unroll
        for (int k = 0; k < 16; k++) {
            float a[4], b[4];
            #pragma unroll
            for (int i = 0; i < 4; i++) a[i] = As[k][ty * 4 + i];
            #pragma unroll
            for (int j = 0; j < 4; j++) b[j] = Bs[k][tx * 4 + j];
            #pragma unroll
            for (int i = 0; i < 4; i++)
                #pragma unroll
                for (int j = 0; j < 4; j++) acc[i][j] += a[i] * b[j];
        }
        __syncthreads();
    }
    #pragma unroll
    for (int i = 0; i < 4; i++) {
        int r = row0 + ty * 4 + i;
        #pragma unroll
        for (int j = 0; j < 4; j++) {
            int c = col0 + tx * 4 + j;
            float v = acc[i][j];
            if (bias) v += bias[c];
            C[(size_t)r * Ndim + c] = v;
        }
    }
}

// ---------------- R[bh,i,r] = dot(Q[b,i,h*64:], rel_k[r,:]) ----------------
__global__ __launch_bounds__(256) void relk_kernel(const float* __restrict__ rel_k)
{
    __shared__ float Qs[16][DK];
    __shared__ float RKs[NR][DK];
    const int bh = blockIdx.y;
    const int b = bh / Hh, h = bh % Hh;
    const int i0 = blockIdx.x * 16;
    const int tid = threadIdx.x;

    for (int idx = tid; idx < 16 * DK; idx += 256) {
        int r = idx / DK, c = idx % DK;
        Qs[r][c] = g_Q[(size_t)(b * Sq + i0 + r) * Dm + h * DK + c];
    }
    for (int idx = tid; idx < NR * DK; idx += 256) {
        RKs[idx / DK][idx % DK] = rel_k[idx];
    }
    __syncthreads();
    for (int idx = tid; idx < 16 * NR; idx += 256) {
        int il = idx / NR, r = idx % NR;
        float s = 0.f;
        #pragma unroll
        for (int d = 0; d < DK; d++) s += Qs[il][d] * RKs[r][d];
        g_R[(size_t)(bh * Sq + i0 + il) * NR + r] = s;
    }
}

// ---------------- scores = QK^T/scale + R[rel_idx] -> g_attn ----------------
__global__ __launch_bounds__(256) void scores_kernel()
{
    __shared__ float Qs[64][DK + 1];
    __shared__ float Ks[64][DK + 1];
    const int bh = blockIdx.z;
    const int b = bh / Hh, h = bh % Hh;
    const int i0 = blockIdx.y * 64, j0 = blockIdx.x * 64;
    const int tid = threadIdx.x;
    const int tx = tid % 16, ty = tid / 16;

    for (int idx = tid; idx < 64 * DK; idx += 256) {
        int r = idx / DK, c = idx % DK;
        Qs[r][c] = g_Q[(size_t)(b * Sq + i0 + r) * Dm + h * DK + c];
        Ks[r][c] = g_K[(size_t)(b * Sq + j0 + r) * Dm + h * DK + c];
    }
    __syncthreads();

    float acc[4][4] = {};
    #pragma unroll
    for (int k = 0; k < DK; k++) {
        float a[4], bv[4];
        #pragma unroll
        for (int i = 0; i < 4; i++) a[i] = Qs[ty * 4 + i][k];
        #pragma unroll
        for (int j = 0; j < 4; j++) bv[j] = Ks[tx * 4 + j][k];
        #pragma unroll
        for (int i = 0; i < 4; i++)
            #pragma unroll
            for (int j = 0; j < 4; j++) acc[i][j] += a[i] * bv[j];
    }
    const float inv_scale = 0.125f; // 1/sqrt(64)
    #pragma unroll
    for (int i = 0; i < 4; i++) {
        int ii = i0 + ty * 4 + i;
        #pragma unroll
        for (int j = 0; j < 4; j++) {
            int jj = j0 + tx * 4 + j;
            int rel = jj - ii;
            rel = (rel < -32 ? -32 : (rel > 32 ? 32 : rel)) + 32;
            float v = acc[i][j] * inv_scale + g_R[(size_t)(bh * Sq + ii) * NR + rel];
            g_attn[((size_t)bh * Sq + ii) * Sq + jj] = v;
        }
    }
}

// ---------------- row softmax (in place) + bucket sums W ----------------
__global__ __launch_bounds__(256) void softmax_kernel()
{
    const int rowid = blockIdx.x;       // bh*S + i
    const int i = rowid % Sq;
    float* row = &g_attn[(size_t)rowid * Sq];
    const int tid = threadIdx.x;

    __shared__ float red[256];
    __shared__ float sW[NR];

    float v[4];
    float mx = -1e30f;
    #pragma unroll
    for (int l = 0; l < 4; l++) { v[l] = row[tid + l * 256]; mx = fmaxf(mx, v[l]); }
    red[tid] = mx; __syncthreads();
    for (int s2 = 128; s2 > 0; s2 >>= 1) { if (tid < s2) red[tid] = fmaxf(red[tid], red[tid + s2]); __syncthreads(); }
    mx = red[0]; __syncthreads();

    float sum = 0.f;
    #pragma unroll
    for (int l = 0; l < 4; l++) { v[l] = expf(v[l] - mx); sum += v[l]; }
    red[tid] = sum; __syncthreads();
    for (int s2 = 128; s2 > 0; s2 >>= 1) { if (tid < s2) red[tid] += red[tid + s2]; __syncthreads(); }
    const float inv = 1.f / red[0]; __syncthreads();

    if (tid < NR) sW[tid] = 0.f;
    __syncthreads();

    float lowsum = 0.f, highsum = 0.f;
    #pragma unroll
    for (int l = 0; l < 4; l++) {
        int j = tid + l * 256;
        float p = v[l] * inv;
        row[j] = p;
        int d = j - i;
        if (d <= -32)       lowsum  += p;
        else if (d >= 32)   highsum += p;
        else                sW[d + 32] = p;   // unique j per d in (-31,31]
    }
    red[tid] = lowsum; __syncthreads();
    for (int s2 = 128; s2 > 0; s2 >>= 1) { if (tid < s2) red[tid] += red[tid + s2]; __syncthreads(); }
    float lowT = red[0]; __syncthreads();
    red[tid] = highsum; __syncthreads();
    for (int s2 = 128; s2 > 0; s2 >>= 1) { if (tid < s2) red[tid] += red[tid + s2]; __syncthreads(); }
    float highT = red[0]; __syncthreads();
    if (tid == 0) { sW[0] = lowT; sW[64] = highT; }
    __syncthreads();
    if (tid < NR) g_W[(size_t)rowid * NR + tid] = sW[tid];
}

// ---------------- attn mean over heads ----------------
__global__ __launch_bounds__(256) void mean_kernel(float* __restrict__ out2)
{
    size_t idx = (size_t)blockIdx.x * 256 + threadIdx.x;   // over B*S*S
    int b = (int)(idx / ((size_t)Sq * Sq));
    size_t rem = idx % ((size_t)Sq * Sq);
    const float* base = &g_attn[((size_t)b * Hh) * Sq * Sq + rem];
    float s = 0.f;
    #pragma unroll
    for (int h = 0; h < Hh; h++) s += base[(size_t)h * Sq * Sq];
    out2[idx] = s * (1.0f / Hh);
}

// ---------------- ctx = attn @ V + W @ rel_v  (per head) ----------------
__global__ __launch_bounds__(256) void ctx_kernel(const float* __restrict__ rel_v)
{
    __shared__ float As[64][33];   // [i][k]
    __shared__ float Vs[32][65];   // [k][d]
    const int bh = blockIdx.y;
    const int b = bh / Hh, h = bh % Hh;
    const int i0 = blockIdx.x * 64;
    const int tid = threadIdx.x;
    const int tx = tid % 16, ty = tid / 16;

    float acc[4][4] = {};
    const float* attnBase = &g_attn[((size_t)bh * Sq + i0) * Sq];

    for (int kb = 0; kb < Sq; kb += 32) {
        for (int idx = tid; idx < 64 * 32; idx += 256) {
            int r = idx / 32, c = idx % 32;
            As[r][c] = attnBase[(size_t)r * Sq + kb + c];
        }
        for (int idx = tid; idx < 32 * 64; idx += 256) {
            int r = idx / 64, c = idx % 64;
            Vs[r][c] = g_V[(size_t)(b * Sq + kb + r) * Dm + h * DK + c];
        }
        __syncthreads();
        #pragma unroll
        for (int k = 0; k < 32; k++) {
            float a[4], bv[4];
            #pragma unroll
            for (int i = 0; i < 4; i++) a[i] = As[ty * 4 + i][k];
            #pragma unroll
            for (int j = 0; j < 4; j++) bv[j] = Vs[k][tx * 4 + j];
            #pragma unroll
            for (int i = 0; i < 4; i++)
                #pragma unroll
                for (int j = 0; j < 4; j++) acc[i][j] += a[i] * bv[j];
        }
        __syncthreads();
    }

    // + W @ rel_v   (K2 = 65, zero-padded chunks of 32)
    const float* Wbase = &g_W[(size_t)(bh * Sq + i0) * NR];
    for (int rb = 0; rb < NR; rb += 32) {
        int cnt = NR - rb; if (cnt > 32) cnt = 32;
        for (int idx = tid; idx < 64 * 32; idx += 256) {
            int r = idx / 32, c = idx % 32;
            As[r][c] = (c < cnt) ? Wbase[(size_t)r * NR + rb + c] : 0.f;
        }
        for (int idx = tid; idx < 32 * 64; idx += 256) {
            int r = idx / 64, c = idx % 64;
            Vs[r][c] = (r < cnt) ? rel_v[(rb + r) * DK + c] : 0.f;
        }
        __syncthreads();
        #pragma unroll
        for (int k = 0; k < 32; k++) {
            float a[4], bv[4];
            #pragma unroll
            for (int i = 0; i < 4; i++) a[i] = As[ty * 4 + i][k];
            #pragma unroll
            for (int j = 0; j < 4; j++) bv[j] = Vs[k][tx * 4 + j];
            #pragma unroll
            for (int i = 0; i < 4; i++)
                #pragma unroll
                for (int j = 0; j < 4; j++) acc[i][j] += a[i] * bv[j];
        }
        __syncthreads();
    }

    #pragma unroll
    for (int i = 0; i < 4; i++) {
        int r = i0 + ty * 4 + i;
        #pragma unroll
        for (int j = 0; j < 4; j++) {
            g_ctx[(size_t)(b * Sq + r) * Dm + h * DK + tx * 4 + j] = acc[i][j];
        }
    }
}

// ---------------- launch ----------------
extern "C" void kernel_launch(void* const* d_in, const int* in_sizes, int n_in,
                              void* d_out, int out_size)
{
    const float* query = (const float*)d_in[0];
    const float* key   = (const float*)d_in[1];
    const float* value = (const float*)d_in[2];
    const float* Wq    = (const float*)d_in[3];
    const float* Wk    = (const float*)d_in[4];
    const float* Wv    = (const float*)d_in[5];
    const float* Wo    = (const float*)d_in[6];
    const float* bo    = (const float*)d_in[7];
    const float* rel_k = (const float*)d_in[8];
    const float* rel_v = (const float*)d_in[9];

    float* out      = (float*)d_out;                         // [B,S,D]
    float* out_attn = out + (size_t)Bb * Sq * Dm;            // [B,S,S]

    float *pQ, *pK, *pV, *pCtx;
    cudaGetSymbolAddress((void**)&pQ,   g_Q);
    cudaGetSymbolAddress((void**)&pK,   g_K);
    cudaGetSymbolAddress((void**)&pV,   g_V);
    cudaGetSymbolAddress((void**)&pCtx, g_ctx);

    dim3 gProj(Dm / 64, Mrows / 64);   // (16, 64)

    // 1. projections
    sgemm_kernel<<<gProj, 256>>>(query, Wq, nullptr, pQ, Mrows, Dm, Dm);
    sgemm_kernel<<<gProj, 256>>>(key,   Wk, nullptr, pK, Mrows, Dm, Dm);
    sgemm_kernel<<<gProj, 256>>>(value, Wv, nullptr, pV, Mrows, Dm, Dm);

    // 2. rel_k scores R
    relk_kernel<<<dim3(Sq / 16, BH), 256>>>(rel_k);

    // 3. scores + rel bias -> g_attn
    scores_kernel<<<dim3(Sq / 64, Sq / 64, BH), 256>>>();

    // 4. softmax + bucket sums
    softmax_kernel<<<BH * Sq, 256>>>();

    // 5. head mean
    mean_kernel<<<(unsigned)(((size_t)Bb * Sq * Sq) / 256), 256>>>(out_attn);

    // 6. context = attn@V + W@rel_v
    ctx_kernel<<<dim3(Sq / 64, BH), 256>>>(rel_v);

    // 7. output projection + bias
    sgemm_kernel<<<gProj, 256>>>(pCtx, Wo, bo, out, Mrows, Dm, Dm);
}

// round 3
// speedup vs baseline: 2.4086x; 2.4086x over previous
#include <cuda_runtime.h>
#include <cstdint>
#include <cstddef>

#define Sq 1024
#define Bb 4
#define Dm 1024
#define Hh 16
#define DK 64
#define NR 65
#define WPAD 96
#define BH (Bb*Hh)
#define Mrows (Bb*Sq)

// ---------------- scratch (device globals; no allocation) ----------------
__device__ float g_Q[(size_t)Mrows * Dm];
__device__ float g_K[(size_t)Mrows * Dm];
__device__ float g_V[(size_t)Mrows * Dm];
__device__ float g_ctx[(size_t)Mrows * Dm];
__device__ float g_Rt[(size_t)BH * NR * Sq];        // R transposed: [bh][r][i]
__device__ float g_W[(size_t)BH * Sq * WPAD];       // bucketed attn sums, padded to 96
__device__ float g_attn[(size_t)BH * Sq * Sq];      // 256 MB

// ---------------- tf32 helpers ----------------
__device__ __forceinline__ uint32_t f2tf(float x) {
    uint32_t u; asm("cvt.rna.tf32.f32 %0, %1;" : "=r"(u) : "f"(x)); return u;
}
__device__ __forceinline__ void mma8(float4& d, const uint32_t* a, const uint32_t* b) {
    asm volatile("mma.sync.aligned.m16n8k8.row.col.f32.tf32.tf32.f32 "
                 "{%0,%1,%2,%3},{%4,%5,%6,%7},{%8,%9},{%0,%1,%2,%3};"
                 : "+f"(d.x), "+f"(d.y), "+f"(d.z), "+f"(d.w)
                 : "r"(a[0]), "r"(a[1]), "r"(a[2]), "r"(a[3]), "r"(b[0]), "r"(b[1]));
}

// =====================================================================
// Generic 1024x1024 K=1024 GEMM body: C[4096,1024] tile = A @ W (+bias)
// BM=128, BN=64, BK=32, 256 threads (8 warps, 2x4), warp tile 64x16
// =====================================================================
__device__ __forceinline__ void gemm_body(const float* __restrict__ A,
                                          const float* __restrict__ W,
                                          const float* __restrict__ bias,
                                          float* __restrict__ C)
{
    __shared__ uint32_t As[128][36];   // [m][k], pad->conflict-free frags
    __shared__ uint32_t Bs[32][72];    // [k][n]

    const int tid  = threadIdx.x;
    const int lane = tid & 31;
    const int wid  = tid >> 5;
    const int g = lane >> 2, t = lane & 3;
    const int wm = (wid >> 2) * 64;
    const int wn = (wid & 3) * 16;
    const int row0 = blockIdx.y * 128, col0 = blockIdx.x * 64;

    const int aRow = tid >> 3,  aCol = (tid & 7)  * 4;
    const int bRow = tid >> 4,  bCol = (tid & 15) * 4;

    float4 ar[4], br[2];

    auto ldg = [&](int kb) {
        #pragma unroll
        for (int p = 0; p < 4; p++)
            ar[p] = *(const float4*)&A[(size_t)(row0 + aRow + 32 * p) * 1024 + kb + aCol];
        #pragma unroll
        for (int p = 0; p < 2; p++)
            br[p] = *(const float4*)&W[(size_t)(kb + bRow + 16 * p) * 1024 + col0 + bCol];
    };
    auto sts = [&]() {
        #pragma unroll
        for (int p = 0; p < 4; p++) {
            uint4 u = make_uint4(f2tf(ar[p].x), f2tf(ar[p].y), f2tf(ar[p].z), f2tf(ar[p].w));
            *(uint4*)&As[aRow + 32 * p][aCol] = u;
        }
        #pragma unroll
        for (int p = 0; p < 2; p++) {
            uint4 u = make_uint4(f2tf(br[p].x), f2tf(br[p].y), f2tf(br[p].z), f2tf(br[p].w));
            *(uint4*)&Bs[bRow + 16 * p][bCol] = u;
        }
    };

    float4 acc[4][2];
    #pragma unroll
    for (int i = 0; i < 4; i++)
        #pragma unroll
        for (int j = 0; j < 2; j++) acc[i][j] = make_float4(0.f, 0.f, 0.f, 0.f);

    ldg(0); sts(); __syncthreads();

    #pragma unroll 1
    for (int kb = 0; kb < 1024; kb += 32) {
        const bool nxt = (kb + 32) < 1024;
        if (nxt) ldg(kb + 32);
        #pragma unroll
        for (int ks = 0; ks < 4; ks++) {
            const int k0 = ks * 8;
            uint32_t af[4][4], bf[2][2];
            #pragma unroll
            for (int ma = 0; ma < 4; ma++) {
                const int m = wm + ma * 16 + g;
                af[ma][0] = As[m][k0 + t];     af[ma][1] = As[m + 8][k0 + t];
                af[ma][2] = As[m][k0 + t + 4]; af[ma][3] = As[m + 8][k0 + t + 4];
            }
            #pragma unroll
            for (int na = 0; na < 2; na++) {
                const int n = wn + na * 8 + g;
                bf[na][0] = Bs[k0 + t][n]; bf[na][1] = Bs[k0 + t + 4][n];
            }
            #pragma unroll
            for (int ma = 0; ma < 4; ma++)
                #pragma unroll
                for (int na = 0; na < 2; na++)
                    mma8(acc[ma][na], af[ma], bf[na]);
        }
        __syncthreads();
        if (nxt) { sts(); __syncthreads(); }
    }

    #pragma unroll
    for (int ma = 0; ma < 4; ma++) {
        const int r = row0 + wm + ma * 16 + g;
        #pragma unroll
        for (int na = 0; na < 2; na++) {
            const int c = col0 + wn + na * 8 + 2 * t;
            float bx = 0.f, by = 0.f;
            if (bias) { bx = bias[c]; by = bias[c + 1]; }
            C[(size_t)r * 1024 + c]           = acc[ma][na].x + bx;
            C[(size_t)r * 1024 + c + 1]       = acc[ma][na].y + by;
            C[(size_t)(r + 8) * 1024 + c]     = acc[ma][na].z + bx;
            C[(size_t)(r + 8) * 1024 + c + 1] = acc[ma][na].w + by;
        }
    }
}

// three projections in one launch (z selects matrix)
__global__ __launch_bounds__(256, 2) void proj3_kernel(
    const float* __restrict__ q, const float* __restrict__ k, const float* __restrict__ v,
    const float* __restrict__ Wq, const float* __restrict__ Wk, const float* __restrict__ Wv)
{
    const int z = blockIdx.z;
    const float* A = (z == 0) ? q : (z == 1) ? k : v;
    const float* W = (z == 0) ? Wq : (z == 1) ? Wk : Wv;
    float* C = (z == 0) ? g_Q : (z == 1) ? g_K : g_V;
    gemm_body(A, W, nullptr, C);
}

__global__ __launch_bounds__(256, 2) void outproj_kernel(
    const float* __restrict__ Wo, const float* __restrict__ bo, float* __restrict__ out)
{
    gemm_body(g_ctx, Wo, bo, out);
}

// =====================================================================
// relk: Rt[bh][r][i] = dot(Q[b,i,h*64:], rel_k[r,:]) — coalesced stores
// =====================================================================
__global__ __launch_bounds__(128) void relk_kernel(const float* __restrict__ rel_k)
{
    __shared__ float4 RK[NR][16];
    const int bh = blockIdx.y;
    const int b = bh >> 4, h = bh & 15;
    const int i0 = blockIdx.x * 128;
    const int tid = threadIdx.x;

    for (int idx = tid; idx < NR * 16; idx += 128)
        RK[idx / 16][idx % 16] = ((const float4*)rel_k)[idx];
    __syncthreads();

    float4 q[16];
    const float4* qrow = (const float4*)&g_Q[(size_t)(b * Sq + i0 + tid) * Dm + h * DK];
    #pragma unroll
    for (int d = 0; d < 16; d++) q[d] = qrow[d];

    float* outp = &g_Rt[(size_t)bh * NR * Sq + i0 + tid];
    #pragma unroll 1
    for (int r = 0; r < NR; r++) {
        float s = 0.f;
        #pragma unroll
        for (int d = 0; d < 16; d++) {
            float4 rk = RK[r][d];
            s += q[d].x * rk.x + q[d].y * rk.y + q[d].z * rk.z + q[d].w * rk.w;
        }
        outp[(size_t)r * Sq] = s;
    }
}

// =====================================================================
// scores: g_attn = QK^T/8 + Rt[rel]    (tf32 mma, BM=BN=64, K=64)
// 256 threads, 8 warps 2x4, warp tile 32x16
// =====================================================================
__global__ __launch_bounds__(256, 2) void scores_kernel()
{
    __shared__ uint32_t Qs[64][68];   // [m][k]
    __shared__ uint32_t Ks[64][68];   // [n][k]

    const int bh = blockIdx.z;
    const int b = bh >> 4, h = bh & 15;
    const int i0 = blockIdx.y * 64, j0 = blockIdx.x * 64;
    const int tid = threadIdx.x;
    const int lane = tid & 31, wid = tid >> 5;
    const int g = lane >> 2, t = lane & 3;
    const int wm = (wid >> 2) * 32;
    const int wn = (wid & 3) * 16;

    const int lr = tid >> 4, lc = (tid & 15) * 4;
    #pragma unroll
    for (int p = 0; p < 4; p++) {
        float4 qv = *(const float4*)&g_Q[(size_t)(b * Sq + i0 + lr + 16 * p) * Dm + h * DK + lc];
        *(uint4*)&Qs[lr + 16 * p][lc] = make_uint4(f2tf(qv.x), f2tf(qv.y), f2tf(qv.z), f2tf(qv.w));
        float4 kv = *(const float4*)&g_K[(size_t)(b * Sq + j0 + lr + 16 * p) * Dm + h * DK + lc];
        *(uint4*)&Ks[lr + 16 * p][lc] = make_uint4(f2tf(kv.x), f2tf(kv.y), f2tf(kv.z), f2tf(kv.w));
    }
    __syncthreads();

    float4 acc[2][2];
    #pragma unroll
    for (int i = 0; i < 2; i++)
        #pragma unroll
        for (int j = 0; j < 2; j++) acc[i][j] = make_float4(0.f, 0.f, 0.f, 0.f);

    #pragma unroll
    for (int ks = 0; ks < 8; ks++) {
        const int k0 = ks * 8;
        uint32_t af[2][4], bf[2][2];
        #pragma unroll
        for (int ma = 0; ma < 2; ma++) {
            const int m = wm + ma * 16 + g;
            af[ma][0] = Qs[m][k0 + t];     af[ma][1] = Qs[m + 8][k0 + t];
            af[ma][2] = Qs[m][k0 + t + 4]; af[ma][3] = Qs[m + 8][k0 + t + 4];
        }
        #pragma unroll
        for (int na = 0; na < 2; na++) {
            const int n = wn + na * 8 + g;
            bf[na][0] = Ks[n][k0 + t]; bf[na][1] = Ks[n][k0 + t + 4];
        }
        #pragma unroll
        for (int ma = 0; ma < 2; ma++)
            #pragma unroll
            for (int na = 0; na < 2; na++)
                mma8(acc[ma][na], af[ma], bf[na]);
    }

    const float* Rt = &g_Rt[(size_t)bh * NR * Sq];
    float* attnBase = &g_attn[(size_t)bh * Sq * Sq];
    #pragma unroll
    for (int ma = 0; ma < 2; ma++) {
        const int ia = i0 + wm + ma * 16 + g;
        #pragma unroll
        for (int na = 0; na < 2; na++) {
            const int ja = j0 + wn + na * 8 + 2 * t;
            #pragma unroll
            for (int e = 0; e < 4; e++) {
                const int ii = ia + (e >= 2 ? 8 : 0);
                const int jj = ja + (e & 1);
                int rel = jj - ii;
                rel = (rel < -32 ? -32 : (rel > 32 ? 32 : rel)) + 32;
                const float v = (e == 0 ? acc[ma][na].x : e == 1 ? acc[ma][na].y :
                                 e == 2 ? acc[ma][na].z : acc[ma][na].w);
                attnBase[(size_t)ii * Sq + jj] = v * 0.125f + Rt[(size_t)rel * Sq + ii];
            }
        }
    }
}

// =====================================================================
// softmax (in place) + padded bucket sums W
// =====================================================================
__global__ __launch_bounds__(256) void softmax_kernel()
{
    const int rowid = blockIdx.x;       // bh*S + i
    const int i = rowid & (Sq - 1);
    float* row = &g_attn[(size_t)rowid * Sq];
    const int tid = threadIdx.x;

    __shared__ float red[256];
    __shared__ float sW[NR];

    float v[4];
    float mx = -1e30f;
    #pragma unroll
    for (int l = 0; l < 4; l++) { v[l] = row[tid + l * 256]; mx = fmaxf(mx, v[l]); }
    red[tid] = mx; __syncthreads();
    for (int s2 = 128; s2 > 0; s2 >>= 1) { if (tid < s2) red[tid] = fmaxf(red[tid], red[tid + s2]); __syncthreads(); }
    mx = red[0]; __syncthreads();

    float sum = 0.f;
    #pragma unroll
    for (int l = 0; l < 4; l++) { v[l] = __expf(v[l] - mx); sum += v[l]; }
    red[tid] = sum; __syncthreads();
    for (int s2 = 128; s2 > 0; s2 >>= 1) { if (tid < s2) red[tid] += red[tid + s2]; __syncthreads(); }
    const float inv = 1.f / red[0]; __syncthreads();

    if (tid < NR) sW[tid] = 0.f;
    __syncthreads();

    float lowsum = 0.f, highsum = 0.f;
    #pragma unroll
    for (int l = 0; l < 4; l++) {
        const int j = tid + l * 256;
        const float p = v[l] * inv;
        row[j] = p;
        const int d = j - i;
        if (d <= -32)      lowsum  += p;
        else if (d >= 32)  highsum += p;
        else               sW[d + 32] = p;
    }
    red[tid] = lowsum; __syncthreads();
    for (int s2 = 128; s2 > 0; s2 >>= 1) { if (tid < s2) red[tid] += red[tid + s2]; __syncthreads(); }
    const float lowT = red[0]; __syncthreads();
    red[tid] = highsum; __syncthreads();
    for (int s2 = 128; s2 > 0; s2 >>= 1) { if (tid < s2) red[tid] += red[tid + s2]; __syncthreads(); }
    const float highT = red[0]; __syncthreads();
    if (tid == 0) { sW[0] = lowT; sW[64] = highT; }
    __syncthreads();
    if (tid < WPAD) {
        float w = (tid < NR) ? sW[tid] : 0.f;
        g_W[(size_t)rowid * WPAD + tid] = w;
    }
}

// ---------------- attn mean over heads ----------------
__global__ __launch_bounds__(256) void mean_kernel(float* __restrict__ out2)
{
    const size_t idx = (size_t)blockIdx.x * 256 + threadIdx.x;
    const int b = (int)(idx / ((size_t)Sq * Sq));
    const size_t rem = idx % ((size_t)Sq * Sq);
    const float* base = &g_attn[((size_t)b * Hh) * Sq * Sq + rem];
    float s = 0.f;
    #pragma unroll
    for (int h = 0; h < Hh; h++) s += base[(size_t)h * Sq * Sq];
    out2[idx] = s * (1.0f / Hh);
}

// =====================================================================
// ctx = attn @ V + W @ rel_v   (tf32 mma; BM=128, BN=64, BK=32; 35 k-blocks)
// =====================================================================
__global__ __launch_bounds__(256, 2) void ctx_kernel(const float* __restrict__ rel_v)
{
    __shared__ uint32_t As[128][36];
    __shared__ uint32_t Bs[32][72];

    const int bh = blockIdx.y;
    const int b = bh >> 4, h = bh & 15;
    const int i0 = blockIdx.x * 128;
    const int tid = threadIdx.x;
    const int lane = tid & 31, wid = tid >> 5;
    const int g = lane >> 2, t = lane & 3;
    const int wm = (wid >> 2) * 64;
    const int wn = (wid & 3) * 16;

    const int aRow = tid >> 3,  aCol = (tid & 7)  * 4;
    const int bRow = tid >> 4,  bCol = (tid & 15) * 4;

    const float* attnBase = &g_attn[((size_t)bh * Sq + i0) * Sq];
    const float* wBase    = &g_W[(size_t)(bh * Sq + i0) * WPAD];

    float4 ar[4], br[2];

    auto ldg = [&](int kt) {
        if (kt < 32) {
            const int kb = kt * 32;
            #pragma unroll
            for (int p = 0; p < 4; p++)
                ar[p] = *(const float4*)&attnBase[(size_t)(aRow + 32 * p) * Sq + kb + aCol];
            #pragma unroll
            for (int p = 0; p < 2; p++)
                br[p] = *(const float4*)&g_V[(size_t)(b * Sq + kb + bRow + 16 * p) * Dm + h * DK + bCol];
        } else {
            const int kk = (kt - 32) * 32;
            #pragma unroll
            for (int p = 0; p < 4; p++)
                ar[p] = *(const float4*)&wBase[(size_t)(aRow + 32 * p) * WPAD + kk + aCol];
            #pragma unroll
            for (int p = 0; p < 2; p++) {
                const int rr = kk + bRow + 16 * p;
                br[p] = (rr < NR) ? *(const float4*)&rel_v[rr * DK + bCol]
                                  : make_float4(0.f, 0.f, 0.f, 0.f);
            }
        }
    };
    auto sts = [&]() {
        #pragma unroll
        for (int p = 0; p < 4; p++) {
            uint4 u = make_uint4(f2tf(ar[p].x), f2tf(ar[p].y), f2tf(ar[p].z), f2tf(ar[p].w));
            *(uint4*)&As[aRow + 32 * p][aCol] = u;
        }
        #pragma unroll
        for (int p = 0; p < 2; p++) {
            uint4 u = make_uint4(f2tf(br[p].x), f2tf(br[p].y), f2tf(br[p].z), f2tf(br[p].w));
            *(uint4*)&Bs[bRow + 16 * p][bCol] = u;
        }
    };

    float4 acc[4][2];
    #pragma unroll
    for (int i = 0; i < 4; i++)
        #pragma unroll
        for (int j = 0; j < 2; j++) acc[i][j] = make_float4(0.f, 0.f, 0.f, 0.f);

    ldg(0); sts(); __syncthreads();

    #pragma unroll 1
    for (int kt = 0; kt < 35; kt++) {
        const bool nxt = (kt + 1) < 35;
        if (nxt) ldg(kt + 1);
        #pragma unroll
        for (int ks = 0; ks < 4; ks++) {
            const int k0 = ks * 8;
            uint32_t af[4][4], bf[2][2];
            #pragma unroll
            for (int ma = 0; ma < 4; ma++) {
                const int m = wm + ma * 16 + g;
                af[ma][0] = As[m][k0 + t];     af[ma][1] = As[m + 8][k0 + t];
                af[ma][2] = As[m][k0 + t + 4]; af[ma][3] = As[m + 8][k0 + t + 4];
            }
            #pragma unroll
            for (int na = 0; na < 2; na++) {
                const int n = wn + na * 8 + g;
                bf[na][0] = Bs[k0 + t][n]; bf[na][1] = Bs[k0 + t + 4][n];
            }
            #pragma unroll
            for (int ma = 0; ma < 4; ma++)
                #pragma unroll
                for (int na = 0; na < 2; na++)
                    mma8(acc[ma][na], af[ma], bf[na]);
        }
        __syncthreads();
        if (nxt) { sts(); __syncthreads(); }
    }

    #pragma unroll
    for (int ma = 0; ma < 4; ma++) {
        const int r = i0 + wm + ma * 16 + g;
        #pragma unroll
        for (int na = 0; na < 2; na++) {
            const int c = wn + na * 8 + 2 * t;
            g_ctx[(size_t)(b * Sq + r) * Dm + h * DK + c]           = acc[ma][na].x;
            g_ctx[(size_t)(b * Sq + r) * Dm + h * DK + c + 1]       = acc[ma][na].y;
            g_ctx[(size_t)(b * Sq + r + 8) * Dm + h * DK + c]       = acc[ma][na].z;
            g_ctx[(size_t)(b * Sq + r + 8) * Dm + h * DK + c + 1]   = acc[ma][na].w;
        }
    }
}

// ---------------- launch ----------------
extern "C" void kernel_launch(void* const* d_in, const int* in_sizes, int n_in,
                              void* d_out, int out_size)
{
    const float* query = (const float*)d_in[0];
    const float* key   = (const float*)d_in[1];
    const float* value = (const float*)d_in[2];
    const float* Wq    = (const float*)d_in[3];
    const float* Wk    = (const float*)d_in[4];
    const float* Wv    = (const float*)d_in[5];
    const float* Wo    = (const float*)d_in[6];
    const float* bo    = (const float*)d_in[7];
    const float* rel_k = (const float*)d_in[8];
    const float* rel_v = (const float*)d_in[9];

    float* out      = (float*)d_out;                 // [B,S,D]
    float* out_attn = out + (size_t)Bb * Sq * Dm;    // [B,S,S]

    // 1. projections (fused into one launch; z picks q/k/v)
    proj3_kernel<<<dim3(Dm / 64, Mrows / 128, 3), 256>>>(query, key, value, Wq, Wk, Wv);

    // 2. rel_k dot products (transposed output for coalesced stores)
    relk_kernel<<<dim3(Sq / 128, BH), 128>>>(rel_k);

    // 3. scores + rel bias -> g_attn
    scores_kernel<<<dim3(Sq / 64, Sq / 64, BH), 256>>>();

    // 4. softmax + bucket sums
    softmax_kernel<<<BH * Sq, 256>>>();

    // 5. head mean
    mean_kernel<<<(unsigned)(((size_t)Bb * Sq * Sq) / 256), 256>>>(out_attn);

    // 6. context = attn@V + W@rel_v
    ctx_kernel<<<dim3(Sq / 128, BH), 256>>>(rel_v);

    // 7. output projection + bias
    outproj_kernel<<<dim3(Dm / 64, Mrows / 128), 256>>>(Wo, bo, out);
}

// round 4
// speedup vs baseline: 3.0751x; 1.2767x over previous
#include <cuda_runtime.h>
#include <cstdint>
#include <cstddef>

#define Sq 1024
#define Bb 4
#define Dm 1024
#define Hh 16
#define DK 64
#define NR 65
#define WPAD 96
#define BH (Bb*Hh)
#define Mrows (Bb*Sq)
#define PBUF_PAD 1028   // float4-aligned rows (4112B), 2-way bank conflict max

// ---------------- scratch (device globals; no allocation) ----------------
__device__ float g_Q[(size_t)Mrows * Dm];
__device__ float g_K[(size_t)Mrows * Dm];
__device__ float g_V[(size_t)Mrows * Dm];
__device__ float g_ctx[(size_t)Mrows * Dm];
__device__ float g_Rt[(size_t)BH * NR * Sq];        // R transposed: [bh][r][i]
__device__ float g_W[(size_t)BH * Sq * WPAD];       // bucketed attn sums, padded to 96
__device__ float g_attn[(size_t)BH * Sq * Sq];      // 256 MB

// ---------------- tf32 helpers ----------------
__device__ __forceinline__ uint32_t f2tf(float x) {
    uint32_t u; asm("cvt.rna.tf32.f32 %0, %1;" : "=r"(u) : "f"(x)); return u;
}
__device__ __forceinline__ void mma8(float4& d, const uint32_t* a, const uint32_t* b) {
    asm volatile("mma.sync.aligned.m16n8k8.row.col.f32.tf32.tf32.f32 "
                 "{%0,%1,%2,%3},{%4,%5,%6,%7},{%8,%9},{%0,%1,%2,%3};"
                 : "+f"(d.x), "+f"(d.y), "+f"(d.z), "+f"(d.w)
                 : "r"(a[0]), "r"(a[1]), "r"(a[2]), "r"(a[3]), "r"(b[0]), "r"(b[1]));
}

// =====================================================================
// Generic 1024x1024 K=1024 GEMM body: C[4096,1024] tile = A @ W (+bias)
// BM=128, BN=64, BK=32, 256 threads (8 warps, 2x4), warp tile 64x16
// =====================================================================
__device__ __forceinline__ void gemm_body(const float* __restrict__ A,
                                          const float* __restrict__ W,
                                          const float* __restrict__ bias,
                                          float* __restrict__ C)
{
    __shared__ uint32_t As[128][36];   // [m][k], pad->conflict-free frags
    __shared__ uint32_t Bs[32][72];    // [k][n]

    const int tid  = threadIdx.x;
    const int lane = tid & 31;
    const int wid  = tid >> 5;
    const int g = lane >> 2, t = lane & 3;
    const int wm = (wid >> 2) * 64;
    const int wn = (wid & 3) * 16;
    const int row0 = blockIdx.y * 128, col0 = blockIdx.x * 64;

    const int aRow = tid >> 3,  aCol = (tid & 7)  * 4;
    const int bRow = tid >> 4,  bCol = (tid & 15) * 4;

    float4 ar[4], br[2];

    auto ldg = [&](int kb) {
        #pragma unroll
        for (int p = 0; p < 4; p++)
            ar[p] = *(const float4*)&A[(size_t)(row0 + aRow + 32 * p) * 1024 + kb + aCol];
        #pragma unroll
        for (int p = 0; p < 2; p++)
            br[p] = *(const float4*)&W[(size_t)(kb + bRow + 16 * p) * 1024 + col0 + bCol];
    };
    auto sts = [&]() {
        #pragma unroll
        for (int p = 0; p < 4; p++) {
            uint4 u = make_uint4(f2tf(ar[p].x), f2tf(ar[p].y), f2tf(ar[p].z), f2tf(ar[p].w));
            *(uint4*)&As[aRow + 32 * p][aCol] = u;
        }
        #pragma unroll
        for (int p = 0; p < 2; p++) {
            uint4 u = make_uint4(f2tf(br[p].x), f2tf(br[p].y), f2tf(br[p].z), f2tf(br[p].w));
            *(uint4*)&Bs[bRow + 16 * p][bCol] = u;
        }
    };

    float4 acc[4][2];
    #pragma unroll
    for (int i = 0; i < 4; i++)
        #pragma unroll
        for (int j = 0; j < 2; j++) acc[i][j] = make_float4(0.f, 0.f, 0.f, 0.f);

    ldg(0); sts(); __syncthreads();

    #pragma unroll 1
    for (int kb = 0; kb < 1024; kb += 32) {
        const bool nxt = (kb + 32) < 1024;
        if (nxt) ldg(kb + 32);
        #pragma unroll
        for (int ks = 0; ks < 4; ks++) {
            const int k0 = ks * 8;
            uint32_t af[4][4], bf[2][2];
            #pragma unroll
            for (int ma = 0; ma < 4; ma++) {
                const int m = wm + ma * 16 + g;
                af[ma][0] = As[m][k0 + t];     af[ma][1] = As[m + 8][k0 + t];
                af[ma][2] = As[m][k0 + t + 4]; af[ma][3] = As[m + 8][k0 + t + 4];
            }
            #pragma unroll
            for (int na = 0; na < 2; na++) {
                const int n = wn + na * 8 + g;
                bf[na][0] = Bs[k0 + t][n]; bf[na][1] = Bs[k0 + t + 4][n];
            }
            #pragma unroll
            for (int ma = 0; ma < 4; ma++)
                #pragma unroll
                for (int na = 0; na < 2; na++)
                    mma8(acc[ma][na], af[ma], bf[na]);
        }
        __syncthreads();
        if (nxt) { sts(); __syncthreads(); }
    }

    #pragma unroll
    for (int ma = 0; ma < 4; ma++) {
        const int r = row0 + wm + ma * 16 + g;
        #pragma unroll
        for (int na = 0; na < 2; na++) {
            const int c = col0 + wn + na * 8 + 2 * t;
            float bx = 0.f, by = 0.f;
            if (bias) { bx = bias[c]; by = bias[c + 1]; }
            C[(size_t)r * 1024 + c]           = acc[ma][na].x + bx;
            C[(size_t)r * 1024 + c + 1]       = acc[ma][na].y + by;
            C[(size_t)(r + 8) * 1024 + c]     = acc[ma][na].z + bx;
            C[(size_t)(r + 8) * 1024 + c + 1] = acc[ma][na].w + by;
        }
    }
}

// three projections in one launch (z selects matrix)
__global__ __launch_bounds__(256, 2) void proj3_kernel(
    const float* __restrict__ q, const float* __restrict__ k, const float* __restrict__ v,
    const float* __restrict__ Wq, const float* __restrict__ Wk, const float* __restrict__ Wv)
{
    const int z = blockIdx.z;
    const float* A = (z == 0) ? q : (z == 1) ? k : v;
    const float* W = (z == 0) ? Wq : (z == 1) ? Wk : Wv;
    float* C = (z == 0) ? g_Q : (z == 1) ? g_K : g_V;
    gemm_body(A, W, nullptr, C);
}

__global__ __launch_bounds__(256, 2) void outproj_kernel(
    const float* __restrict__ Wo, const float* __restrict__ bo, float* __restrict__ out)
{
    gemm_body(g_ctx, Wo, bo, out);
}

// =====================================================================
// relk: Rt[bh][r][i] = dot(Q[b,i,h*64:], rel_k[r,:]) — coalesced stores
// =====================================================================
__global__ __launch_bounds__(128) void relk_kernel(const float* __restrict__ rel_k)
{
    __shared__ float4 RK[NR][16];
    const int bh = blockIdx.y;
    const int b = bh >> 4, h = bh & 15;
    const int i0 = blockIdx.x * 128;
    const int tid = threadIdx.x;

    for (int idx = tid; idx < NR * 16; idx += 128)
        RK[idx / 16][idx % 16] = ((const float4*)rel_k)[idx];
    __syncthreads();

    float4 q[16];
    const float4* qrow = (const float4*)&g_Q[(size_t)(b * Sq + i0 + tid) * Dm + h * DK];
    #pragma unroll
    for (int d = 0; d < 16; d++) q[d] = qrow[d];

    float* outp = &g_Rt[(size_t)bh * NR * Sq + i0 + tid];
    #pragma unroll 1
    for (int r = 0; r < NR; r++) {
        float s = 0.f;
        #pragma unroll
        for (int d = 0; d < 16; d++) {
            float4 rk = RK[r][d];
            s += q[d].x * rk.x + q[d].y * rk.y + q[d].z * rk.z + q[d].w * rk.w;
        }
        outp[(size_t)r * Sq] = s;
    }
}

// =====================================================================
// scores: g_attn = QK^T/8 + Rt[rel]    (tf32 mma, BM=BN=64, K=64)
// =====================================================================
__global__ __launch_bounds__(256, 2) void scores_kernel()
{
    __shared__ uint32_t Qs[64][68];   // [m][k]
    __shared__ uint32_t Ks[64][68];   // [n][k]

    const int bh = blockIdx.z;
    const int b = bh >> 4, h = bh & 15;
    const int i0 = blockIdx.y * 64, j0 = blockIdx.x * 64;
    const int tid = threadIdx.x;
    const int lane = tid & 31, wid = tid >> 5;
    const int g = lane >> 2, t = lane & 3;
    const int wm = (wid >> 2) * 32;
    const int wn = (wid & 3) * 16;

    const int lr = tid >> 4, lc = (tid & 15) * 4;
    #pragma unroll
    for (int p = 0; p < 4; p++) {
        float4 qv = *(const float4*)&g_Q[(size_t)(b * Sq + i0 + lr + 16 * p) * Dm + h * DK + lc];
        *(uint4*)&Qs[lr + 16 * p][lc] = make_uint4(f2tf(qv.x), f2tf(qv.y), f2tf(qv.z), f2tf(qv.w));
        float4 kv = *(const float4*)&g_K[(size_t)(b * Sq + j0 + lr + 16 * p) * Dm + h * DK + lc];
        *(uint4*)&Ks[lr + 16 * p][lc] = make_uint4(f2tf(kv.x), f2tf(kv.y), f2tf(kv.z), f2tf(kv.w));
    }
    __syncthreads();

    float4 acc[2][2];
    #pragma unroll
    for (int i = 0; i < 2; i++)
        #pragma unroll
        for (int j = 0; j < 2; j++) acc[i][j] = make_float4(0.f, 0.f, 0.f, 0.f);

    #pragma unroll
    for (int ks = 0; ks < 8; ks++) {
        const int k0 = ks * 8;
        uint32_t af[2][4], bf[2][2];
        #pragma unroll
        for (int ma = 0; ma < 2; ma++) {
            const int m = wm + ma * 16 + g;
            af[ma][0] = Qs[m][k0 + t];     af[ma][1] = Qs[m + 8][k0 + t];
            af[ma][2] = Qs[m][k0 + t + 4]; af[ma][3] = Qs[m + 8][k0 + t + 4];
        }
        #pragma unroll
        for (int na = 0; na < 2; na++) {
            const int n = wn + na * 8 + g;
            bf[na][0] = Ks[n][k0 + t]; bf[na][1] = Ks[n][k0 + t + 4];
        }
        #pragma unroll
        for (int ma = 0; ma < 2; ma++)
            #pragma unroll
            for (int na = 0; na < 2; na++)
                mma8(acc[ma][na], af[ma], bf[na]);
    }

    const float* Rt = &g_Rt[(size_t)bh * NR * Sq];
    float* attnBase = &g_attn[(size_t)bh * Sq * Sq];
    #pragma unroll
    for (int ma = 0; ma < 2; ma++) {
        const int ia = i0 + wm + ma * 16 + g;
        #pragma unroll
        for (int na = 0; na < 2; na++) {
            const int ja = j0 + wn + na * 8 + 2 * t;
            #pragma unroll
            for (int e = 0; e < 4; e++) {
                const int ii = ia + (e >= 2 ? 8 : 0);
                const int jj = ja + (e & 1);
                int rel = jj - ii;
                rel = (rel < -32 ? -32 : (rel > 32 ? 32 : rel)) + 32;
                const float v = (e == 0 ? acc[ma][na].x : e == 1 ? acc[ma][na].y :
                                 e == 2 ? acc[ma][na].z : acc[ma][na].w);
                attnBase[(size_t)ii * Sq + jj] = v * 0.125f + Rt[(size_t)rel * Sq + ii];
            }
        }
    }
}

// =====================================================================
// FUSED: softmax (in place, warp-per-head) + bucket W + head-mean output
// Block = (i, b); 512 threads = 16 warps; warp w owns head w's row.
// =====================================================================
__global__ __launch_bounds__(512) void softmax_fused_kernel(float* __restrict__ out_attn)
{
    extern __shared__ float sm[];
    float* pbuf = sm;                        // [16][PBUF_PAD]
    float* sWb  = sm + 16 * PBUF_PAD;        // [16][96]

    const int i = blockIdx.x;
    const int b = blockIdx.y;
    const int tid  = threadIdx.x;
    const int w    = tid >> 5;
    const int lane = tid & 31;
    const int bh = b * Hh + w;

    float4* row4 = (float4*)&g_attn[((size_t)bh * Sq + i) * Sq];

    float4 v[8];
    #pragma unroll
    for (int k = 0; k < 8; k++) v[k] = row4[lane + 32 * k];

    // warp max
    float mx = -1e30f;
    #pragma unroll
    for (int k = 0; k < 8; k++) {
        mx = fmaxf(mx, fmaxf(fmaxf(v[k].x, v[k].y), fmaxf(v[k].z, v[k].w)));
    }
    #pragma unroll
    for (int o = 16; o; o >>= 1) mx = fmaxf(mx, __shfl_xor_sync(0xFFFFFFFFu, mx, o));

    // exp + warp sum
    float sum = 0.f;
    #pragma unroll
    for (int k = 0; k < 8; k++) {
        v[k].x = __expf(v[k].x - mx); v[k].y = __expf(v[k].y - mx);
        v[k].z = __expf(v[k].z - mx); v[k].w = __expf(v[k].w - mx);
        sum += v[k].x + v[k].y + v[k].z + v[k].w;
    }
    #pragma unroll
    for (int o = 16; o; o >>= 1) sum += __shfl_xor_sync(0xFFFFFFFFu, sum, o);
    const float inv = 1.f / sum;

    // zero this warp's sW
    float* sW = &sWb[w * 96];
    sW[lane] = 0.f; sW[lane + 32] = 0.f; sW[lane + 64] = 0.f;
    __syncwarp();

    // normalize, store back (global + smem), bucket
    float* prow = &pbuf[w * PBUF_PAD];
    float lowsum = 0.f, highsum = 0.f;
    #pragma unroll
    for (int k = 0; k < 8; k++) {
        const int j0 = (lane + 32 * k) * 4;
        v[k].x *= inv; v[k].y *= inv; v[k].z *= inv; v[k].w *= inv;
        row4[lane + 32 * k] = v[k];
        *(float4*)&prow[j0] = v[k];
        #pragma unroll
        for (int e = 0; e < 4; e++) {
            const int j = j0 + e;
            const float p = (e == 0 ? v[k].x : e == 1 ? v[k].y : e == 2 ? v[k].z : v[k].w);
            const int d = j - i;
            if (d <= -32)      lowsum  += p;
            else if (d >= 32)  highsum += p;
            else               sW[d + 32] = p;    // unique lane per slot
        }
    }
    #pragma unroll
    for (int o = 16; o; o >>= 1) {
        lowsum  += __shfl_xor_sync(0xFFFFFFFFu, lowsum,  o);
        highsum += __shfl_xor_sync(0xFFFFFFFFu, highsum, o);
    }
    if (lane == 0) { sW[0] = lowsum; sW[64] = highsum; }
    __syncwarp();

    // coalesced W write
    float* gw = &g_W[(size_t)(bh * Sq + i) * WPAD];
    gw[lane]      = sW[lane];
    gw[lane + 32] = sW[lane + 32];
    gw[lane + 64] = sW[lane + 64];

    // cross-head mean
    __syncthreads();
    float* orow = &out_attn[((size_t)b * Sq + i) * Sq];
    #pragma unroll
    for (int rep = 0; rep < 2; rep++) {
        const int j = tid + rep * 512;
        float s = 0.f;
        #pragma unroll
        for (int h = 0; h < Hh; h++) s += pbuf[h * PBUF_PAD + j];
        orow[j] = s * (1.0f / Hh);
    }
}

// =====================================================================
// ctx = attn @ V + W @ rel_v   (tf32 mma; BM=128, BN=64, BK=32; 35 k-blocks)
// =====================================================================
__global__ __launch_bounds__(256, 2) void ctx_kernel(const float* __restrict__ rel_v)
{
    __shared__ uint32_t As[128][36];
    __shared__ uint32_t Bs[32][72];

    const int bh = blockIdx.y;
    const int b = bh >> 4, h = bh & 15;
    const int i0 = blockIdx.x * 128;
    const int tid = threadIdx.x;
    const int lane = tid & 31, wid = tid >> 5;
    const int g = lane >> 2, t = lane & 3;
    const int wm = (wid >> 2) * 64;
    const int wn = (wid & 3) * 16;

    const int aRow = tid >> 3,  aCol = (tid & 7)  * 4;
    const int bRow = tid >> 4,  bCol = (tid & 15) * 4;

    const float* attnBase = &g_attn[((size_t)bh * Sq + i0) * Sq];
    const float* wBase    = &g_W[(size_t)(bh * Sq + i0) * WPAD];

    float4 ar[4], br[2];

    auto ldg = [&](int kt) {
        if (kt < 32) {
            const int kb = kt * 32;
            #pragma unroll
            for (int p = 0; p < 4; p++)
                ar[p] = *(const float4*)&attnBase[(size_t)(aRow + 32 * p) * Sq + kb + aCol];
            #pragma unroll
            for (int p = 0; p < 2; p++)
                br[p] = *(const float4*)&g_V[(size_t)(b * Sq + kb + bRow + 16 * p) * Dm + h * DK + bCol];
        } else {
            const int kk = (kt - 32) * 32;
            #pragma unroll
            for (int p = 0; p < 4; p++)
                ar[p] = *(const float4*)&wBase[(size_t)(aRow + 32 * p) * WPAD + kk + aCol];
            #pragma unroll
            for (int p = 0; p < 2; p++) {
                const int rr = kk + bRow + 16 * p;
                br[p] = (rr < NR) ? *(const float4*)&rel_v[rr * DK + bCol]
                                  : make_float4(0.f, 0.f, 0.f, 0.f);
            }
        }
    };
    auto sts = [&]() {
        #pragma unroll
        for (int p = 0; p < 4; p++) {
            uint4 u = make_uint4(f2tf(ar[p].x), f2tf(ar[p].y), f2tf(ar[p].z), f2tf(ar[p].w));
            *(uint4*)&As[aRow + 32 * p][aCol] = u;
        }
        #pragma unroll
        for (int p = 0; p < 2; p++) {
            uint4 u = make_uint4(f2tf(br[p].x), f2tf(br[p].y), f2tf(br[p].z), f2tf(br[p].w));
            *(uint4*)&Bs[bRow + 16 * p][bCol] = u;
        }
    };

    float4 acc[4][2];
    #pragma unroll
    for (int i = 0; i < 4; i++)
        #pragma unroll
        for (int j = 0; j < 2; j++) acc[i][j] = make_float4(0.f, 0.f, 0.f, 0.f);

    ldg(0); sts(); __syncthreads();

    #pragma unroll 1
    for (int kt = 0; kt < 35; kt++) {
        const bool nxt = (kt + 1) < 35;
        if (nxt) ldg(kt + 1);
        #pragma unroll
        for (int ks = 0; ks < 4; ks++) {
            const int k0 = ks * 8;
            uint32_t af[4][4], bf[2][2];
            #pragma unroll
            for (int ma = 0; ma < 4; ma++) {
                const int m = wm + ma * 16 + g;
                af[ma][0] = As[m][k0 + t];     af[ma][1] = As[m + 8][k0 + t];
                af[ma][2] = As[m][k0 + t + 4]; af[ma][3] = As[m + 8][k0 + t + 4];
            }
            #pragma unroll
            for (int na = 0; na < 2; na++) {
                const int n = wn + na * 8 + g;
                bf[na][0] = Bs[k0 + t][n]; bf[na][1] = Bs[k0 + t + 4][n];
            }
            #pragma unroll
            for (int ma = 0; ma < 4; ma++)
                #pragma unroll
                for (int na = 0; na < 2; na++)
                    mma8(acc[ma][na], af[ma], bf[na]);
        }
        __syncthreads();
        if (nxt) { sts(); __syncthreads(); }
    }

    #pragma unroll
    for (int ma = 0; ma < 4; ma++) {
        const int r = i0 + wm + ma * 16 + g;
        #pragma unroll
        for (int na = 0; na < 2; na++) {
            const int c = wn + na * 8 + 2 * t;
            g_ctx[(size_t)(b * Sq + r) * Dm + h * DK + c]           = acc[ma][na].x;
            g_ctx[(size_t)(b * Sq + r) * Dm + h * DK + c + 1]       = acc[ma][na].y;
            g_ctx[(size_t)(b * Sq + r + 8) * Dm + h * DK + c]       = acc[ma][na].z;
            g_ctx[(size_t)(b * Sq + r + 8) * Dm + h * DK + c + 1]   = acc[ma][na].w;
        }
    }
}

// ---------------- launch ----------------
extern "C" void kernel_launch(void* const* d_in, const int* in_sizes, int n_in,
                              void* d_out, int out_size)
{
    const float* query = (const float*)d_in[0];
    const float* key   = (const float*)d_in[1];
    const float* value = (const float*)d_in[2];
    const float* Wq    = (const float*)d_in[3];
    const float* Wk    = (const float*)d_in[4];
    const float* Wv    = (const float*)d_in[5];
    const float* Wo    = (const float*)d_in[6];
    const float* bo    = (const float*)d_in[7];
    const float* rel_k = (const float*)d_in[8];
    const float* rel_v = (const float*)d_in[9];

    float* out      = (float*)d_out;                 // [B,S,D]
    float* out_attn = out + (size_t)Bb * Sq * Dm;    // [B,S,S]

    const int fused_smem = (16 * PBUF_PAD + 16 * 96) * (int)sizeof(float);  // ~72 KB
    static bool attr_set = false;
    if (!attr_set) {
        cudaFuncSetAttribute(softmax_fused_kernel,
                             cudaFuncAttributeMaxDynamicSharedMemorySize, fused_smem);
        attr_set = true;
    }

    // 1. projections (fused into one launch; z picks q/k/v)
    proj3_kernel<<<dim3(Dm / 64, Mrows / 128, 3), 256>>>(query, key, value, Wq, Wk, Wv);

    // 2. rel_k dot products (transposed output for coalesced stores)
    relk_kernel<<<dim3(Sq / 128, BH), 128>>>(rel_k);

    // 3. scores + rel bias -> g_attn
    scores_kernel<<<dim3(Sq / 64, Sq / 64, BH), 256>>>();

    // 4. softmax + bucket sums + head-mean (fused)
    softmax_fused_kernel<<<dim3(Sq, Bb), 512, fused_smem>>>(out_attn);

    // 5. context = attn@V + W@rel_v
    ctx_kernel<<<dim3(Sq / 128, BH), 256>>>(rel_v);

    // 6. output projection + bias
    outproj_kernel<<<dim3(Dm / 64, Mrows / 128), 256>>>(Wo, bo, out);
}

// round 5
// speedup vs baseline: 3.1969x; 1.0396x over previous
#include <cuda_runtime.h>
#include <cstdint>
#include <cstddef>

#define Sq 1024
#define Bb 4
#define Dm 1024
#define Hh 16
#define DK 64
#define NR 65
#define WPAD 96
#define BH (Bb*Hh)
#define Mrows (Bb*Sq)
#define PBUF_PAD 1028

// ---------------- scratch (device globals; no allocation) ----------------
__device__ __align__(128) float g_Q[(size_t)Mrows * Dm];
__device__ __align__(128) float g_K[(size_t)Mrows * Dm];
__device__ __align__(128) float g_V[(size_t)Mrows * Dm];
__device__ __align__(128) float g_ctx[(size_t)Mrows * Dm];
__device__ __align__(128) float g_Rt[(size_t)BH * NR * Sq];
__device__ __align__(128) float g_W[(size_t)BH * Sq * WPAD];
__device__ __align__(128) float g_attn[(size_t)BH * Sq * Sq];   // 256 MB

// ---------------- tf32 / mma / cp.async helpers ----------------
__device__ __forceinline__ uint32_t f2tf(float x) {
    uint32_t u; asm("cvt.rna.tf32.f32 %0, %1;" : "=r"(u) : "f"(x)); return u;
}
__device__ __forceinline__ void mma8(float4& d, const uint32_t* a, const uint32_t* b) {
    asm volatile("mma.sync.aligned.m16n8k8.row.col.f32.tf32.tf32.f32 "
                 "{%0,%1,%2,%3},{%4,%5,%6,%7},{%8,%9},{%0,%1,%2,%3};"
                 : "+f"(d.x), "+f"(d.y), "+f"(d.z), "+f"(d.w)
                 : "r"(a[0]), "r"(a[1]), "r"(a[2]), "r"(a[3]), "r"(b[0]), "r"(b[1]));
}
__device__ __forceinline__ void cp16(void* dst, const void* src) {
    uint32_t d = (uint32_t)__cvta_generic_to_shared(dst);
    asm volatile("cp.async.cg.shared.global [%0], [%1], 16;" :: "r"(d), "l"(src) : "memory");
}
__device__ __forceinline__ void cp16z(void* dst, const void* src, bool valid) {
    uint32_t d = (uint32_t)__cvta_generic_to_shared(dst);
    int sz = valid ? 16 : 0;
    asm volatile("cp.async.cg.shared.global [%0], [%1], 16, %2;" :: "r"(d), "l"(src), "r"(sz) : "memory");
}
#define CP_COMMIT() asm volatile("cp.async.commit_group;" ::: "memory")
#define CP_WAIT1()  asm volatile("cp.async.wait_group 1;" ::: "memory")

// per-stage smem tile: A 128x32 (pad 36), B 32x64 (pad 72), raw fp32
struct SmemStage { float As[128][36]; float Bs[32][72]; };
#define GEMM_SMEM (3 * (int)sizeof(SmemStage))   // 82944 B

// =====================================================================
// Pipelined TF32 GEMM body: C[4096,1024] = A[4096,1024] @ W[1024,1024] (+bias)
// BM=128, BN=64, BK=32, 3-stage cp.async, 256 thr (8 warps 2x4, warp 64x16)
// =====================================================================
__device__ __forceinline__ void gemm_body_async(const float* __restrict__ A,
                                                const float* __restrict__ W,
                                                const float* __restrict__ bias,
                                                float* __restrict__ C)
{
    extern __shared__ SmemStage stages[];

    const int tid  = threadIdx.x;
    const int lane = tid & 31;
    const int wid  = tid >> 5;
    const int g = lane >> 2, t = lane & 3;
    const int wm = (wid >> 2) * 64;
    const int wn = (wid & 3) * 16;
    const int row0 = blockIdx.y * 128, col0 = blockIdx.x * 64;

    const int aRow = tid >> 3,  aCol = (tid & 7)  * 4;
    const int bRow = tid >> 4,  bCol = (tid & 15) * 4;

    auto issue = [&](int kt, int s) {
        SmemStage& st = stages[s];
        const int kb = kt * 32;
        #pragma unroll
        for (int p = 0; p < 4; p++)
            cp16(&st.As[aRow + 32 * p][aCol],
                 &A[(size_t)(row0 + aRow + 32 * p) * 1024 + kb + aCol]);
        #pragma unroll
        for (int p = 0; p < 2; p++)
            cp16(&st.Bs[bRow + 16 * p][bCol],
                 &W[(size_t)(kb + bRow + 16 * p) * 1024 + col0 + bCol]);
    };

    float4 acc[4][2];
    #pragma unroll
    for (int i = 0; i < 4; i++)
        #pragma unroll
        for (int j = 0; j < 2; j++) acc[i][j] = make_float4(0.f, 0.f, 0.f, 0.f);

    issue(0, 0); CP_COMMIT();
    issue(1, 1); CP_COMMIT();

    int scur = 0, snxt = 2;
    #pragma unroll 1
    for (int kt = 0; kt < 32; kt++) {
        CP_WAIT1();
        __syncthreads();
        if (kt + 2 < 32) issue(kt + 2, snxt);
        CP_COMMIT();

        SmemStage& st = stages[scur];
        #pragma unroll
        for (int ks = 0; ks < 4; ks++) {
            const int k0 = ks * 8;
            uint32_t af[4][4], bf[2][2];
            #pragma unroll
            for (int ma = 0; ma < 4; ma++) {
                const int m = wm + ma * 16 + g;
                af[ma][0] = f2tf(st.As[m][k0 + t]);     af[ma][1] = f2tf(st.As[m + 8][k0 + t]);
                af[ma][2] = f2tf(st.As[m][k0 + t + 4]); af[ma][3] = f2tf(st.As[m + 8][k0 + t + 4]);
            }
            #pragma unroll
            for (int na = 0; na < 2; na++) {
                const int n = wn + na * 8 + g;
                bf[na][0] = f2tf(st.Bs[k0 + t][n]); bf[na][1] = f2tf(st.Bs[k0 + t + 4][n]);
            }
            #pragma unroll
            for (int ma = 0; ma < 4; ma++)
                #pragma unroll
                for (int na = 0; na < 2; na++)
                    mma8(acc[ma][na], af[ma], bf[na]);
        }
        scur = (scur + 1 == 3) ? 0 : scur + 1;
        snxt = (snxt + 1 == 3) ? 0 : snxt + 1;
    }

    #pragma unroll
    for (int ma = 0; ma < 4; ma++) {
        const int r = row0 + wm + ma * 16 + g;
        #pragma unroll
        for (int na = 0; na < 2; na++) {
            const int c = col0 + wn + na * 8 + 2 * t;
            float bx = 0.f, by = 0.f;
            if (bias) { bx = bias[c]; by = bias[c + 1]; }
            C[(size_t)r * 1024 + c]           = acc[ma][na].x + bx;
            C[(size_t)r * 1024 + c + 1]       = acc[ma][na].y + by;
            C[(size_t)(r + 8) * 1024 + c]     = acc[ma][na].z + bx;
            C[(size_t)(r + 8) * 1024 + c + 1] = acc[ma][na].w + by;
        }
    }
}

__global__ __launch_bounds__(256, 2) void proj3_kernel(
    const float* __restrict__ q, const float* __restrict__ k, const float* __restrict__ v,
    const float* __restrict__ Wq, const float* __restrict__ Wk, const float* __restrict__ Wv)
{
    const int z = blockIdx.z;
    const float* A = (z == 0) ? q : (z == 1) ? k : v;
    const float* W = (z == 0) ? Wq : (z == 1) ? Wk : Wv;
    float* C = (z == 0) ? g_Q : (z == 1) ? g_K : g_V;
    gemm_body_async(A, W, nullptr, C);
}

__global__ __launch_bounds__(256, 2) void outproj_kernel(
    const float* __restrict__ Wo, const float* __restrict__ bo, float* __restrict__ out)
{
    gemm_body_async(g_ctx, Wo, bo, out);
}

// =====================================================================
// relk: Rt[bh][r][i] = dot(Q[b,i,h*64:], rel_k[r,:]) — coalesced stores
// =====================================================================
__global__ __launch_bounds__(128) void relk_kernel(const float* __restrict__ rel_k)
{
    __shared__ float4 RK[NR][16];
    const int bh = blockIdx.y;
    const int b = bh >> 4, h = bh & 15;
    const int i0 = blockIdx.x * 128;
    const int tid = threadIdx.x;

    for (int idx = tid; idx < NR * 16; idx += 128)
        RK[idx / 16][idx % 16] = ((const float4*)rel_k)[idx];
    __syncthreads();

    float4 q[16];
    const float4* qrow = (const float4*)&g_Q[(size_t)(b * Sq + i0 + tid) * Dm + h * DK];
    #pragma unroll
    for (int d = 0; d < 16; d++) q[d] = qrow[d];

    float* outp = &g_Rt[(size_t)bh * NR * Sq + i0 + tid];
    #pragma unroll 1
    for (int r = 0; r < NR; r++) {
        float s = 0.f;
        #pragma unroll
        for (int d = 0; d < 16; d++) {
            float4 rk = RK[r][d];
            s += q[d].x * rk.x + q[d].y * rk.y + q[d].z * rk.z + q[d].w * rk.w;
        }
        outp[(size_t)r * Sq] = s;
    }
}

// =====================================================================
// scores: g_attn = QK^T/8 + Rt[rel]    (tf32 mma, BM=BN=64, K=64)
// =====================================================================
__global__ __launch_bounds__(256, 2) void scores_kernel()
{
    __shared__ uint32_t Qs[64][68];
    __shared__ uint32_t Ks[64][68];

    const int bh = blockIdx.z;
    const int b = bh >> 4, h = bh & 15;
    const int i0 = blockIdx.y * 64, j0 = blockIdx.x * 64;
    const int tid = threadIdx.x;
    const int lane = tid & 31, wid = tid >> 5;
    const int g = lane >> 2, t = lane & 3;
    const int wm = (wid >> 2) * 32;
    const int wn = (wid & 3) * 16;

    const int lr = tid >> 4, lc = (tid & 15) * 4;
    #pragma unroll
    for (int p = 0; p < 4; p++) {
        float4 qv = *(const float4*)&g_Q[(size_t)(b * Sq + i0 + lr + 16 * p) * Dm + h * DK + lc];
        *(uint4*)&Qs[lr + 16 * p][lc] = make_uint4(f2tf(qv.x), f2tf(qv.y), f2tf(qv.z), f2tf(qv.w));
        float4 kv = *(const float4*)&g_K[(size_t)(b * Sq + j0 + lr + 16 * p) * Dm + h * DK + lc];
        *(uint4*)&Ks[lr + 16 * p][lc] = make_uint4(f2tf(kv.x), f2tf(kv.y), f2tf(kv.z), f2tf(kv.w));
    }
    __syncthreads();

    float4 acc[2][2];
    #pragma unroll
    for (int i = 0; i < 2; i++)
        #pragma unroll
        for (int j = 0; j < 2; j++) acc[i][j] = make_float4(0.f, 0.f, 0.f, 0.f);

    #pragma unroll
    for (int ks = 0; ks < 8; ks++) {
        const int k0 = ks * 8;
        uint32_t af[2][4], bf[2][2];
        #pragma unroll
        for (int ma = 0; ma < 2; ma++) {
            const int m = wm + ma * 16 + g;
            af[ma][0] = Qs[m][k0 + t];     af[ma][1] = Qs[m + 8][k0 + t];
            af[ma][2] = Qs[m][k0 + t + 4]; af[ma][3] = Qs[m + 8][k0 + t + 4];
        }
        #pragma unroll
        for (int na = 0; na < 2; na++) {
            const int n = wn + na * 8 + g;
            bf[na][0] = Ks[n][k0 + t]; bf[na][1] = Ks[n][k0 + t + 4];
        }
        #pragma unroll
        for (int ma = 0; ma < 2; ma++)
            #pragma unroll
            for (int na = 0; na < 2; na++)
                mma8(acc[ma][na], af[ma], bf[na]);
    }

    const float* Rt = &g_Rt[(size_t)bh * NR * Sq];
    float* attnBase = &g_attn[(size_t)bh * Sq * Sq];
    #pragma unroll
    for (int ma = 0; ma < 2; ma++) {
        const int ia = i0 + wm + ma * 16 + g;
        #pragma unroll
        for (int na = 0; na < 2; na++) {
            const int ja = j0 + wn + na * 8 + 2 * t;
            #pragma unroll
            for (int e = 0; e < 4; e++) {
                const int ii = ia + (e >= 2 ? 8 : 0);
                const int jj = ja + (e & 1);
                int rel = jj - ii;
                rel = (rel < -32 ? -32 : (rel > 32 ? 32 : rel)) + 32;
                const float v = (e == 0 ? acc[ma][na].x : e == 1 ? acc[ma][na].y :
                                 e == 2 ? acc[ma][na].z : acc[ma][na].w);
                attnBase[(size_t)ii * Sq + jj] = v * 0.125f + Rt[(size_t)rel * Sq + ii];
            }
        }
    }
}

// =====================================================================
// FUSED: softmax (in place, warp-per-head) + bucket W + head-mean output
// =====================================================================
__global__ __launch_bounds__(512) void softmax_fused_kernel(float* __restrict__ out_attn)
{
    extern __shared__ float sm[];
    float* pbuf = sm;                        // [16][PBUF_PAD]
    float* sWb  = sm + 16 * PBUF_PAD;        // [16][96]

    const int i = blockIdx.x;
    const int b = blockIdx.y;
    const int tid  = threadIdx.x;
    const int w    = tid >> 5;
    const int lane = tid & 31;
    const int bh = b * Hh + w;

    float4* row4 = (float4*)&g_attn[((size_t)bh * Sq + i) * Sq];

    float4 v[8];
    #pragma unroll
    for (int k = 0; k < 8; k++) v[k] = row4[lane + 32 * k];

    float mx = -1e30f;
    #pragma unroll
    for (int k = 0; k < 8; k++)
        mx = fmaxf(mx, fmaxf(fmaxf(v[k].x, v[k].y), fmaxf(v[k].z, v[k].w)));
    #pragma unroll
    for (int o = 16; o; o >>= 1) mx = fmaxf(mx, __shfl_xor_sync(0xFFFFFFFFu, mx, o));

    float sum = 0.f;
    #pragma unroll
    for (int k = 0; k < 8; k++) {
        v[k].x = __expf(v[k].x - mx); v[k].y = __expf(v[k].y - mx);
        v[k].z = __expf(v[k].z - mx); v[k].w = __expf(v[k].w - mx);
        sum += v[k].x + v[k].y + v[k].z + v[k].w;
    }
    #pragma unroll
    for (int o = 16; o; o >>= 1) sum += __shfl_xor_sync(0xFFFFFFFFu, sum, o);
    const float inv = 1.f / sum;

    float* sW = &sWb[w * 96];
    sW[lane] = 0.f; sW[lane + 32] = 0.f; sW[lane + 64] = 0.f;
    __syncwarp();

    float* prow = &pbuf[w * PBUF_PAD];
    float lowsum = 0.f, highsum = 0.f;
    #pragma unroll
    for (int k = 0; k < 8; k++) {
        const int j0 = (lane + 32 * k) * 4;
        v[k].x *= inv; v[k].y *= inv; v[k].z *= inv; v[k].w *= inv;
        row4[lane + 32 * k] = v[k];
        *(float4*)&prow[j0] = v[k];
        #pragma unroll
        for (int e = 0; e < 4; e++) {
            const int j = j0 + e;
            const float p = (e == 0 ? v[k].x : e == 1 ? v[k].y : e == 2 ? v[k].z : v[k].w);
            const int d = j - i;
            if (d <= -32)      lowsum  += p;
            else if (d >= 32)  highsum += p;
            else               sW[d + 32] = p;
        }
    }
    #pragma unroll
    for (int o = 16; o; o >>= 1) {
        lowsum  += __shfl_xor_sync(0xFFFFFFFFu, lowsum,  o);
        highsum += __shfl_xor_sync(0xFFFFFFFFu, highsum, o);
    }
    if (lane == 0) { sW[0] = lowsum; sW[64] = highsum; }
    __syncwarp();

    float* gw = &g_W[(size_t)(bh * Sq + i) * WPAD];
    gw[lane]      = sW[lane];
    gw[lane + 32] = sW[lane + 32];
    gw[lane + 64] = sW[lane + 64];

    __syncthreads();
    float* orow = &out_attn[((size_t)b * Sq + i) * Sq];
    #pragma unroll
    for (int rep = 0; rep < 2; rep++) {
        const int j = tid + rep * 512;
        float s = 0.f;
        #pragma unroll
        for (int h = 0; h < Hh; h++) s += pbuf[h * PBUF_PAD + j];
        orow[j] = s * (1.0f / Hh);
    }
}

// =====================================================================
// ctx = attn @ V + W @ rel_v  (pipelined tf32; BM=128,BN=64,BK=32; 35 kb)
// =====================================================================
__global__ __launch_bounds__(256, 2) void ctx_kernel(const float* __restrict__ rel_v)
{
    extern __shared__ SmemStage stages[];

    const int bh = blockIdx.y;
    const int b = bh >> 4, h = bh & 15;
    const int i0 = blockIdx.x * 128;
    const int tid = threadIdx.x;
    const int lane = tid & 31, wid = tid >> 5;
    const int g = lane >> 2, t = lane & 3;
    const int wm = (wid >> 2) * 64;
    const int wn = (wid & 3) * 16;

    const int aRow = tid >> 3,  aCol = (tid & 7)  * 4;
    const int bRow = tid >> 4,  bCol = (tid & 15) * 4;

    const float* attnBase = &g_attn[((size_t)bh * Sq + i0) * Sq];
    const float* wBase    = &g_W[(size_t)(bh * Sq + i0) * WPAD];

    auto issue = [&](int kt, int s) {
        SmemStage& st = stages[s];
        if (kt < 32) {
            const int kb = kt * 32;
            #pragma unroll
            for (int p = 0; p < 4; p++)
                cp16(&st.As[aRow + 32 * p][aCol],
                     &attnBase[(size_t)(aRow + 32 * p) * Sq + kb + aCol]);
            #pragma unroll
            for (int p = 0; p < 2; p++)
                cp16(&st.Bs[bRow + 16 * p][bCol],
                     &g_V[(size_t)(b * Sq + kb + bRow + 16 * p) * Dm + h * DK + bCol]);
        } else {
            const int kk = (kt - 32) * 32;
            #pragma unroll
            for (int p = 0; p < 4; p++)
                cp16(&st.As[aRow + 32 * p][aCol],
                     &wBase[(size_t)(aRow + 32 * p) * WPAD + kk + aCol]);
            #pragma unroll
            for (int p = 0; p < 2; p++) {
                const int rr = kk + bRow + 16 * p;
                const int rc = rr < 64 ? rr : 64;
                cp16z(&st.Bs[bRow + 16 * p][bCol], &rel_v[rc * DK + bCol], rr < NR);
            }
        }
    };

    float4 acc[4][2];
    #pragma unroll
    for (int i = 0; i < 4; i++)
        #pragma unroll
        for (int j = 0; j < 2; j++) acc[i][j] = make_float4(0.f, 0.f, 0.f, 0.f);

    issue(0, 0); CP_COMMIT();
    issue(1, 1); CP_COMMIT();

    int scur = 0, snxt = 2;
    #pragma unroll 1
    for (int kt = 0; kt < 35; kt++) {
        CP_WAIT1();
        __syncthreads();
        if (kt + 2 < 35) issue(kt + 2, snxt);
        CP_COMMIT();

        SmemStage& st = stages[scur];
        #pragma unroll
        for (int ks = 0; ks < 4; ks++) {
            const int k0 = ks * 8;
            uint32_t af[4][4], bf[2][2];
            #pragma unroll
            for (int ma = 0; ma < 4; ma++) {
                const int m = wm + ma * 16 + g;
                af[ma][0] = f2tf(st.As[m][k0 + t]);     af[ma][1] = f2tf(st.As[m + 8][k0 + t]);
                af[ma][2] = f2tf(st.As[m][k0 + t + 4]); af[ma][3] = f2tf(st.As[m + 8][k0 + t + 4]);
            }
            #pragma unroll
            for (int na = 0; na < 2; na++) {
                const int n = wn + na * 8 + g;
                bf[na][0] = f2tf(st.Bs[k0 + t][n]); bf[na][1] = f2tf(st.Bs[k0 + t + 4][n]);
            }
            #pragma unroll
            for (int ma = 0; ma < 4; ma++)
                #pragma unroll
                for (int na = 0; na < 2; na++)
                    mma8(acc[ma][na], af[ma], bf[na]);
        }
        scur = (scur + 1 == 3) ? 0 : scur + 1;
        snxt = (snxt + 1 == 3) ? 0 : snxt + 1;
    }

    #pragma unroll
    for (int ma = 0; ma < 4; ma++) {
        const int r = i0 + wm + ma * 16 + g;
        #pragma unroll
        for (int na = 0; na < 2; na++) {
            const int c = wn + na * 8 + 2 * t;
            g_ctx[(size_t)(b * Sq + r) * Dm + h * DK + c]           = acc[ma][na].x;
            g_ctx[(size_t)(b * Sq + r) * Dm + h * DK + c + 1]       = acc[ma][na].y;
            g_ctx[(size_t)(b * Sq + r + 8) * Dm + h * DK + c]       = acc[ma][na].z;
            g_ctx[(size_t)(b * Sq + r + 8) * Dm + h * DK + c + 1]   = acc[ma][na].w;
        }
    }
}

// ---------------- launch ----------------
extern "C" void kernel_launch(void* const* d_in, const int* in_sizes, int n_in,
                              void* d_out, int out_size)
{
    const float* query = (const float*)d_in[0];
    const float* key   = (const float*)d_in[1];
    const float* value = (const float*)d_in[2];
    const float* Wq    = (const float*)d_in[3];
    const float* Wk    = (const float*)d_in[4];
    const float* Wv    = (const float*)d_in[5];
    const float* Wo    = (const float*)d_in[6];
    const float* bo    = (const float*)d_in[7];
    const float* rel_k = (const float*)d_in[8];
    const float* rel_v = (const float*)d_in[9];

    float* out      = (float*)d_out;                 // [B,S,D]
    float* out_attn = out + (size_t)Bb * Sq * Dm;    // [B,S,S]

    const int fused_smem = (16 * PBUF_PAD + 16 * 96) * (int)sizeof(float);
    static bool attr_set = false;
    if (!attr_set) {
        cudaFuncSetAttribute(softmax_fused_kernel,
                             cudaFuncAttributeMaxDynamicSharedMemorySize, fused_smem);
        cudaFuncSetAttribute(proj3_kernel,
                             cudaFuncAttributeMaxDynamicSharedMemorySize, GEMM_SMEM);
        cudaFuncSetAttribute(outproj_kernel,
                             cudaFuncAttributeMaxDynamicSharedMemorySize, GEMM_SMEM);
        cudaFuncSetAttribute(ctx_kernel,
                             cudaFuncAttributeMaxDynamicSharedMemorySize, GEMM_SMEM);
        attr_set = true;
    }

    // 1. projections (fused launch)
    proj3_kernel<<<dim3(Dm / 64, Mrows / 128, 3), 256, GEMM_SMEM>>>(query, key, value, Wq, Wk, Wv);

    // 2. rel_k dot products
    relk_kernel<<<dim3(Sq / 128, BH), 128>>>(rel_k);

    // 3. scores + rel bias -> g_attn
    scores_kernel<<<dim3(Sq / 64, Sq / 64, BH), 256>>>();

    // 4. softmax + bucket sums + head-mean (fused)
    softmax_fused_kernel<<<dim3(Sq, Bb), 512, fused_smem>>>(out_attn);

    // 5. context = attn@V + W@rel_v
    ctx_kernel<<<dim3(Sq / 128, BH), 256, GEMM_SMEM>>>(rel_v);

    // 6. output projection + bias
    outproj_kernel<<<dim3(Dm / 64, Mrows / 128), 256, GEMM_SMEM>>>(Wo, bo, out);
}

// round 8
// speedup vs baseline: 5.1073x; 1.5976x over previous
#include <cuda_runtime.h>
#include <cuda_fp16.h>
#include <cstdint>
#include <cstddef>

#define Sq 1024
#define Bb 4
#define Dm 1024
#define Hh 16
#define DK 64
#define NR 65
#define WPAD 96
#define BH (Bb*Hh)
#define Mrows (Bb*Sq)
#define PBUF_PAD 1028

// ---------------- scratch (device globals; no allocation) ----------------
__device__ __align__(128) float  g_attn[(size_t)BH * Sq * Sq];    // fp32 logits, 256 MB
__device__ __align__(128) __half g_attnh[(size_t)BH * Sq * Sq];   // fp16 probs, 128 MB
__device__ __align__(128) __half g_Qh[(size_t)Mrows * Dm];
__device__ __align__(128) __half g_Kh[(size_t)Mrows * Dm];
__device__ __align__(128) __half g_Vh[(size_t)Mrows * Dm];
__device__ __align__(128) __half g_ctxh[(size_t)Mrows * Dm];
__device__ __align__(128) __half g_Xh[(size_t)3 * Mrows * Dm];    // fp16 inputs q,k,v
__device__ __align__(128) __half g_Wth[(size_t)4 * Dm * Dm];      // W^T fp16: q,k,v,o
__device__ __align__(128) __half g_Wh[(size_t)BH * Sq * WPAD];    // bucket sums fp16
__device__ __align__(128) __half g_relvh[96 * DK];                // rel_v fp16, zero-padded
__device__ __align__(128) float  g_Rt[(size_t)BH * NR * Sq];      // rel_k bias, transposed

// ---------------- helpers ----------------
__device__ __forceinline__ void mma16(float4& d, const uint32_t* a, const uint32_t* b) {
    asm volatile("mma.sync.aligned.m16n8k16.row.col.f32.f16.f16.f32 "
                 "{%0,%1,%2,%3},{%4,%5,%6,%7},{%8,%9},{%0,%1,%2,%3};"
                 : "+f"(d.x), "+f"(d.y), "+f"(d.z), "+f"(d.w)
                 : "r"(a[0]), "r"(a[1]), "r"(a[2]), "r"(a[3]), "r"(b[0]), "r"(b[1]));
}
__device__ __forceinline__ void cp16(void* dst, const void* src) {
    uint32_t d = (uint32_t)__cvta_generic_to_shared(dst);
    asm volatile("cp.async.cg.shared.global [%0], [%1], 16;" :: "r"(d), "l"(src) : "memory");
}
#define CP_COMMIT() asm volatile("cp.async.commit_group;" ::: "memory")
#define CP_WAIT1()  asm volatile("cp.async.wait_group 1;" ::: "memory")
__device__ __forceinline__ uint32_t pack16(const __half& a, const __half& b) {
    return (uint32_t)*(const uint16_t*)&a | ((uint32_t)*(const uint16_t*)&b << 16);
}

// ---------------- prep kernels ----------------
__global__ __launch_bounds__(256) void cvt_inputs_kernel(
    const float* __restrict__ q, const float* __restrict__ k, const float* __restrict__ v)
{
    const int z = blockIdx.y;
    const float4* s = (const float4*)(z == 0 ? q : z == 1 ? k : v);
    const int idx = blockIdx.x * 256 + threadIdx.x;
    float4 a = s[idx];
    __half2* d = (__half2*)(g_Xh + (size_t)z * Mrows * Dm);
    d[idx * 2]     = __floats2half2_rn(a.x, a.y);
    d[idx * 2 + 1] = __floats2half2_rn(a.z, a.w);
}

__global__ __launch_bounds__(256) void cvt_w_kernel(
    const float* __restrict__ Wq, const float* __restrict__ Wk,
    const float* __restrict__ Wv, const float* __restrict__ Wo)
{
    __shared__ float t[32][33];
    const int z = blockIdx.z;
    const float* W = (z == 0) ? Wq : (z == 1) ? Wk : (z == 2) ? Wv : Wo;
    __half* Wt = g_Wth + (size_t)z * Dm * Dm;
    const int x0 = blockIdx.x * 32, y0 = blockIdx.y * 32;
    const int tx = threadIdx.x & 31, ty = threadIdx.x >> 5;
    #pragma unroll
    for (int i = 0; i < 4; i++)
        t[ty + 8 * i][tx] = W[(size_t)(y0 + ty + 8 * i) * Dm + x0 + tx];
    __syncthreads();
    #pragma unroll
    for (int i = 0; i < 4; i++)
        Wt[(size_t)(x0 + ty + 8 * i) * Dm + y0 + tx] = __float2half(t[tx][ty + 8 * i]);
}

__global__ __launch_bounds__(256) void cvt_relv_kernel(const float* __restrict__ rel_v)
{
    for (int idx = threadIdx.x; idx < 96 * DK; idx += 256) {
        const int row = idx / DK, col = idx % DK;
        g_relvh[idx] = __float2half(row < NR ? rel_v[row * DK + col] : 0.f);
    }
}

// =====================================================================
// fp16 GEMM: C[4096,1024](tile 128x128) = A[m][k] @ Bt[n][k]^T (+bias)
// BM=128, BN=128, BK=32; 3-stage cp.async; 8 warps 2x4; warp 64x32
// =====================================================================
struct ProjStage { __half As[128][40]; __half Bs[128][40]; };
#define PROJ_SMEM (3 * (int)sizeof(ProjStage))   // 61440

template<bool HALF_OUT>
__device__ __forceinline__ void gemm_h_body(const __half* __restrict__ A,
                                            const __half* __restrict__ Bt,
                                            const float* __restrict__ bias,
                                            void* __restrict__ Cv)
{
    extern __shared__ ProjStage pstages[];
    const int tid = threadIdx.x, lane = tid & 31, wid = tid >> 5;
    const int g = lane >> 2, t = lane & 3;
    const int wm = (wid >> 2) * 64, wn = (wid & 3) * 32;
    const int row0 = blockIdx.y * 128, col0 = blockIdx.x * 128;

    auto issue = [&](int kt, int s) {
        ProjStage& st = pstages[s];
        const int kb = kt * 32;
        #pragma unroll
        for (int it = 0; it < 2; it++) {
            const int id = it * 256 + tid;
            const int row = id >> 2, seg = id & 3;
            cp16(&st.As[row][seg * 8], &A[(size_t)(row0 + row) * 1024 + kb + seg * 8]);
            cp16(&st.Bs[row][seg * 8], &Bt[(size_t)(col0 + row) * 1024 + kb + seg * 8]);
        }
    };

    float4 acc[4][4];
    #pragma unroll
    for (int i = 0; i < 4; i++)
        #pragma unroll
        for (int j = 0; j < 4; j++) acc[i][j] = make_float4(0.f, 0.f, 0.f, 0.f);

    issue(0, 0); CP_COMMIT();
    issue(1, 1); CP_COMMIT();

    int scur = 0, snxt = 2;
    #pragma unroll 1
    for (int kt = 0; kt < 32; kt++) {
        CP_WAIT1();
        __syncthreads();
        if (kt + 2 < 32) issue(kt + 2, snxt);
        CP_COMMIT();

        ProjStage& st = pstages[scur];
        #pragma unroll
        for (int ks = 0; ks < 2; ks++) {
            const int k0 = ks * 16;
            uint32_t af[4][4], bf[4][2];
            #pragma unroll
            for (int ma = 0; ma < 4; ma++) {
                const int m = wm + ma * 16 + g;
                af[ma][0] = *(const uint32_t*)&st.As[m][k0 + 2 * t];
                af[ma][1] = *(const uint32_t*)&st.As[m + 8][k0 + 2 * t];
                af[ma][2] = *(const uint32_t*)&st.As[m][k0 + 2 * t + 8];
                af[ma][3] = *(const uint32_t*)&st.As[m + 8][k0 + 2 * t + 8];
            }
            #pragma unroll
            for (int na = 0; na < 4; na++) {
                const int n = wn + na * 8 + g;
                bf[na][0] = *(const uint32_t*)&st.Bs[n][k0 + 2 * t];
                bf[na][1] = *(const uint32_t*)&st.Bs[n][k0 + 2 * t + 8];
            }
            #pragma unroll
            for (int ma = 0; ma < 4; ma++)
                #pragma unroll
                for (int na = 0; na < 4; na++)
                    mma16(acc[ma][na], af[ma], bf[na]);
        }
        scur = (scur + 1 == 3) ? 0 : scur + 1;
        snxt = (snxt + 1 == 3) ? 0 : snxt + 1;
    }

    #pragma unroll
    for (int ma = 0; ma < 4; ma++) {
        const int r = row0 + wm + ma * 16 + g;
        #pragma unroll
        for (int na = 0; na < 4; na++) {
            const int c = col0 + wn + na * 8 + 2 * t;
            if (HALF_OUT) {
                __half* Ch = (__half*)Cv;
                *(__half2*)&Ch[(size_t)r * 1024 + c]       = __floats2half2_rn(acc[ma][na].x, acc[ma][na].y);
                *(__half2*)&Ch[(size_t)(r + 8) * 1024 + c] = __floats2half2_rn(acc[ma][na].z, acc[ma][na].w);
            } else {
                float* Cf = (float*)Cv;
                const float bx = bias[c], by = bias[c + 1];
                *(float2*)&Cf[(size_t)r * 1024 + c]       = make_float2(acc[ma][na].x + bx, acc[ma][na].y + by);
                *(float2*)&Cf[(size_t)(r + 8) * 1024 + c] = make_float2(acc[ma][na].z + bx, acc[ma][na].w + by);
            }
        }
    }
}

__global__ __launch_bounds__(256, 2) void proj3h_kernel()
{
    const int z = blockIdx.z;
    const __half* A = g_Xh + (size_t)z * Mrows * Dm;
    const __half* Bt = g_Wth + (size_t)z * Dm * Dm;
    __half* C = (z == 0) ? g_Qh : (z == 1) ? g_Kh : g_Vh;
    gemm_h_body<true>(A, Bt, nullptr, C);
}

__global__ __launch_bounds__(256, 2) void outprojh_kernel(
    const float* __restrict__ bo, float* __restrict__ out)
{
    gemm_h_body<false>(g_ctxh, g_Wth + (size_t)3 * Dm * Dm, bo, out);
}

// =====================================================================
// relk: Rt[bh][r][i] = dot(Q[b,i,h*64:], rel_k[r,:])
// =====================================================================
__global__ __launch_bounds__(128) void relk_kernel(const float* __restrict__ rel_k)
{
    __shared__ float4 RK[NR][16];
    const int bh = blockIdx.y;
    const int b = bh >> 4, h = bh & 15;
    const int i0 = blockIdx.x * 128;
    const int tid = threadIdx.x;

    for (int idx = tid; idx < NR * 16; idx += 128)
        RK[idx / 16][idx % 16] = ((const float4*)rel_k)[idx];
    __syncthreads();

    float2 q[32];
    const __half2* qrow = (const __half2*)&g_Qh[(size_t)(b * Sq + i0 + tid) * Dm + h * DK];
    #pragma unroll
    for (int d = 0; d < 32; d++) q[d] = __half22float2(qrow[d]);

    float* outp = &g_Rt[(size_t)bh * NR * Sq + i0 + tid];
    #pragma unroll 1
    for (int r = 0; r < NR; r++) {
        float s = 0.f;
        #pragma unroll
        for (int d = 0; d < 16; d++) {
            float4 rk = RK[r][d];
            s += q[2 * d].x * rk.x + q[2 * d].y * rk.y + q[2 * d + 1].x * rk.z + q[2 * d + 1].y * rk.w;
        }
        outp[(size_t)r * Sq] = s;
    }
}

// =====================================================================
// scores: g_attn(fp32) = QK^T/8 + Rt[rel]   (fp16 mma, BM=BN=64, K=64)
// =====================================================================
__global__ __launch_bounds__(256, 2) void scores_kernel()
{
    __shared__ __align__(16) __half Qs[64][72];
    __shared__ __align__(16) __half Ks[64][72];

    const int bh = blockIdx.z;
    const int b = bh >> 4, h = bh & 15;
    const int i0 = blockIdx.y * 64, j0 = blockIdx.x * 64;
    const int tid = threadIdx.x;
    const int lane = tid & 31, wid = tid >> 5;
    const int g = lane >> 2, t = lane & 3;
    const int wm = (wid >> 2) * 32;
    const int wn = (wid & 3) * 16;

    for (int idx = tid; idx < 512; idx += 256) {
        const int r = idx >> 3, s = idx & 7;
        *(uint4*)&Qs[r][s * 8] = *(const uint4*)&g_Qh[(size_t)(b * Sq + i0 + r) * Dm + h * DK + s * 8];
        *(uint4*)&Ks[r][s * 8] = *(const uint4*)&g_Kh[(size_t)(b * Sq + j0 + r) * Dm + h * DK + s * 8];
    }
    __syncthreads();

    float4 acc[2][2];
    #pragma unroll
    for (int i = 0; i < 2; i++)
        #pragma unroll
        for (int j = 0; j < 2; j++) acc[i][j] = make_float4(0.f, 0.f, 0.f, 0.f);

    #pragma unroll
    for (int ks = 0; ks < 4; ks++) {
        const int k0 = ks * 16;
        uint32_t af[2][4], bf[2][2];
        #pragma unroll
        for (int ma = 0; ma < 2; ma++) {
            const int m = wm + ma * 16 + g;
            af[ma][0] = *(const uint32_t*)&Qs[m][k0 + 2 * t];
            af[ma][1] = *(const uint32_t*)&Qs[m + 8][k0 + 2 * t];
            af[ma][2] = *(const uint32_t*)&Qs[m][k0 + 2 * t + 8];
            af[ma][3] = *(const uint32_t*)&Qs[m + 8][k0 + 2 * t + 8];
        }
        #pragma unroll
        for (int na = 0; na < 2; na++) {
            const int n = wn + na * 8 + g;
            bf[na][0] = *(const uint32_t*)&Ks[n][k0 + 2 * t];
            bf[na][1] = *(const uint32_t*)&Ks[n][k0 + 2 * t + 8];
        }
        #pragma unroll
        for (int ma = 0; ma < 2; ma++)
            #pragma unroll
            for (int na = 0; na < 2; na++)
                mma16(acc[ma][na], af[ma], bf[na]);
    }

    const float* Rt = &g_Rt[(size_t)bh * NR * Sq];
    float* attnBase = &g_attn[(size_t)bh * Sq * Sq];
    #pragma unroll
    for (int ma = 0; ma < 2; ma++) {
        const int ia = i0 + wm + ma * 16 + g;
        #pragma unroll
        for (int na = 0; na < 2; na++) {
            const int ja = j0 + wn + na * 8 + 2 * t;
            #pragma unroll
            for (int e = 0; e < 4; e++) {
                const int ii = ia + (e >= 2 ? 8 : 0);
                const int jj = ja + (e & 1);
                int rel = jj - ii;
                rel = (rel < -32 ? -32 : (rel > 32 ? 32 : rel)) + 32;
                const float v = (e == 0 ? acc[ma][na].x : e == 1 ? acc[ma][na].y :
                                 e == 2 ? acc[ma][na].z : acc[ma][na].w);
                attnBase[(size_t)ii * Sq + jj] = v * 0.125f + Rt[(size_t)rel * Sq + ii];
            }
        }
    }
}

// =====================================================================
// FUSED softmax: fp32 logits in -> fp16 probs + fp16 bucket W + fp32 mean
// =====================================================================
__global__ __launch_bounds__(512) void softmax_fused_kernel(float* __restrict__ out_attn)
{
    extern __shared__ float sm[];
    float* pbuf = sm;                        // [16][PBUF_PAD]
    float* sWb  = sm + 16 * PBUF_PAD;        // [16][96]

    const int i = blockIdx.x;
    const int b = blockIdx.y;
    const int tid  = threadIdx.x;
    const int w    = tid >> 5;
    const int lane = tid & 31;
    const int bh = b * Hh + w;

    const float4* row4 = (const float4*)&g_attn[((size_t)bh * Sq + i) * Sq];
    __half2* rowh = (__half2*)&g_attnh[((size_t)bh * Sq + i) * Sq];

    float4 v[8];
    #pragma unroll
    for (int k = 0; k < 8; k++) v[k] = row4[lane + 32 * k];

    float mx = -1e30f;
    #pragma unroll
    for (int k = 0; k < 8; k++)
        mx = fmaxf(mx, fmaxf(fmaxf(v[k].x, v[k].y), fmaxf(v[k].z, v[k].w)));
    #pragma unroll
    for (int o = 16; o; o >>= 1) mx = fmaxf(mx, __shfl_xor_sync(0xFFFFFFFFu, mx, o));

    float sum = 0.f;
    #pragma unroll
    for (int k = 0; k < 8; k++) {
        v[k].x = __expf(v[k].x - mx); v[k].y = __expf(v[k].y - mx);
        v[k].z = __expf(v[k].z - mx); v[k].w = __expf(v[k].w - mx);
        sum += v[k].x + v[k].y + v[k].z + v[k].w;
    }
    #pragma unroll
    for (int o = 16; o; o >>= 1) sum += __shfl_xor_sync(0xFFFFFFFFu, sum, o);
    const float inv = 1.f / sum;

    float* sW = &sWb[w * 96];
    sW[lane] = 0.f; sW[lane + 32] = 0.f; sW[lane + 64] = 0.f;
    __syncwarp();

    float* prow = &pbuf[w * PBUF_PAD];
    float lowsum = 0.f, highsum = 0.f;
    #pragma unroll
    for (int k = 0; k < 8; k++) {
        const int j0 = (lane + 32 * k) * 4;
        v[k].x *= inv; v[k].y *= inv; v[k].z *= inv; v[k].w *= inv;
        __half2 h01 = __floats2half2_rn(v[k].x, v[k].y);
        __half2 h23 = __floats2half2_rn(v[k].z, v[k].w);
        rowh[(lane + 32 * k) * 2]     = h01;
        rowh[(lane + 32 * k) * 2 + 1] = h23;
        *(float4*)&prow[j0] = v[k];
        #pragma unroll
        for (int e = 0; e < 4; e++) {
            const int j = j0 + e;
            const float p = (e == 0 ? v[k].x : e == 1 ? v[k].y : e == 2 ? v[k].z : v[k].w);
            const int d = j - i;
            if (d <= -32)      lowsum  += p;
            else if (d >= 32)  highsum += p;
            else               sW[d + 32] = p;
        }
    }
    #pragma unroll
    for (int o = 16; o; o >>= 1) {
        lowsum  += __shfl_xor_sync(0xFFFFFFFFu, lowsum,  o);
        highsum += __shfl_xor_sync(0xFFFFFFFFu, highsum, o);
    }
    if (lane == 0) { sW[0] = lowsum; sW[64] = highsum; }
    __syncwarp();

    __half* gw = &g_Wh[(size_t)(bh * Sq + i) * WPAD];
    gw[lane]      = __float2half(sW[lane]);
    gw[lane + 32] = __float2half(sW[lane + 32]);
    gw[lane + 64] = __float2half(sW[lane + 64]);

    __syncthreads();
    float* orow = &out_attn[((size_t)b * Sq + i) * Sq];
    #pragma unroll
    for (int rep = 0; rep < 2; rep++) {
        const int j = tid + rep * 512;
        float s = 0.f;
        #pragma unroll
        for (int h = 0; h < Hh; h++) s += pbuf[h * PBUF_PAD + j];
        orow[j] = s * (1.0f / Hh);
    }
}

// =====================================================================
// ctx = attn @ V + W @ rel_v  (fp16 mma; BM=128, BN=64, BK=32; 35 kb)
// =====================================================================
struct CtxStage { __half As[128][40]; __half Bs[32][72]; };
#define CTX_SMEM (3 * (int)sizeof(CtxStage))   // 44544

__global__ __launch_bounds__(256, 2) void ctxh_kernel()
{
    extern __shared__ CtxStage cstages[];

    const int bh = blockIdx.y;
    const int b = bh >> 4, h = bh & 15;
    const int i0 = blockIdx.x * 128;
    const int tid = threadIdx.x;
    const int lane = tid & 31, wid = tid >> 5;
    const int g = lane >> 2, t = lane & 3;
    const int wm = (wid >> 2) * 64;
    const int wn = (wid & 3) * 16;

    auto issue = [&](int kt, int s) {
        CtxStage& st = cstages[s];
        if (kt < 32) {
            const int kb = kt * 32;
            #pragma unroll
            for (int it = 0; it < 2; it++) {
                const int id = it * 256 + tid;
                const int row = id >> 2, seg = id & 3;
                cp16(&st.As[row][seg * 8],
                     &g_attnh[((size_t)bh * Sq + i0 + row) * Sq + kb + seg * 8]);
            }
            const int vr = tid >> 3, vs = tid & 7;
            cp16(&st.Bs[vr][vs * 8],
                 &g_Vh[(size_t)(b * Sq + kb + vr) * Dm + h * DK + vs * 8]);
        } else {
            const int kk = (kt - 32) * 32;
            #pragma unroll
            for (int it = 0; it < 2; it++) {
                const int id = it * 256 + tid;
                const int row = id >> 2, seg = id & 3;
                cp16(&st.As[row][seg * 8],
                     &g_Wh[(size_t)(bh * Sq + i0 + row) * WPAD + kk + seg * 8]);
            }
            const int vr = tid >> 3, vs = tid & 7;
            cp16(&st.Bs[vr][vs * 8], &g_relvh[(kk + vr) * DK + vs * 8]);
        }
    };

    float4 acc[4][2];
    #pragma unroll
    for (int i = 0; i < 4; i++)
        #pragma unroll
        for (int j = 0; j < 2; j++) acc[i][j] = make_float4(0.f, 0.f, 0.f, 0.f);

    issue(0, 0); CP_COMMIT();
    issue(1, 1); CP_COMMIT();

    int scur = 0, snxt = 2;
    #pragma unroll 1
    for (int kt = 0; kt < 35; kt++) {
        CP_WAIT1();
        __syncthreads();
        if (kt + 2 < 35) issue(kt + 2, snxt);
        CP_COMMIT();

        CtxStage& st = cstages[scur];
        #pragma unroll
        for (int ks = 0; ks < 2; ks++) {
            const int k0 = ks * 16;
            uint32_t af[4][4], bf[2][2];
            #pragma unroll
            for (int ma = 0; ma < 4; ma++) {
                const int m = wm + ma * 16 + g;
                af[ma][0] = *(const uint32_t*)&st.As[m][k0 + 2 * t];
                af[ma][1] = *(const uint32_t*)&st.As[m + 8][k0 + 2 * t];
                af[ma][2] = *(const uint32_t*)&st.As[m][k0 + 2 * t + 8];
                af[ma][3] = *(const uint32_t*)&st.As[m + 8][k0 + 2 * t + 8];
            }
            #pragma unroll
            for (int na = 0; na < 2; na++) {
                const int n = wn + na * 8 + g;
                bf[na][0] = pack16(st.Bs[k0 + 2 * t][n],     st.Bs[k0 + 2 * t + 1][n]);
                bf[na][1] = pack16(st.Bs[k0 + 2 * t + 8][n], st.Bs[k0 + 2 * t + 9][n]);
            }
            #pragma unroll
            for (int ma = 0; ma < 4; ma++)
                #pragma unroll
                for (int na = 0; na < 2; na++)
                    mma16(acc[ma][na], af[ma], bf[na]);
        }
        scur = (scur + 1 == 3) ? 0 : scur + 1;
        snxt = (snxt + 1 == 3) ? 0 : snxt + 1;
    }

    #pragma unroll
    for (int ma = 0; ma < 4; ma++) {
        const int r = i0 + wm + ma * 16 + g;
        #pragma unroll
        for (int na = 0; na < 2; na++) {
            const int c = wn + na * 8 + 2 * t;
            *(__half2*)&g_ctxh[(size_t)(b * Sq + r) * Dm + h * DK + c] =
                __floats2half2_rn(acc[ma][na].x, acc[ma][na].y);
            *(__half2*)&g_ctxh[(size_t)(b * Sq + r + 8) * Dm + h * DK + c] =
                __floats2half2_rn(acc[ma][na].z, acc[ma][na].w);
        }
    }
}

// ---------------- launch ----------------
extern "C" void kernel_launch(void* const* d_in, const int* in_sizes, int n_in,
                              void* d_out, int out_size)
{
    const float* query = (const float*)d_in[0];
    const float* key   = (const float*)d_in[1];
    const float* value = (const float*)d_in[2];
    const float* Wq    = (const float*)d_in[3];
    const float* Wk    = (const float*)d_in[4];
    const float* Wv    = (const float*)d_in[5];
    const float* Wo    = (const float*)d_in[6];
    const float* bo    = (const float*)d_in[7];
    const float* rel_k = (const float*)d_in[8];
    const float* rel_v = (const float*)d_in[9];

    float* out      = (float*)d_out;                 // [B,S,D]
    float* out_attn = out + (size_t)Bb * Sq * Dm;    // [B,S,S]

    const int fused_smem = (16 * PBUF_PAD + 16 * 96) * (int)sizeof(float);
    static bool attr_set = false;
    if (!attr_set) {
        cudaFuncSetAttribute(softmax_fused_kernel,
                             cudaFuncAttributeMaxDynamicSharedMemorySize, fused_smem);
        cudaFuncSetAttribute(proj3h_kernel,
                             cudaFuncAttributeMaxDynamicSharedMemorySize, PROJ_SMEM);
        cudaFuncSetAttribute(outprojh_kernel,
                             cudaFuncAttributeMaxDynamicSharedMemorySize, PROJ_SMEM);
        cudaFuncSetAttribute(ctxh_kernel,
                             cudaFuncAttributeMaxDynamicSharedMemorySize, CTX_SMEM);
        attr_set = true;
    }

    // 0. prep: fp16 conversions
    cvt_inputs_kernel<<<dim3(Mrows * Dm / 4 / 256, 3), 256>>>(query, key, value);
    cvt_w_kernel<<<dim3(Dm / 32, Dm / 32, 4), 256>>>(Wq, Wk, Wv, Wo);
    cvt_relv_kernel<<<1, 256>>>(rel_v);

    // 1. projections (fp16 mma)
    proj3h_kernel<<<dim3(Dm / 128, Mrows / 128, 3), 256, PROJ_SMEM>>>();

    // 2. rel_k dot products
    relk_kernel<<<dim3(Sq / 128, BH), 128>>>(rel_k);

    // 3. scores + rel bias -> g_attn (fp32 logits)
    scores_kernel<<<dim3(Sq / 64, Sq / 64, BH), 256>>>();

    // 4. softmax -> fp16 probs + bucket sums + head-mean
    softmax_fused_kernel<<<dim3(Sq, Bb), 512, fused_smem>>>(out_attn);

    // 5. context = attn@V + W@rel_v (fp16 mma)
    ctxh_kernel<<<dim3(Sq / 128, BH), 256, CTX_SMEM>>>();

    // 6. output projection + bias (fp16 mma, fp32 out)
    outprojh_kernel<<<dim3(Dm / 128, Mrows / 128), 256, PROJ_SMEM>>>(bo, out);
}

// round 9
// speedup vs baseline: 5.3025x; 1.0382x over previous
#include <cuda_runtime.h>
#include <cuda_fp16.h>
#include <cstdint>
#include <cstddef>

#define Sq 1024
#define Bb 4
#define Dm 1024
#define Hh 16
#define DK 64
#define NR 65
#define WPAD 96
#define BH (Bb*Hh)
#define Mrows (Bb*Sq)
#define PBUF_PAD 1028

// ---------------- scratch (device globals; no allocation) ----------------
__device__ __align__(128) float  g_attn[(size_t)BH * Sq * Sq];    // fp32 logits, 256 MB
__device__ __align__(128) __half g_attnh[(size_t)BH * Sq * Sq];   // fp16 probs, 128 MB
__device__ __align__(128) __half g_Qh[(size_t)Mrows * Dm];
__device__ __align__(128) __half g_Kh[(size_t)Mrows * Dm];
__device__ __align__(128) __half g_Vh[(size_t)Mrows * Dm];
__device__ __align__(128) __half g_ctxh[(size_t)Mrows * Dm];
__device__ __align__(128) __half g_Xh[(size_t)3 * Mrows * Dm];    // fp16 inputs q,k,v
__device__ __align__(128) __half g_Wth[(size_t)4 * Dm * Dm];      // W^T fp16: q,k,v,o
__device__ __align__(128) __half g_Wh[(size_t)BH * Sq * WPAD];    // bucket sums fp16
__device__ __align__(128) __half g_relvh[96 * DK];                // rel_v fp16, zero-padded
__device__ __align__(128) float  g_Rt[(size_t)BH * NR * Sq];      // rel_k bias, transposed

// ---------------- helpers ----------------
__device__ __forceinline__ void mma16(float4& d, const uint32_t* a, const uint32_t* b) {
    asm volatile("mma.sync.aligned.m16n8k16.row.col.f32.f16.f16.f32 "
                 "{%0,%1,%2,%3},{%4,%5,%6,%7},{%8,%9},{%0,%1,%2,%3};"
                 : "+f"(d.x), "+f"(d.y), "+f"(d.z), "+f"(d.w)
                 : "r"(a[0]), "r"(a[1]), "r"(a[2]), "r"(a[3]), "r"(b[0]), "r"(b[1]));
}
__device__ __forceinline__ void ldm_x4(uint32_t* r, uint32_t a) {
    asm volatile("ldmatrix.sync.aligned.m8n8.x4.shared.b16 {%0,%1,%2,%3}, [%4];"
                 : "=r"(r[0]), "=r"(r[1]), "=r"(r[2]), "=r"(r[3]) : "r"(a));
}
__device__ __forceinline__ void ldm_x4_t(uint32_t* r, uint32_t a) {
    asm volatile("ldmatrix.sync.aligned.m8n8.x4.trans.shared.b16 {%0,%1,%2,%3}, [%4];"
                 : "=r"(r[0]), "=r"(r[1]), "=r"(r[2]), "=r"(r[3]) : "r"(a));
}
__device__ __forceinline__ void cp16(void* dst, const void* src) {
    uint32_t d = (uint32_t)__cvta_generic_to_shared(dst);
    asm volatile("cp.async.cg.shared.global [%0], [%1], 16;" :: "r"(d), "l"(src) : "memory");
}
#define CP_COMMIT() asm volatile("cp.async.commit_group;" ::: "memory")
#define CP_WAIT1()  asm volatile("cp.async.wait_group 1;" ::: "memory")

// ---------------- prep kernels ----------------
__global__ __launch_bounds__(256) void cvt_inputs_kernel(
    const float* __restrict__ q, const float* __restrict__ k, const float* __restrict__ v)
{
    const int z = blockIdx.y;
    const float4* s = (const float4*)(z == 0 ? q : z == 1 ? k : v);
    const int idx = blockIdx.x * 256 + threadIdx.x;
    float4 a = s[idx];
    __half2* d = (__half2*)(g_Xh + (size_t)z * Mrows * Dm);
    d[idx * 2]     = __floats2half2_rn(a.x, a.y);
    d[idx * 2 + 1] = __floats2half2_rn(a.z, a.w);
}

__global__ __launch_bounds__(256) void cvt_w_kernel(
    const float* __restrict__ Wq, const float* __restrict__ Wk,
    const float* __restrict__ Wv, const float* __restrict__ Wo)
{
    __shared__ float t[32][33];
    const int z = blockIdx.z;
    const float* W = (z == 0) ? Wq : (z == 1) ? Wk : (z == 2) ? Wv : Wo;
    __half* Wt = g_Wth + (size_t)z * Dm * Dm;
    const int x0 = blockIdx.x * 32, y0 = blockIdx.y * 32;
    const int tx = threadIdx.x & 31, ty = threadIdx.x >> 5;
    #pragma unroll
    for (int i = 0; i < 4; i++)
        t[ty + 8 * i][tx] = W[(size_t)(y0 + ty + 8 * i) * Dm + x0 + tx];
    __syncthreads();
    #pragma unroll
    for (int i = 0; i < 4; i++)
        Wt[(size_t)(x0 + ty + 8 * i) * Dm + y0 + tx] = __float2half(t[tx][ty + 8 * i]);
}

__global__ __launch_bounds__(256) void cvt_relv_kernel(const float* __restrict__ rel_v)
{
    for (int idx = threadIdx.x; idx < 96 * DK; idx += 256) {
        const int row = idx / DK, col = idx % DK;
        g_relvh[idx] = __float2half(row < NR ? rel_v[row * DK + col] : 0.f);
    }
}

// =====================================================================
// fp16 GEMM: C[4096,1024](tile 128x128) = A[m][k] @ Bt[n][k]^T (+bias)
// BM=128, BN=128, BK=32; 3-stage cp.async; 8 warps 2x4; warp 64x32
// Fragment loads via ldmatrix (pad-40 rows: 80B pitch, LDSM conflict-free)
// =====================================================================
struct ProjStage { __half As[128][40]; __half Bs[128][40]; };
#define PROJ_STAGE_SZ ((int)sizeof(ProjStage))   // 20480
#define PROJ_SMEM (3 * PROJ_STAGE_SZ)            // 61440

template<bool HALF_OUT>
__device__ __forceinline__ void gemm_h_body(const __half* __restrict__ A,
                                            const __half* __restrict__ Bt,
                                            const float* __restrict__ bias,
                                            void* __restrict__ Cv)
{
    extern __shared__ ProjStage pstages[];
    const int tid = threadIdx.x, lane = tid & 31, wid = tid >> 5;
    const int g = lane >> 2, t = lane & 3;
    const int wm = (wid >> 2) * 64, wn = (wid & 3) * 32;
    const int row0 = blockIdx.y * 128, col0 = blockIdx.x * 128;

    const uint32_t sb = (uint32_t)__cvta_generic_to_shared(pstages);
    // A-style ldmatrix lane offset (row pitch 80B): rows m0+(L&7)+((L>>3)&1)*8, col k0+(L>>4)*8
    const uint32_t laneA = (uint32_t)(((lane & 7) + ((lane >> 3) & 1) * 8) * 80 + (lane >> 4) * 16);
    // B x4 covering two n-groups: M0=(n0,k0) M1=(n0,k0+8) M2=(n0+8,k0) M3=(n0+8,k0+8)
    const uint32_t laneB = (uint32_t)((lane & 7) * 80 + ((lane >> 3) & 1) * 16 + (lane >> 4) * 640);
    const uint32_t warpA = (uint32_t)(wm * 80) + laneA;
    const uint32_t warpB = (uint32_t)(10240 + wn * 80) + laneB;

    auto issue = [&](int kt, int s) {
        ProjStage& st = pstages[s];
        const int kb = kt * 32;
        #pragma unroll
        for (int it = 0; it < 2; it++) {
            const int id = it * 256 + tid;
            const int row = id >> 2, seg = id & 3;
            cp16(&st.As[row][seg * 8], &A[(size_t)(row0 + row) * 1024 + kb + seg * 8]);
            cp16(&st.Bs[row][seg * 8], &Bt[(size_t)(col0 + row) * 1024 + kb + seg * 8]);
        }
    };

    float4 acc[4][4];
    #pragma unroll
    for (int i = 0; i < 4; i++)
        #pragma unroll
        for (int j = 0; j < 4; j++) acc[i][j] = make_float4(0.f, 0.f, 0.f, 0.f);

    issue(0, 0); CP_COMMIT();
    issue(1, 1); CP_COMMIT();

    int scur = 0, snxt = 2;
    #pragma unroll 1
    for (int kt = 0; kt < 32; kt++) {
        CP_WAIT1();
        __syncthreads();
        if (kt + 2 < 32) issue(kt + 2, snxt);
        CP_COMMIT();

        const uint32_t stb = sb + scur * PROJ_STAGE_SZ;
        #pragma unroll
        for (int ks = 0; ks < 2; ks++) {
            const uint32_t k0b = ks * 32;   // k0*2 bytes
            uint32_t af[4][4], bf[4][2];
            #pragma unroll
            for (int ma = 0; ma < 4; ma++)
                ldm_x4(af[ma], stb + warpA + ma * 1280 + k0b);
            #pragma unroll
            for (int p = 0; p < 2; p++) {
                uint32_t bq[4];
                ldm_x4(bq, stb + warpB + p * 1280 + k0b);
                bf[2 * p][0] = bq[0]; bf[2 * p][1] = bq[1];
                bf[2 * p + 1][0] = bq[2]; bf[2 * p + 1][1] = bq[3];
            }
            #pragma unroll
            for (int ma = 0; ma < 4; ma++)
                #pragma unroll
                for (int na = 0; na < 4; na++)
                    mma16(acc[ma][na], af[ma], bf[na]);
        }
        scur = (scur + 1 == 3) ? 0 : scur + 1;
        snxt = (snxt + 1 == 3) ? 0 : snxt + 1;
    }

    #pragma unroll
    for (int ma = 0; ma < 4; ma++) {
        const int r = row0 + wm + ma * 16 + g;
        #pragma unroll
        for (int na = 0; na < 4; na++) {
            const int c = col0 + wn + na * 8 + 2 * t;
            if (HALF_OUT) {
                __half* Ch = (__half*)Cv;
                *(__half2*)&Ch[(size_t)r * 1024 + c]       = __floats2half2_rn(acc[ma][na].x, acc[ma][na].y);
                *(__half2*)&Ch[(size_t)(r + 8) * 1024 + c] = __floats2half2_rn(acc[ma][na].z, acc[ma][na].w);
            } else {
                float* Cf = (float*)Cv;
                const float bx = bias[c], by = bias[c + 1];
                *(float2*)&Cf[(size_t)r * 1024 + c]       = make_float2(acc[ma][na].x + bx, acc[ma][na].y + by);
                *(float2*)&Cf[(size_t)(r + 8) * 1024 + c] = make_float2(acc[ma][na].z + bx, acc[ma][na].w + by);
            }
        }
    }
}

__global__ __launch_bounds__(256, 2) void proj3h_kernel()
{
    const int z = blockIdx.z;
    const __half* A = g_Xh + (size_t)z * Mrows * Dm;
    const __half* Bt = g_Wth + (size_t)z * Dm * Dm;
    __half* C = (z == 0) ? g_Qh : (z == 1) ? g_Kh : g_Vh;
    gemm_h_body<true>(A, Bt, nullptr, C);
}

__global__ __launch_bounds__(256, 2) void outprojh_kernel(
    const float* __restrict__ bo, float* __restrict__ out)
{
    gemm_h_body<false>(g_ctxh, g_Wth + (size_t)3 * Dm * Dm, bo, out);
}

// =====================================================================
// relk: Rt[bh][r][i] = dot(Q[b,i,h*64:], rel_k[r,:])
// =====================================================================
__global__ __launch_bounds__(128) void relk_kernel(const float* __restrict__ rel_k)
{
    __shared__ float4 RK[NR][16];
    const int bh = blockIdx.y;
    const int b = bh >> 4, h = bh & 15;
    const int i0 = blockIdx.x * 128;
    const int tid = threadIdx.x;

    for (int idx = tid; idx < NR * 16; idx += 128)
        RK[idx / 16][idx % 16] = ((const float4*)rel_k)[idx];
    __syncthreads();

    float2 q[32];
    const __half2* qrow = (const __half2*)&g_Qh[(size_t)(b * Sq + i0 + tid) * Dm + h * DK];
    #pragma unroll
    for (int d = 0; d < 32; d++) q[d] = __half22float2(qrow[d]);

    float* outp = &g_Rt[(size_t)bh * NR * Sq + i0 + tid];
    #pragma unroll 1
    for (int r = 0; r < NR; r++) {
        float s = 0.f;
        #pragma unroll
        for (int d = 0; d < 16; d++) {
            float4 rk = RK[r][d];
            s += q[2 * d].x * rk.x + q[2 * d].y * rk.y + q[2 * d + 1].x * rk.z + q[2 * d + 1].y * rk.w;
        }
        outp[(size_t)r * Sq] = s;
    }
}

// =====================================================================
// scores: g_attn(fp32) = QK^T/8 + Rt[rel]   (fp16 mma + ldmatrix)
// pad 72 -> 144B pitch, LDSM conflict-free
// =====================================================================
__global__ __launch_bounds__(256, 2) void scores_kernel()
{
    __shared__ __align__(16) __half Qs[64][72];
    __shared__ __align__(16) __half Ks[64][72];

    const int bh = blockIdx.z;
    const int b = bh >> 4, h = bh & 15;
    const int i0 = blockIdx.y * 64, j0 = blockIdx.x * 64;
    const int tid = threadIdx.x;
    const int lane = tid & 31, wid = tid >> 5;
    const int g = lane >> 2, t = lane & 3;
    const int wm = (wid >> 2) * 32;
    const int wn = (wid & 3) * 16;

    for (int idx = tid; idx < 512; idx += 256) {
        const int r = idx >> 3, s = idx & 7;
        *(uint4*)&Qs[r][s * 8] = *(const uint4*)&g_Qh[(size_t)(b * Sq + i0 + r) * Dm + h * DK + s * 8];
        *(uint4*)&Ks[r][s * 8] = *(const uint4*)&g_Kh[(size_t)(b * Sq + j0 + r) * Dm + h * DK + s * 8];
    }
    __syncthreads();

    const uint32_t qb = (uint32_t)__cvta_generic_to_shared(Qs);
    const uint32_t kb = (uint32_t)__cvta_generic_to_shared(Ks);
    const uint32_t laneA = (uint32_t)(((lane & 7) + ((lane >> 3) & 1) * 8) * 144 + (lane >> 4) * 16);
    const uint32_t laneB = (uint32_t)((lane & 7) * 144 + ((lane >> 3) & 1) * 16 + (lane >> 4) * 1152);
    const uint32_t warpQ = qb + (uint32_t)(wm * 144) + laneA;
    const uint32_t warpK = kb + (uint32_t)(wn * 144) + laneB;

    float4 acc[2][2];
    #pragma unroll
    for (int i = 0; i < 2; i++)
        #pragma unroll
        for (int j = 0; j < 2; j++) acc[i][j] = make_float4(0.f, 0.f, 0.f, 0.f);

    #pragma unroll
    for (int ks = 0; ks < 4; ks++) {
        const uint32_t k0b = ks * 32;
        uint32_t af[2][4], bf[2][2];
        #pragma unroll
        for (int ma = 0; ma < 2; ma++)
            ldm_x4(af[ma], warpQ + ma * 2304 + k0b);
        {
            uint32_t bq[4];
            ldm_x4(bq, warpK + k0b);
            bf[0][0] = bq[0]; bf[0][1] = bq[1]; bf[1][0] = bq[2]; bf[1][1] = bq[3];
        }
        #pragma unroll
        for (int ma = 0; ma < 2; ma++)
            #pragma unroll
            for (int na = 0; na < 2; na++)
                mma16(acc[ma][na], af[ma], bf[na]);
    }

    const float* Rt = &g_Rt[(size_t)bh * NR * Sq];
    float* attnBase = &g_attn[(size_t)bh * Sq * Sq];
    #pragma unroll
    for (int ma = 0; ma < 2; ma++) {
        const int ia = i0 + wm + ma * 16 + g;
        #pragma unroll
        for (int na = 0; na < 2; na++) {
            const int ja = j0 + wn + na * 8 + 2 * t;
            #pragma unroll
            for (int e = 0; e < 4; e++) {
                const int ii = ia + (e >= 2 ? 8 : 0);
                const int jj = ja + (e & 1);
                int rel = jj - ii;
                rel = (rel < -32 ? -32 : (rel > 32 ? 32 : rel)) + 32;
                const float v = (e == 0 ? acc[ma][na].x : e == 1 ? acc[ma][na].y :
                                 e == 2 ? acc[ma][na].z : acc[ma][na].w);
                attnBase[(size_t)ii * Sq + jj] = v * 0.125f + Rt[(size_t)rel * Sq + ii];
            }
        }
    }
}

// =====================================================================
// FUSED softmax: fp32 logits in -> fp16 probs + fp16 bucket W + fp32 mean
// =====================================================================
__global__ __launch_bounds__(512) void softmax_fused_kernel(float* __restrict__ out_attn)
{
    extern __shared__ float sm[];
    float* pbuf = sm;                        // [16][PBUF_PAD]
    float* sWb  = sm + 16 * PBUF_PAD;        // [16][96]

    const int i = blockIdx.x;
    const int b = blockIdx.y;
    const int tid  = threadIdx.x;
    const int w    = tid >> 5;
    const int lane = tid & 31;
    const int bh = b * Hh + w;

    const float4* row4 = (const float4*)&g_attn[((size_t)bh * Sq + i) * Sq];
    __half2* rowh = (__half2*)&g_attnh[((size_t)bh * Sq + i) * Sq];

    float4 v[8];
    #pragma unroll
    for (int k = 0; k < 8; k++) v[k] = row4[lane + 32 * k];

    float mx = -1e30f;
    #pragma unroll
    for (int k = 0; k < 8; k++)
        mx = fmaxf(mx, fmaxf(fmaxf(v[k].x, v[k].y), fmaxf(v[k].z, v[k].w)));
    #pragma unroll
    for (int o = 16; o; o >>= 1) mx = fmaxf(mx, __shfl_xor_sync(0xFFFFFFFFu, mx, o));

    float sum = 0.f;
    #pragma unroll
    for (int k = 0; k < 8; k++) {
        v[k].x = __expf(v[k].x - mx); v[k].y = __expf(v[k].y - mx);
        v[k].z = __expf(v[k].z - mx); v[k].w = __expf(v[k].w - mx);
        sum += v[k].x + v[k].y + v[k].z + v[k].w;
    }
    #pragma unroll
    for (int o = 16; o; o >>= 1) sum += __shfl_xor_sync(0xFFFFFFFFu, sum, o);
    const float inv = 1.f / sum;

    float* sW = &sWb[w * 96];
    sW[lane] = 0.f; sW[lane + 32] = 0.f; sW[lane + 64] = 0.f;
    __syncwarp();

    float* prow = &pbuf[w * PBUF_PAD];
    float lowsum = 0.f, highsum = 0.f;
    #pragma unroll
    for (int k = 0; k < 8; k++) {
        const int j0 = (lane + 32 * k) * 4;
        v[k].x *= inv; v[k].y *= inv; v[k].z *= inv; v[k].w *= inv;
        __half2 h01 = __floats2half2_rn(v[k].x, v[k].y);
        __half2 h23 = __floats2half2_rn(v[k].z, v[k].w);
        rowh[(lane + 32 * k) * 2]     = h01;
        rowh[(lane + 32 * k) * 2 + 1] = h23;
        *(float4*)&prow[j0] = v[k];
        #pragma unroll
        for (int e = 0; e < 4; e++) {
            const int j = j0 + e;
            const float p = (e == 0 ? v[k].x : e == 1 ? v[k].y : e == 2 ? v[k].z : v[k].w);
            const int d = j - i;
            if (d <= -32)      lowsum  += p;
            else if (d >= 32)  highsum += p;
            else               sW[d + 32] = p;
        }
    }
    #pragma unroll
    for (int o = 16; o; o >>= 1) {
        lowsum  += __shfl_xor_sync(0xFFFFFFFFu, lowsum,  o);
        highsum += __shfl_xor_sync(0xFFFFFFFFu, highsum, o);
    }
    if (lane == 0) { sW[0] = lowsum; sW[64] = highsum; }
    __syncwarp();

    __half* gw = &g_Wh[(size_t)(bh * Sq + i) * WPAD];
    gw[lane]      = __float2half(sW[lane]);
    gw[lane + 32] = __float2half(sW[lane + 32]);
    gw[lane + 64] = __float2half(sW[lane + 64]);

    __syncthreads();
    float* orow = &out_attn[((size_t)b * Sq + i) * Sq];
    #pragma unroll
    for (int rep = 0; rep < 2; rep++) {
        const int j = tid + rep * 512;
        float s = 0.f;
        #pragma unroll
        for (int h = 0; h < Hh; h++) s += pbuf[h * PBUF_PAD + j];
        orow[j] = s * (1.0f / Hh);
    }
}

// =====================================================================
// ctx = attn @ V + W @ rel_v  (fp16 mma + ldmatrix/.trans; BM=128,BN=64)
// =====================================================================
struct CtxStage { __half As[128][40]; __half Bs[32][72]; };
#define CTX_STAGE_SZ ((int)sizeof(CtxStage))   // 14848
#define CTX_SMEM (3 * CTX_STAGE_SZ)

__global__ __launch_bounds__(256, 2) void ctxh_kernel()
{
    extern __shared__ CtxStage cstages[];

    const int bh = blockIdx.y;
    const int b = bh >> 4, h = bh & 15;
    const int i0 = blockIdx.x * 128;
    const int tid = threadIdx.x;
    const int lane = tid & 31, wid = tid >> 5;
    const int g = lane >> 2, t = lane & 3;
    const int wm = (wid >> 2) * 64;
    const int wn = (wid & 3) * 16;

    const uint32_t sb = (uint32_t)__cvta_generic_to_shared(cstages);
    const uint32_t laneA = (uint32_t)(((lane & 7) + ((lane >> 3) & 1) * 8) * 80 + (lane >> 4) * 16);
    // trans-B: rows k0+(L&7)+((L>>3)&1)*8 (pitch 144B), col wn+(L>>4)*8
    const uint32_t laneBt = (uint32_t)(((lane & 7) + ((lane >> 3) & 1) * 8) * 144 + (lane >> 4) * 16);
    const uint32_t warpA  = (uint32_t)(wm * 80) + laneA;
    const uint32_t warpBt = (uint32_t)(10240 + wn * 2) + laneBt;

    auto issue = [&](int kt, int s) {
        CtxStage& st = cstages[s];
        if (kt < 32) {
            const int kb = kt * 32;
            #pragma unroll
            for (int it = 0; it < 2; it++) {
                const int id = it * 256 + tid;
                const int row = id >> 2, seg = id & 3;
                cp16(&st.As[row][seg * 8],
                     &g_attnh[((size_t)bh * Sq + i0 + row) * Sq + kb + seg * 8]);
            }
            const int vr = tid >> 3, vs = tid & 7;
            cp16(&st.Bs[vr][vs * 8],
                 &g_Vh[(size_t)(b * Sq + kb + vr) * Dm + h * DK + vs * 8]);
        } else {
            const int kk = (kt - 32) * 32;
            #pragma unroll
            for (int it = 0; it < 2; it++) {
                const int id = it * 256 + tid;
                const int row = id >> 2, seg = id & 3;
                cp16(&st.As[row][seg * 8],
                     &g_Wh[(size_t)(bh * Sq + i0 + row) * WPAD + kk + seg * 8]);
            }
            const int vr = tid >> 3, vs = tid & 7;
            cp16(&st.Bs[vr][vs * 8], &g_relvh[(kk + vr) * DK + vs * 8]);
        }
    };

    float4 acc[4][2];
    #pragma unroll
    for (int i = 0; i < 4; i++)
        #pragma unroll
        for (int j = 0; j < 2; j++) acc[i][j] = make_float4(0.f, 0.f, 0.f, 0.f);

    issue(0, 0); CP_COMMIT();
    issue(1, 1); CP_COMMIT();

    int scur = 0, snxt = 2;
    #pragma unroll 1
    for (int kt = 0; kt < 35; kt++) {
        CP_WAIT1();
        __syncthreads();
        if (kt + 2 < 35) issue(kt + 2, snxt);
        CP_COMMIT();

        const uint32_t stb = sb + scur * CTX_STAGE_SZ;
        #pragma unroll
        for (int ks = 0; ks < 2; ks++) {
            uint32_t af[4][4], bf[2][2];
            #pragma unroll
            for (int ma = 0; ma < 4; ma++)
                ldm_x4(af[ma], stb + warpA + ma * 1280 + ks * 32);
            {
                uint32_t bq[4];
                ldm_x4_t(bq, stb + warpBt + ks * 16 * 144);
                bf[0][0] = bq[0]; bf[0][1] = bq[1]; bf[1][0] = bq[2]; bf[1][1] = bq[3];
            }
            #pragma unroll
            for (int ma = 0; ma < 4; ma++)
                #pragma unroll
                for (int na = 0; na < 2; na++)
                    mma16(acc[ma][na], af[ma], bf[na]);
        }
        scur = (scur + 1 == 3) ? 0 : scur + 1;
        snxt = (snxt + 1 == 3) ? 0 : snxt + 1;
    }

    #pragma unroll
    for (int ma = 0; ma < 4; ma++) {
        const int r = i0 + wm + ma * 16 + g;
        #pragma unroll
        for (int na = 0; na < 2; na++) {
            const int c = wn + na * 8 + 2 * t;
            *(__half2*)&g_ctxh[(size_t)(b * Sq + r) * Dm + h * DK + c] =
                __floats2half2_rn(acc[ma][na].x, acc[ma][na].y);
            *(__half2*)&g_ctxh[(size_t)(b * Sq + r + 8) * Dm + h * DK + c] =
                __floats2half2_rn(acc[ma][na].z, acc[ma][na].w);
        }
    }
}

// ---------------- launch ----------------
extern "C" void kernel_launch(void* const* d_in, const int* in_sizes, int n_in,
                              void* d_out, int out_size)
{
    const float* query = (const float*)d_in[0];
    const float* key   = (const float*)d_in[1];
    const float* value = (const float*)d_in[2];
    const float* Wq    = (const float*)d_in[3];
    const float* Wk    = (const float*)d_in[4];
    const float* Wv    = (const float*)d_in[5];
    const float* Wo    = (const float*)d_in[6];
    const float* bo    = (const float*)d_in[7];
    const float* rel_k = (const float*)d_in[8];
    const float* rel_v = (const float*)d_in[9];

    float* out      = (float*)d_out;                 // [B,S,D]
    float* out_attn = out + (size_t)Bb * Sq * Dm;    // [B,S,S]

    const int fused_smem = (16 * PBUF_PAD + 16 * 96) * (int)sizeof(float);
    static bool attr_set = false;
    if (!attr_set) {
        cudaFuncSetAttribute(softmax_fused_kernel,
                             cudaFuncAttributeMaxDynamicSharedMemorySize, fused_smem);
        cudaFuncSetAttribute(proj3h_kernel,
                             cudaFuncAttributeMaxDynamicSharedMemorySize, PROJ_SMEM);
        cudaFuncSetAttribute(outprojh_kernel,
                             cudaFuncAttributeMaxDynamicSharedMemorySize, PROJ_SMEM);
        cudaFuncSetAttribute(ctxh_kernel,
                             cudaFuncAttributeMaxDynamicSharedMemorySize, CTX_SMEM);
        attr_set = true;
    }

    // 0. prep: fp16 conversions
    cvt_inputs_kernel<<<dim3(Mrows * Dm / 4 / 256, 3), 256>>>(query, key, value);
    cvt_w_kernel<<<dim3(Dm / 32, Dm / 32, 4), 256>>>(Wq, Wk, Wv, Wo);
    cvt_relv_kernel<<<1, 256>>>(rel_v);

    // 1. projections (fp16 mma + ldmatrix)
    proj3h_kernel<<<dim3(Dm / 128, Mrows / 128, 3), 256, PROJ_SMEM>>>();

    // 2. rel_k dot products
    relk_kernel<<<dim3(Sq / 128, BH), 128>>>(rel_k);

    // 3. scores + rel bias -> g_attn (fp32 logits)
    scores_kernel<<<dim3(Sq / 64, Sq / 64, BH), 256>>>();

    // 4. softmax -> fp16 probs + bucket sums + head-mean
    softmax_fused_kernel<<<dim3(Sq, Bb), 512, fused_smem>>>(out_attn);

    // 5. context = attn@V + W@rel_v (fp16 mma + ldmatrix)
    ctxh_kernel<<<dim3(Sq / 128, BH), 256, CTX_SMEM>>>();

    // 6. output projection + bias (fp16 mma, fp32 out)
    outprojh_kernel<<<dim3(Dm / 128, Mrows / 128), 256, PROJ_SMEM>>>(bo, out);
}

// round 10
// speedup vs baseline: 5.5019x; 1.0376x over previous
#include <cuda_runtime.h>
#include <cuda_fp16.h>
#include <cstdint>
#include <cstddef>

#define Sq 1024
#define Bb 4
#define Dm 1024
#define Hh 16
#define DK 64
#define NR 65
#define WPAD 96
#define BH (Bb*Hh)
#define Mrows (Bb*Sq)
#define PBUF_PAD 1028

// ---------------- scratch (device globals; no allocation) ----------------
__device__ __align__(128) float  g_attn[(size_t)BH * Sq * Sq];    // fp32 logits, 256 MB
__device__ __align__(128) __half g_attnh[(size_t)BH * Sq * Sq];   // fp16 probs, 128 MB
__device__ __align__(128) __half g_Qh[(size_t)Mrows * Dm];
__device__ __align__(128) __half g_Kh[(size_t)Mrows * Dm];
__device__ __align__(128) __half g_Vh[(size_t)Mrows * Dm];
__device__ __align__(128) __half g_ctxh[(size_t)Mrows * Dm];
__device__ __align__(128) __half g_Xh[(size_t)3 * Mrows * Dm];    // fp16 inputs q,k,v
__device__ __align__(128) __half g_Wth[(size_t)4 * Dm * Dm];      // W^T fp16: q,k,v,o
__device__ __align__(128) __half g_Wh[(size_t)BH * Sq * WPAD];    // bucket sums fp16
__device__ __align__(128) __half g_relvh[96 * DK];                // rel_v fp16, zero-padded
__device__ __align__(128) float  g_Rt[(size_t)BH * NR * Sq];      // rel_k bias, transposed

// ---------------- helpers ----------------
__device__ __forceinline__ void mma16(float4& d, const uint32_t* a, const uint32_t* b) {
    asm volatile("mma.sync.aligned.m16n8k16.row.col.f32.f16.f16.f32 "
                 "{%0,%1,%2,%3},{%4,%5,%6,%7},{%8,%9},{%0,%1,%2,%3};"
                 : "+f"(d.x), "+f"(d.y), "+f"(d.z), "+f"(d.w)
                 : "r"(a[0]), "r"(a[1]), "r"(a[2]), "r"(a[3]), "r"(b[0]), "r"(b[1]));
}
__device__ __forceinline__ void ldm_x4(uint32_t* r, uint32_t a) {
    asm volatile("ldmatrix.sync.aligned.m8n8.x4.shared.b16 {%0,%1,%2,%3}, [%4];"
                 : "=r"(r[0]), "=r"(r[1]), "=r"(r[2]), "=r"(r[3]) : "r"(a));
}
__device__ __forceinline__ void ldm_x4_t(uint32_t* r, uint32_t a) {
    asm volatile("ldmatrix.sync.aligned.m8n8.x4.trans.shared.b16 {%0,%1,%2,%3}, [%4];"
                 : "=r"(r[0]), "=r"(r[1]), "=r"(r[2]), "=r"(r[3]) : "r"(a));
}
__device__ __forceinline__ void cp16(void* dst, const void* src) {
    uint32_t d = (uint32_t)__cvta_generic_to_shared(dst);
    asm volatile("cp.async.cg.shared.global [%0], [%1], 16;" :: "r"(d), "l"(src) : "memory");
}
__device__ __forceinline__ void cp16s(uint32_t dst, const void* src) {
    asm volatile("cp.async.cg.shared.global [%0], [%1], 16;" :: "r"(dst), "l"(src) : "memory");
}
#define CP_COMMIT() asm volatile("cp.async.commit_group;" ::: "memory")
#define CP_WAIT1()  asm volatile("cp.async.wait_group 1;" ::: "memory")

// ---------------- prep kernels ----------------
__global__ __launch_bounds__(256) void cvt_inputs_kernel(
    const float* __restrict__ q, const float* __restrict__ k, const float* __restrict__ v)
{
    const int z = blockIdx.y;
    const float4* s = (const float4*)(z == 0 ? q : z == 1 ? k : v);
    const int idx = blockIdx.x * 256 + threadIdx.x;
    float4 a = s[idx];
    __half2* d = (__half2*)(g_Xh + (size_t)z * Mrows * Dm);
    d[idx * 2]     = __floats2half2_rn(a.x, a.y);
    d[idx * 2 + 1] = __floats2half2_rn(a.z, a.w);
}

__global__ __launch_bounds__(256) void cvt_w_kernel(
    const float* __restrict__ Wq, const float* __restrict__ Wk,
    const float* __restrict__ Wv, const float* __restrict__ Wo)
{
    __shared__ float t[32][33];
    const int z = blockIdx.z;
    const float* W = (z == 0) ? Wq : (z == 1) ? Wk : (z == 2) ? Wv : Wo;
    __half* Wt = g_Wth + (size_t)z * Dm * Dm;
    const int x0 = blockIdx.x * 32, y0 = blockIdx.y * 32;
    const int tx = threadIdx.x & 31, ty = threadIdx.x >> 5;
    #pragma unroll
    for (int i = 0; i < 4; i++)
        t[ty + 8 * i][tx] = W[(size_t)(y0 + ty + 8 * i) * Dm + x0 + tx];
    __syncthreads();
    #pragma unroll
    for (int i = 0; i < 4; i++)
        Wt[(size_t)(x0 + ty + 8 * i) * Dm + y0 + tx] = __float2half(t[tx][ty + 8 * i]);
}

__global__ __launch_bounds__(256) void cvt_relv_kernel(const float* __restrict__ rel_v)
{
    for (int idx = threadIdx.x; idx < 96 * DK; idx += 256) {
        const int row = idx / DK, col = idx % DK;
        g_relvh[idx] = __float2half(row < NR ? rel_v[row * DK + col] : 0.f);
    }
}

// =====================================================================
// fp16 GEMM: C[4096,1024](tile 128x128) = A[m][k] @ Bt[n][k]^T (+bias)
// BM=128, BN=128, BK=64; 3-stage cp.async ring; 8 warps 2x4; warp 64x32
// pitch-144 rows (pad 72 fp16): LDSM conflict-free; 64 HMMA per barrier
// =====================================================================
struct ProjStage { __half As[128][72]; __half Bs[128][72]; };
#define PROJ_STAGE_SZ ((int)sizeof(ProjStage))   // 36864
#define PROJ_SMEM (3 * PROJ_STAGE_SZ)            // 110592

template<bool HALF_OUT>
__device__ __forceinline__ void gemm_h_body(const __half* __restrict__ A,
                                            const __half* __restrict__ Bt,
                                            const float* __restrict__ bias,
                                            void* __restrict__ Cv)
{
    extern __shared__ ProjStage pstages[];
    const int tid = threadIdx.x, lane = tid & 31, wid = tid >> 5;
    const int g = lane >> 2, t = lane & 3;
    const int wm = (wid >> 2) * 64, wn = (wid & 3) * 32;
    const int row0 = blockIdx.y * 128, col0 = blockIdx.x * 128;

    const uint32_t sb = (uint32_t)__cvta_generic_to_shared(pstages);
    // A ldmatrix: rows m0+(L&7)+((L>>3)&1)*8 (pitch 144B), col k0+(L>>4)*8
    const uint32_t laneA = (uint32_t)(((lane & 7) + ((lane >> 3) & 1) * 8) * 144 + (lane >> 4) * 16);
    // B x4 covering two n-groups: M0=(n0,k0) M1=(n0,k0+8) M2=(n0+8,k0) M3=(n0+8,k0+8)
    const uint32_t laneB = (uint32_t)((lane & 7) * 144 + ((lane >> 3) & 1) * 16 + (lane >> 4) * 1152);
    const uint32_t warpA = (uint32_t)(wm * 144) + laneA;
    const uint32_t warpB = (uint32_t)(18432 + wn * 144) + laneB;

    auto issue = [&](int kt, int s) {
        ProjStage& st = pstages[s];
        const int kb = kt * 64;
        #pragma unroll
        for (int it = 0; it < 4; it++) {
            const int id = it * 256 + tid;
            const int row = id >> 3, seg = id & 7;
            cp16(&st.As[row][seg * 8], &A[(size_t)(row0 + row) * 1024 + kb + seg * 8]);
            cp16(&st.Bs[row][seg * 8], &Bt[(size_t)(col0 + row) * 1024 + kb + seg * 8]);
        }
    };

    float4 acc[4][4];
    #pragma unroll
    for (int i = 0; i < 4; i++)
        #pragma unroll
        for (int j = 0; j < 4; j++) acc[i][j] = make_float4(0.f, 0.f, 0.f, 0.f);

    issue(0, 0); CP_COMMIT();
    issue(1, 1); CP_COMMIT();

    int scur = 0, snxt = 2;
    #pragma unroll 1
    for (int kt = 0; kt < 16; kt++) {
        CP_WAIT1();
        __syncthreads();
        if (kt + 2 < 16) issue(kt + 2, snxt);
        CP_COMMIT();

        const uint32_t stb = sb + scur * PROJ_STAGE_SZ;
        #pragma unroll
        for (int ks = 0; ks < 4; ks++) {
            const uint32_t k0b = ks * 32;   // 16 fp16 = 32 bytes per k-step
            uint32_t af[4][4], bf[4][2];
            #pragma unroll
            for (int ma = 0; ma < 4; ma++)
                ldm_x4(af[ma], stb + warpA + ma * 2304 + k0b);
            #pragma unroll
            for (int p = 0; p < 2; p++) {
                uint32_t bq[4];
                ldm_x4(bq, stb + warpB + p * 2304 + k0b);
                bf[2 * p][0] = bq[0]; bf[2 * p][1] = bq[1];
                bf[2 * p + 1][0] = bq[2]; bf[2 * p + 1][1] = bq[3];
            }
            #pragma unroll
            for (int ma = 0; ma < 4; ma++)
                #pragma unroll
                for (int na = 0; na < 4; na++)
                    mma16(acc[ma][na], af[ma], bf[na]);
        }
        scur = (scur + 1 == 3) ? 0 : scur + 1;
        snxt = (snxt + 1 == 3) ? 0 : snxt + 1;
    }

    #pragma unroll
    for (int ma = 0; ma < 4; ma++) {
        const int r = row0 + wm + ma * 16 + g;
        #pragma unroll
        for (int na = 0; na < 4; na++) {
            const int c = col0 + wn + na * 8 + 2 * t;
            if (HALF_OUT) {
                __half* Ch = (__half*)Cv;
                *(__half2*)&Ch[(size_t)r * 1024 + c]       = __floats2half2_rn(acc[ma][na].x, acc[ma][na].y);
                *(__half2*)&Ch[(size_t)(r + 8) * 1024 + c] = __floats2half2_rn(acc[ma][na].z, acc[ma][na].w);
            } else {
                float* Cf = (float*)Cv;
                const float bx = bias[c], by = bias[c + 1];
                *(float2*)&Cf[(size_t)r * 1024 + c]       = make_float2(acc[ma][na].x + bx, acc[ma][na].y + by);
                *(float2*)&Cf[(size_t)(r + 8) * 1024 + c] = make_float2(acc[ma][na].z + bx, acc[ma][na].w + by);
            }
        }
    }
}

__global__ __launch_bounds__(256, 2) void proj3h_kernel()
{
    const int z = blockIdx.z;
    const __half* A = g_Xh + (size_t)z * Mrows * Dm;
    const __half* Bt = g_Wth + (size_t)z * Dm * Dm;
    __half* C = (z == 0) ? g_Qh : (z == 1) ? g_Kh : g_Vh;
    gemm_h_body<true>(A, Bt, nullptr, C);
}

__global__ __launch_bounds__(256, 2) void outprojh_kernel(
    const float* __restrict__ bo, float* __restrict__ out)
{
    gemm_h_body<false>(g_ctxh, g_Wth + (size_t)3 * Dm * Dm, bo, out);
}

// =====================================================================
// relk: Rt[bh][r][i] = dot(Q[b,i,h*64:], rel_k[r,:])
// =====================================================================
__global__ __launch_bounds__(128) void relk_kernel(const float* __restrict__ rel_k)
{
    __shared__ float4 RK[NR][16];
    const int bh = blockIdx.y;
    const int b = bh >> 4, h = bh & 15;
    const int i0 = blockIdx.x * 128;
    const int tid = threadIdx.x;

    for (int idx = tid; idx < NR * 16; idx += 128)
        RK[idx / 16][idx % 16] = ((const float4*)rel_k)[idx];
    __syncthreads();

    float2 q[32];
    const __half2* qrow = (const __half2*)&g_Qh[(size_t)(b * Sq + i0 + tid) * Dm + h * DK];
    #pragma unroll
    for (int d = 0; d < 32; d++) q[d] = __half22float2(qrow[d]);

    float* outp = &g_Rt[(size_t)bh * NR * Sq + i0 + tid];
    #pragma unroll 1
    for (int r = 0; r < NR; r++) {
        float s = 0.f;
        #pragma unroll
        for (int d = 0; d < 16; d++) {
            float4 rk = RK[r][d];
            s += q[2 * d].x * rk.x + q[2 * d].y * rk.y + q[2 * d + 1].x * rk.z + q[2 * d + 1].y * rk.w;
        }
        outp[(size_t)r * Sq] = s;
    }
}

// =====================================================================
// scores: g_attn(fp32) = QK^T/8 + Rt[rel]   (fp16 mma + ldmatrix)
// =====================================================================
__global__ __launch_bounds__(256, 2) void scores_kernel()
{
    __shared__ __align__(16) __half Qs[64][72];
    __shared__ __align__(16) __half Ks[64][72];

    const int bh = blockIdx.z;
    const int b = bh >> 4, h = bh & 15;
    const int i0 = blockIdx.y * 64, j0 = blockIdx.x * 64;
    const int tid = threadIdx.x;
    const int lane = tid & 31, wid = tid >> 5;
    const int g = lane >> 2, t = lane & 3;
    const int wm = (wid >> 2) * 32;
    const int wn = (wid & 3) * 16;

    for (int idx = tid; idx < 512; idx += 256) {
        const int r = idx >> 3, s = idx & 7;
        *(uint4*)&Qs[r][s * 8] = *(const uint4*)&g_Qh[(size_t)(b * Sq + i0 + r) * Dm + h * DK + s * 8];
        *(uint4*)&Ks[r][s * 8] = *(const uint4*)&g_Kh[(size_t)(b * Sq + j0 + r) * Dm + h * DK + s * 8];
    }
    __syncthreads();

    const uint32_t qb = (uint32_t)__cvta_generic_to_shared(Qs);
    const uint32_t kb = (uint32_t)__cvta_generic_to_shared(Ks);
    const uint32_t laneA = (uint32_t)(((lane & 7) + ((lane >> 3) & 1) * 8) * 144 + (lane >> 4) * 16);
    const uint32_t laneB = (uint32_t)((lane & 7) * 144 + ((lane >> 3) & 1) * 16 + (lane >> 4) * 1152);
    const uint32_t warpQ = qb + (uint32_t)(wm * 144) + laneA;
    const uint32_t warpK = kb + (uint32_t)(wn * 144) + laneB;

    float4 acc[2][2];
    #pragma unroll
    for (int i = 0; i < 2; i++)
        #pragma unroll
        for (int j = 0; j < 2; j++) acc[i][j] = make_float4(0.f, 0.f, 0.f, 0.f);

    #pragma unroll
    for (int ks = 0; ks < 4; ks++) {
        const uint32_t k0b = ks * 32;
        uint32_t af[2][4], bf[2][2];
        #pragma unroll
        for (int ma = 0; ma < 2; ma++)
            ldm_x4(af[ma], warpQ + ma * 2304 + k0b);
        {
            uint32_t bq[4];
            ldm_x4(bq, warpK + k0b);
            bf[0][0] = bq[0]; bf[0][1] = bq[1]; bf[1][0] = bq[2]; bf[1][1] = bq[3];
        }
        #pragma unroll
        for (int ma = 0; ma < 2; ma++)
            #pragma unroll
            for (int na = 0; na < 2; na++)
                mma16(acc[ma][na], af[ma], bf[na]);
    }

    const float* Rt = &g_Rt[(size_t)bh * NR * Sq];
    float* attnBase = &g_attn[(size_t)bh * Sq * Sq];
    #pragma unroll
    for (int ma = 0; ma < 2; ma++) {
        const int ia = i0 + wm + ma * 16 + g;
        #pragma unroll
        for (int na = 0; na < 2; na++) {
            const int ja = j0 + wn + na * 8 + 2 * t;
            #pragma unroll
            for (int e = 0; e < 4; e++) {
                const int ii = ia + (e >= 2 ? 8 : 0);
                const int jj = ja + (e & 1);
                int rel = jj - ii;
                rel = (rel < -32 ? -32 : (rel > 32 ? 32 : rel)) + 32;
                const float v = (e == 0 ? acc[ma][na].x : e == 1 ? acc[ma][na].y :
                                 e == 2 ? acc[ma][na].z : acc[ma][na].w);
                attnBase[(size_t)ii * Sq + jj] = v * 0.125f + Rt[(size_t)rel * Sq + ii];
            }
        }
    }
}

// =====================================================================
// FUSED softmax: fp32 logits in -> fp16 probs + fp16 bucket W + fp32 mean
// =====================================================================
__global__ __launch_bounds__(512) void softmax_fused_kernel(float* __restrict__ out_attn)
{
    extern __shared__ float sm[];
    float* pbuf = sm;                        // [16][PBUF_PAD]
    float* sWb  = sm + 16 * PBUF_PAD;        // [16][96]

    const int i = blockIdx.x;
    const int b = blockIdx.y;
    const int tid  = threadIdx.x;
    const int w    = tid >> 5;
    const int lane = tid & 31;
    const int bh = b * Hh + w;

    const float4* row4 = (const float4*)&g_attn[((size_t)bh * Sq + i) * Sq];
    __half2* rowh = (__half2*)&g_attnh[((size_t)bh * Sq + i) * Sq];

    float4 v[8];
    #pragma unroll
    for (int k = 0; k < 8; k++) v[k] = row4[lane + 32 * k];

    float mx = -1e30f;
    #pragma unroll
    for (int k = 0; k < 8; k++)
        mx = fmaxf(mx, fmaxf(fmaxf(v[k].x, v[k].y), fmaxf(v[k].z, v[k].w)));
    #pragma unroll
    for (int o = 16; o; o >>= 1) mx = fmaxf(mx, __shfl_xor_sync(0xFFFFFFFFu, mx, o));

    float sum = 0.f;
    #pragma unroll
    for (int k = 0; k < 8; k++) {
        v[k].x = __expf(v[k].x - mx); v[k].y = __expf(v[k].y - mx);
        v[k].z = __expf(v[k].z - mx); v[k].w = __expf(v[k].w - mx);
        sum += v[k].x + v[k].y + v[k].z + v[k].w;
    }
    #pragma unroll
    for (int o = 16; o; o >>= 1) sum += __shfl_xor_sync(0xFFFFFFFFu, sum, o);
    const float inv = 1.f / sum;

    float* sW = &sWb[w * 96];
    sW[lane] = 0.f; sW[lane + 32] = 0.f; sW[lane + 64] = 0.f;
    __syncwarp();

    float* prow = &pbuf[w * PBUF_PAD];
    float lowsum = 0.f, highsum = 0.f;
    #pragma unroll
    for (int k = 0; k < 8; k++) {
        const int j0 = (lane + 32 * k) * 4;
        v[k].x *= inv; v[k].y *= inv; v[k].z *= inv; v[k].w *= inv;
        __half2 h01 = __floats2half2_rn(v[k].x, v[k].y);
        __half2 h23 = __floats2half2_rn(v[k].z, v[k].w);
        rowh[(lane + 32 * k) * 2]     = h01;
        rowh[(lane + 32 * k) * 2 + 1] = h23;
        *(float4*)&prow[j0] = v[k];
        #pragma unroll
        for (int e = 0; e < 4; e++) {
            const int j = j0 + e;
            const float p = (e == 0 ? v[k].x : e == 1 ? v[k].y : e == 2 ? v[k].z : v[k].w);
            const int d = j - i;
            if (d <= -32)      lowsum  += p;
            else if (d >= 32)  highsum += p;
            else               sW[d + 32] = p;
        }
    }
    #pragma unroll
    for (int o = 16; o; o >>= 1) {
        lowsum  += __shfl_xor_sync(0xFFFFFFFFu, lowsum,  o);
        highsum += __shfl_xor_sync(0xFFFFFFFFu, highsum, o);
    }
    if (lane == 0) { sW[0] = lowsum; sW[64] = highsum; }
    __syncwarp();

    __half* gw = &g_Wh[(size_t)(bh * Sq + i) * WPAD];
    gw[lane]      = __float2half(sW[lane]);
    gw[lane + 32] = __float2half(sW[lane + 32]);
    gw[lane + 64] = __float2half(sW[lane + 64]);

    __syncthreads();
    float* orow = &out_attn[((size_t)b * Sq + i) * Sq];
    #pragma unroll
    for (int rep = 0; rep < 2; rep++) {
        const int j = tid + rep * 512;
        float s = 0.f;
        #pragma unroll
        for (int h = 0; h < Hh; h++) s += pbuf[h * PBUF_PAD + j];
        orow[j] = s * (1.0f / Hh);
    }
}

// =====================================================================
// ctx = attn @ V + W @ rel_v  (fp16 mma + ldmatrix/.trans; BM=128,BN=64)
// =====================================================================
struct CtxStage { __half As[128][40]; __half Bs[32][72]; };
#define CTX_STAGE_SZ ((int)sizeof(CtxStage))   // 14848
#define CTX_SMEM (3 * CTX_STAGE_SZ)

__global__ __launch_bounds__(256, 2) void ctxh_kernel()
{
    extern __shared__ CtxStage cstages[];

    const int bh = blockIdx.y;
    const int b = bh >> 4, h = bh & 15;
    const int i0 = blockIdx.x * 128;
    const int tid = threadIdx.x;
    const int lane = tid & 31, wid = tid >> 5;
    const int g = lane >> 2, t = lane & 3;
    const int wm = (wid >> 2) * 64;
    const int wn = (wid & 3) * 16;

    const uint32_t sb = (uint32_t)__cvta_generic_to_shared(cstages);
    const uint32_t laneA = (uint32_t)(((lane & 7) + ((lane >> 3) & 1) * 8) * 80 + (lane >> 4) * 16);
    const uint32_t laneBt = (uint32_t)(((lane & 7) + ((lane >> 3) & 1) * 8) * 144 + (lane >> 4) * 16);
    const uint32_t warpA  = (uint32_t)(wm * 80) + laneA;
    const uint32_t warpBt = (uint32_t)(10240 + wn * 2) + laneBt;

    auto issue = [&](int kt, int s) {
        CtxStage& st = cstages[s];
        if (kt < 32) {
            const int kb = kt * 32;
            #pragma unroll
            for (int it = 0; it < 2; it++) {
                const int id = it * 256 + tid;
                const int row = id >> 2, seg = id & 3;
                cp16(&st.As[row][seg * 8],
                     &g_attnh[((size_t)bh * Sq + i0 + row) * Sq + kb + seg * 8]);
            }
            const int vr = tid >> 3, vs = tid & 7;
            cp16(&st.Bs[vr][vs * 8],
                 &g_Vh[(size_t)(b * Sq + kb + vr) * Dm + h * DK + vs * 8]);
        } else {
            const int kk = (kt - 32) * 32;
            #pragma unroll
            for (int it = 0; it < 2; it++) {
                const int id = it * 256 + tid;
                const int row = id >> 2, seg = id & 3;
                cp16(&st.As[row][seg * 8],
                     &g_Wh[(size_t)(bh * Sq + i0 + row) * WPAD + kk + seg * 8]);
            }
            const int vr = tid >> 3, vs = tid & 7;
            cp16(&st.Bs[vr][vs * 8], &g_relvh[(kk + vr) * DK + vs * 8]);
        }
    };

    float4 acc[4][2];
    #pragma unroll
    for (int i = 0; i < 4; i++)
        #pragma unroll
        for (int j = 0; j < 2; j++) acc[i][j] = make_float4(0.f, 0.f, 0.f, 0.f);

    issue(0, 0); CP_COMMIT();
    issue(1, 1); CP_COMMIT();

    int scur = 0, snxt = 2;
    #pragma unroll 1
    for (int kt = 0; kt < 35; kt++) {
        CP_WAIT1();
        __syncthreads();
        if (kt + 2 < 35) issue(kt + 2, snxt);
        CP_COMMIT();

        const uint32_t stb = sb + scur * CTX_STAGE_SZ;
        #pragma unroll
        for (int ks = 0; ks < 2; ks++) {
            uint32_t af[4][4], bf[2][2];
            #pragma unroll
            for (int ma = 0; ma < 4; ma++)
                ldm_x4(af[ma], stb + warpA + ma * 1280 + ks * 32);
            {
                uint32_t bq[4];
                ldm_x4_t(bq, stb + warpBt + ks * 16 * 144);
                bf[0][0] = bq[0]; bf[0][1] = bq[1]; bf[1][0] = bq[2]; bf[1][1] = bq[3];
            }
            #pragma unroll
            for (int ma = 0; ma < 4; ma++)
                #pragma unroll
                for (int na = 0; na < 2; na++)
                    mma16(acc[ma][na], af[ma], bf[na]);
        }
        scur = (scur + 1 == 3) ? 0 : scur + 1;
        snxt = (snxt + 1 == 3) ? 0 : snxt + 1;
    }

    #pragma unroll
    for (int ma = 0; ma < 4; ma++) {
        const int r = i0 + wm + ma * 16 + g;
        #pragma unroll
        for (int na = 0; na < 2; na++) {
            const int c = wn + na * 8 + 2 * t;
            *(__half2*)&g_ctxh[(size_t)(b * Sq + r) * Dm + h * DK + c] =
                __floats2half2_rn(acc[ma][na].x, acc[ma][na].y);
            *(__half2*)&g_ctxh[(size_t)(b * Sq + r + 8) * Dm + h * DK + c] =
                __floats2half2_rn(acc[ma][na].z, acc[ma][na].w);
        }
    }
}

// ---------------- launch ----------------
extern "C" void kernel_launch(void* const* d_in, const int* in_sizes, int n_in,
                              void* d_out, int out_size)
{
    const float* query = (const float*)d_in[0];
    const float* key   = (const float*)d_in[1];
    const float* value = (const float*)d_in[2];
    const float* Wq    = (const float*)d_in[3];
    const float* Wk    = (const float*)d_in[4];
    const float* Wv    = (const float*)d_in[5];
    const float* Wo    = (const float*)d_in[6];
    const float* bo    = (const float*)d_in[7];
    const float* rel_k = (const float*)d_in[8];
    const float* rel_v = (const float*)d_in[9];

    float* out      = (float*)d_out;                 // [B,S,D]
    float* out_attn = out + (size_t)Bb * Sq * Dm;    // [B,S,S]

    const int fused_smem = (16 * PBUF_PAD + 16 * 96) * (int)sizeof(float);
    static bool attr_set = false;
    if (!attr_set) {
        cudaFuncSetAttribute(softmax_fused_kernel,
                             cudaFuncAttributeMaxDynamicSharedMemorySize, fused_smem);
        cudaFuncSetAttribute(proj3h_kernel,
                             cudaFuncAttributeMaxDynamicSharedMemorySize, PROJ_SMEM);
        cudaFuncSetAttribute(outprojh_kernel,
                             cudaFuncAttributeMaxDynamicSharedMemorySize, PROJ_SMEM);
        cudaFuncSetAttribute(ctxh_kernel,
                             cudaFuncAttributeMaxDynamicSharedMemorySize, CTX_SMEM);
        attr_set = true;
    }

    // 0. prep: fp16 conversions
    cvt_inputs_kernel<<<dim3(Mrows * Dm / 4 / 256, 3), 256>>>(query, key, value);
    cvt_w_kernel<<<dim3(Dm / 32, Dm / 32, 4), 256>>>(Wq, Wk, Wv, Wo);
    cvt_relv_kernel<<<1, 256>>>(rel_v);

    // 1. projections (fp16 mma + ldmatrix, BK=64)
    proj3h_kernel<<<dim3(Dm / 128, Mrows / 128, 3), 256, PROJ_SMEM>>>();

    // 2. rel_k dot products
    relk_kernel<<<dim3(Sq / 128, BH), 128>>>(rel_k);

    // 3. scores + rel bias -> g_attn (fp32 logits)
    scores_kernel<<<dim3(Sq / 64, Sq / 64, BH), 256>>>();

    // 4. softmax -> fp16 probs + bucket sums + head-mean
    softmax_fused_kernel<<<dim3(Sq, Bb), 512, fused_smem>>>(out_attn);

    // 5. context = attn@V + W@rel_v (fp16 mma + ldmatrix)
    ctxh_kernel<<<dim3(Sq / 128, BH), 256, CTX_SMEM>>>();

    // 6. output projection + bias (fp16 mma + ldmatrix, BK=64)
    outprojh_kernel<<<dim3(Dm / 128, Mrows / 128), 256, PROJ_SMEM>>>(bo, out);
}

// round 11
// speedup vs baseline: 5.7220x; 1.0400x over previous
#include <cuda_runtime.h>
#include <cuda_fp16.h>
#include <cstdint>
#include <cstddef>

#define Sq 1024
#define Bb 4
#define Dm 1024
#define Hh 16
#define DK 64
#define NR 65
#define WPAD 96
#define BH (Bb*Hh)
#define Mrows (Bb*Sq)

// ---------------- scratch (device globals; no allocation) ----------------
__device__ __align__(128) __half g_attnh[(size_t)BH * Sq * Sq];   // fp16 probs, 128 MB
__device__ __align__(128) __half g_Qh[(size_t)Mrows * Dm];
__device__ __align__(128) __half g_Kh[(size_t)Mrows * Dm];
__device__ __align__(128) __half g_Vh[(size_t)Mrows * Dm];
__device__ __align__(128) __half g_ctxh[(size_t)Mrows * Dm];
__device__ __align__(128) __half g_Xh[(size_t)3 * Mrows * Dm];    // fp16 inputs q,k,v
__device__ __align__(128) __half g_Wth[(size_t)4 * Dm * Dm];      // W^T fp16: q,k,v,o
__device__ __align__(128) __half g_Wh[(size_t)BH * Sq * WPAD];    // bucket sums fp16
__device__ __align__(128) __half g_relvh[96 * DK];                // rel_v fp16, zero-padded
__device__ __align__(128) float  g_Rt[(size_t)BH * NR * Sq];      // rel_k bias, transposed

// ---------------- helpers ----------------
__device__ __forceinline__ void mma16(float4& d, const uint32_t* a, const uint32_t* b) {
    asm volatile("mma.sync.aligned.m16n8k16.row.col.f32.f16.f16.f32 "
                 "{%0,%1,%2,%3},{%4,%5,%6,%7},{%8,%9},{%0,%1,%2,%3};"
                 : "+f"(d.x), "+f"(d.y), "+f"(d.z), "+f"(d.w)
                 : "r"(a[0]), "r"(a[1]), "r"(a[2]), "r"(a[3]), "r"(b[0]), "r"(b[1]));
}
__device__ __forceinline__ void ldm_x4(uint32_t* r, uint32_t a) {
    asm volatile("ldmatrix.sync.aligned.m8n8.x4.shared.b16 {%0,%1,%2,%3}, [%4];"
                 : "=r"(r[0]), "=r"(r[1]), "=r"(r[2]), "=r"(r[3]) : "r"(a));
}
__device__ __forceinline__ void ldm_x4_t(uint32_t* r, uint32_t a) {
    asm volatile("ldmatrix.sync.aligned.m8n8.x4.trans.shared.b16 {%0,%1,%2,%3}, [%4];"
                 : "=r"(r[0]), "=r"(r[1]), "=r"(r[2]), "=r"(r[3]) : "r"(a));
}
__device__ __forceinline__ void cp16(void* dst, const void* src) {
    uint32_t d = (uint32_t)__cvta_generic_to_shared(dst);
    asm volatile("cp.async.cg.shared.global [%0], [%1], 16;" :: "r"(d), "l"(src) : "memory");
}
__device__ __forceinline__ void cp16s(uint32_t dst, const void* src) {
    asm volatile("cp.async.cg.shared.global [%0], [%1], 16;" :: "r"(dst), "l"(src) : "memory");
}
#define CP_COMMIT() asm volatile("cp.async.commit_group;" ::: "memory")
#define CP_WAIT1()  asm volatile("cp.async.wait_group 1;" ::: "memory")
#define CP_WAIT0()  asm volatile("cp.async.wait_group 0;" ::: "memory")

// ---------------- prep kernels ----------------
__global__ __launch_bounds__(256) void cvt_inputs_kernel(
    const float* __restrict__ q, const float* __restrict__ k, const float* __restrict__ v)
{
    const int z = blockIdx.y;
    const float4* s = (const float4*)(z == 0 ? q : z == 1 ? k : v);
    const int idx = blockIdx.x * 256 + threadIdx.x;
    float4 a = s[idx];
    __half2* d = (__half2*)(g_Xh + (size_t)z * Mrows * Dm);
    d[idx * 2]     = __floats2half2_rn(a.x, a.y);
    d[idx * 2 + 1] = __floats2half2_rn(a.z, a.w);
}

__global__ __launch_bounds__(256) void cvt_w_kernel(
    const float* __restrict__ Wq, const float* __restrict__ Wk,
    const float* __restrict__ Wv, const float* __restrict__ Wo)
{
    __shared__ float t[32][33];
    const int z = blockIdx.z;
    const float* W = (z == 0) ? Wq : (z == 1) ? Wk : (z == 2) ? Wv : Wo;
    __half* Wt = g_Wth + (size_t)z * Dm * Dm;
    const int x0 = blockIdx.x * 32, y0 = blockIdx.y * 32;
    const int tx = threadIdx.x & 31, ty = threadIdx.x >> 5;
    #pragma unroll
    for (int i = 0; i < 4; i++)
        t[ty + 8 * i][tx] = W[(size_t)(y0 + ty + 8 * i) * Dm + x0 + tx];
    __syncthreads();
    #pragma unroll
    for (int i = 0; i < 4; i++)
        Wt[(size_t)(x0 + ty + 8 * i) * Dm + y0 + tx] = __float2half(t[tx][ty + 8 * i]);
}

__global__ __launch_bounds__(256) void cvt_relv_kernel(const float* __restrict__ rel_v)
{
    for (int idx = threadIdx.x; idx < 96 * DK; idx += 256) {
        const int row = idx / DK, col = idx % DK;
        g_relvh[idx] = __float2half(row < NR ? rel_v[row * DK + col] : 0.f);
    }
}

// =====================================================================
// fp16 GEMM: C[4096,1024](tile 128x128) = A[m][k] @ Bt[n][k]^T (+bias)
// BM=128, BN=128, BK=64; 3-stage cp.async ring; 8 warps 2x4; warp 64x32
// =====================================================================
struct ProjStage { __half As[128][72]; __half Bs[128][72]; };
#define PROJ_STAGE_SZ ((int)sizeof(ProjStage))   // 36864
#define PROJ_SMEM (3 * PROJ_STAGE_SZ)            // 110592

template<bool HALF_OUT>
__device__ __forceinline__ void gemm_h_body(const __half* __restrict__ A,
                                            const __half* __restrict__ Bt,
                                            const float* __restrict__ bias,
                                            void* __restrict__ Cv)
{
    extern __shared__ ProjStage pstages[];
    const int tid = threadIdx.x, lane = tid & 31, wid = tid >> 5;
    const int g = lane >> 2, t = lane & 3;
    const int wm = (wid >> 2) * 64, wn = (wid & 3) * 32;
    const int row0 = blockIdx.y * 128, col0 = blockIdx.x * 128;

    const uint32_t sb = (uint32_t)__cvta_generic_to_shared(pstages);
    const uint32_t laneA = (uint32_t)(((lane & 7) + ((lane >> 3) & 1) * 8) * 144 + (lane >> 4) * 16);
    const uint32_t laneB = (uint32_t)((lane & 7) * 144 + ((lane >> 3) & 1) * 16 + (lane >> 4) * 1152);
    const uint32_t warpA = (uint32_t)(wm * 144) + laneA;
    const uint32_t warpB = (uint32_t)(18432 + wn * 144) + laneB;

    auto issue = [&](int kt, int s) {
        ProjStage& st = pstages[s];
        const int kb = kt * 64;
        #pragma unroll
        for (int it = 0; it < 4; it++) {
            const int id = it * 256 + tid;
            const int row = id >> 3, seg = id & 7;
            cp16(&st.As[row][seg * 8], &A[(size_t)(row0 + row) * 1024 + kb + seg * 8]);
            cp16(&st.Bs[row][seg * 8], &Bt[(size_t)(col0 + row) * 1024 + kb + seg * 8]);
        }
    };

    float4 acc[4][4];
    #pragma unroll
    for (int i = 0; i < 4; i++)
        #pragma unroll
        for (int j = 0; j < 4; j++) acc[i][j] = make_float4(0.f, 0.f, 0.f, 0.f);

    issue(0, 0); CP_COMMIT();
    issue(1, 1); CP_COMMIT();

    int scur = 0, snxt = 2;
    #pragma unroll 1
    for (int kt = 0; kt < 16; kt++) {
        CP_WAIT1();
        __syncthreads();
        if (kt + 2 < 16) issue(kt + 2, snxt);
        CP_COMMIT();

        const uint32_t stb = sb + scur * PROJ_STAGE_SZ;
        #pragma unroll
        for (int ks = 0; ks < 4; ks++) {
            const uint32_t k0b = ks * 32;
            uint32_t af[4][4], bf[4][2];
            #pragma unroll
            for (int ma = 0; ma < 4; ma++)
                ldm_x4(af[ma], stb + warpA + ma * 2304 + k0b);
            #pragma unroll
            for (int p = 0; p < 2; p++) {
                uint32_t bq[4];
                ldm_x4(bq, stb + warpB + p * 2304 + k0b);
                bf[2 * p][0] = bq[0]; bf[2 * p][1] = bq[1];
                bf[2 * p + 1][0] = bq[2]; bf[2 * p + 1][1] = bq[3];
            }
            #pragma unroll
            for (int ma = 0; ma < 4; ma++)
                #pragma unroll
                for (int na = 0; na < 4; na++)
                    mma16(acc[ma][na], af[ma], bf[na]);
        }
        scur = (scur + 1 == 3) ? 0 : scur + 1;
        snxt = (snxt + 1 == 3) ? 0 : snxt + 1;
    }

    #pragma unroll
    for (int ma = 0; ma < 4; ma++) {
        const int r = row0 + wm + ma * 16 + g;
        #pragma unroll
        for (int na = 0; na < 4; na++) {
            const int c = col0 + wn + na * 8 + 2 * t;
            if (HALF_OUT) {
                __half* Ch = (__half*)Cv;
                *(__half2*)&Ch[(size_t)r * 1024 + c]       = __floats2half2_rn(acc[ma][na].x, acc[ma][na].y);
                *(__half2*)&Ch[(size_t)(r + 8) * 1024 + c] = __floats2half2_rn(acc[ma][na].z, acc[ma][na].w);
            } else {
                float* Cf = (float*)Cv;
                const float bx = bias[c], by = bias[c + 1];
                *(float2*)&Cf[(size_t)r * 1024 + c]       = make_float2(acc[ma][na].x + bx, acc[ma][na].y + by);
                *(float2*)&Cf[(size_t)(r + 8) * 1024 + c] = make_float2(acc[ma][na].z + bx, acc[ma][na].w + by);
            }
        }
    }
}

__global__ __launch_bounds__(256, 2) void proj3h_kernel()
{
    const int z = blockIdx.z;
    const __half* A = g_Xh + (size_t)z * Mrows * Dm;
    const __half* Bt = g_Wth + (size_t)z * Dm * Dm;
    __half* C = (z == 0) ? g_Qh : (z == 1) ? g_Kh : g_Vh;
    gemm_h_body<true>(A, Bt, nullptr, C);
}

__global__ __launch_bounds__(256, 2) void outprojh_kernel(
    const float* __restrict__ bo, float* __restrict__ out)
{
    gemm_h_body<false>(g_ctxh, g_Wth + (size_t)3 * Dm * Dm, bo, out);
}

// =====================================================================
// relk: Rt[bh][r][i] = dot(Q[b,i,h*64:], rel_k[r,:])
// =====================================================================
__global__ __launch_bounds__(128) void relk_kernel(const float* __restrict__ rel_k)
{
    __shared__ float4 RK[NR][16];
    const int bh = blockIdx.y;
    const int b = bh >> 4, h = bh & 15;
    const int i0 = blockIdx.x * 128;
    const int tid = threadIdx.x;

    for (int idx = tid; idx < NR * 16; idx += 128)
        RK[idx / 16][idx % 16] = ((const float4*)rel_k)[idx];
    __syncthreads();

    float2 q[32];
    const __half2* qrow = (const __half2*)&g_Qh[(size_t)(b * Sq + i0 + tid) * Dm + h * DK];
    #pragma unroll
    for (int d = 0; d < 32; d++) q[d] = __half22float2(qrow[d]);

    float* outp = &g_Rt[(size_t)bh * NR * Sq + i0 + tid];
    #pragma unroll 1
    for (int r = 0; r < NR; r++) {
        float s = 0.f;
        #pragma unroll
        for (int d = 0; d < 16; d++) {
            float4 rk = RK[r][d];
            s += q[2 * d].x * rk.x + q[2 * d].y * rk.y + q[2 * d + 1].x * rk.z + q[2 * d + 1].y * rk.w;
        }
        outp[(size_t)r * Sq] = s;
    }
}

// =====================================================================
// FUSED scores+softmax: logits live in registers only.
// Block = 32 query rows x 1 head x all 1024 keys. 256 threads (8 warps).
// K (1024x64 fp16) + Q (32x64) staged in smem, SW128 swizzle.
// Warp wp owns key cols [wp*128, wp*128+128); acc = 32x128 fp32 in regs.
// Outputs: fp16 probs (g_attnh), fp16 bucket W (g_Wh).
// =====================================================================
#define SMX_K    0
#define SMX_Q    131072
#define SMX_PMAX 135168
#define SMX_PSUM 136192
#define SMX_PLOW 137216
#define SMX_PHI  138240
#define SMX_FMAX 139264
#define SMX_FINV 139392
#define SMX_SW   139520
#define SMX_SMEM 151808

__global__ __launch_bounds__(256, 1) void scoresmax_kernel()
{
    extern __shared__ char smx[];
    float* pmax = (float*)(smx + SMX_PMAX);   // [32][8]
    float* psum = (float*)(smx + SMX_PSUM);
    float* plow = (float*)(smx + SMX_PLOW);
    float* phi  = (float*)(smx + SMX_PHI);
    float* fmax = (float*)(smx + SMX_FMAX);   // [32]
    float* finv = (float*)(smx + SMX_FINV);   // [32]
    float* sW   = (float*)(smx + SMX_SW);     // [32][96]

    const int bh = blockIdx.y;
    const int b = bh >> 4, h = bh & 15;
    const int i0 = blockIdx.x * 32;
    const int tid = threadIdx.x;
    const int lane = tid & 31, wp = tid >> 5;
    const int g = lane >> 2, t = lane & 3;

    const uint32_t sbK = (uint32_t)__cvta_generic_to_shared(smx + SMX_K);
    const uint32_t sbQ = (uint32_t)__cvta_generic_to_shared(smx + SMX_Q);

    // zero sW band buffer
    for (int idx = tid; idx < 32 * 96; idx += 256) sW[idx] = 0.f;

    // stage K: 1024 rows x 128B, swizzled
    for (int id = tid; id < 8192; id += 256) {
        const int row = id >> 3, seg = id & 7;
        const uint32_t dst = sbK + row * 128 + ((seg * 16) ^ ((row & 7) << 4));
        cp16s(dst, &g_Kh[(size_t)(b * Sq + row) * Dm + h * DK + seg * 8]);
    }
    // stage Q: 32 rows x 128B (256 threads = exactly 32x8 segs)
    {
        const int row = tid >> 3, seg = tid & 7;
        const uint32_t dst = sbQ + row * 128 + ((seg * 16) ^ ((row & 7) << 4));
        cp16s(dst, &g_Qh[(size_t)(b * Sq + i0 + row) * Dm + h * DK + seg * 8]);
    }
    CP_COMMIT(); CP_WAIT0();
    __syncthreads();

    // ---- phase 1: QK^T (dk=64, 4 k-steps) ----
    float4 acc[2][16];
    #pragma unroll
    for (int mt = 0; mt < 2; mt++)
        #pragma unroll
        for (int nt = 0; nt < 16; nt++) acc[mt][nt] = make_float4(0.f, 0.f, 0.f, 0.f);

    const int arow = (lane & 7) + ((lane >> 3) & 1) * 8;     // A row within 16-group
    const int acolsel = (lane >> 4) * 16;                    // A k-half byte offset
    const int brow7 = lane & 7;
    const int brow = (lane & 7) + ((lane >> 4) << 3);        // B row within 16-group
    const int bcolsel = ((lane >> 3) & 1) * 16;              // B k-half byte offset

    #pragma unroll
    for (int ks = 0; ks < 4; ks++) {
        const int kb2 = ks * 32;
        uint32_t af[2][4];
        #pragma unroll
        for (int mt = 0; mt < 2; mt++) {
            const int row = mt * 16 + arow;
            const uint32_t col = (uint32_t)((kb2 + acolsel) ^ ((arow & 7) << 4));
            ldm_x4(af[mt], sbQ + row * 128 + col);
        }
        #pragma unroll
        for (int nt2 = 0; nt2 < 8; nt2++) {
            const int n0 = wp * 128 + nt2 * 16;
            const uint32_t colb = (uint32_t)((kb2 + bcolsel) ^ (brow7 << 4));
            uint32_t bq[4];
            ldm_x4(bq, sbK + (n0 + brow) * 128 + colb);
            uint32_t bf0[2] = { bq[0], bq[1] }, bf1[2] = { bq[2], bq[3] };
            #pragma unroll
            for (int mt = 0; mt < 2; mt++) {
                mma16(acc[mt][2 * nt2],     af[mt], bf0);
                mma16(acc[mt][2 * nt2 + 1], af[mt], bf1);
            }
        }
    }

    // ---- phase 2: bias + scale + row max ----
    const float* RtB = &g_Rt[(size_t)bh * NR * Sq];
    float mxa[2] = { -1e30f, -1e30f }, mxb[2] = { -1e30f, -1e30f };
    #pragma unroll
    for (int mt = 0; mt < 2; mt++) {
        const int ia = i0 + mt * 16 + g, ib = ia + 8;
        #pragma unroll
        for (int nt = 0; nt < 16; nt++) {
            const int j0 = wp * 128 + nt * 8 + 2 * t;
            float4& a = acc[mt][nt];
            int r0 = j0 - ia;     r0 = (r0 < -32 ? -32 : (r0 > 32 ? 32 : r0)) + 32;
            int r1 = j0 + 1 - ia; r1 = (r1 < -32 ? -32 : (r1 > 32 ? 32 : r1)) + 32;
            int r2 = j0 - ib;     r2 = (r2 < -32 ? -32 : (r2 > 32 ? 32 : r2)) + 32;
            int r3 = j0 + 1 - ib; r3 = (r3 < -32 ? -32 : (r3 > 32 ? 32 : r3)) + 32;
            a.x = a.x * 0.125f + RtB[(size_t)r0 * Sq + ia];
            a.y = a.y * 0.125f + RtB[(size_t)r1 * Sq + ia];
            a.z = a.z * 0.125f + RtB[(size_t)r2 * Sq + ib];
            a.w = a.w * 0.125f + RtB[(size_t)r3 * Sq + ib];
            mxa[mt] = fmaxf(mxa[mt], fmaxf(a.x, a.y));
            mxb[mt] = fmaxf(mxb[mt], fmaxf(a.z, a.w));
        }
    }
    #pragma unroll
    for (int o = 1; o <= 2; o <<= 1) {
        #pragma unroll
        for (int mt = 0; mt < 2; mt++) {
            mxa[mt] = fmaxf(mxa[mt], __shfl_xor_sync(0xFFFFFFFFu, mxa[mt], o));
            mxb[mt] = fmaxf(mxb[mt], __shfl_xor_sync(0xFFFFFFFFu, mxb[mt], o));
        }
    }
    if (t == 0) {
        #pragma unroll
        for (int mt = 0; mt < 2; mt++) {
            pmax[(mt * 16 + g) * 8 + wp]     = mxa[mt];
            pmax[(mt * 16 + g + 8) * 8 + wp] = mxb[mt];
        }
    }
    __syncthreads();
    if (tid < 32) {
        float m = -1e30f;
        #pragma unroll
        for (int ww = 0; ww < 8; ww++) m = fmaxf(m, pmax[tid * 8 + ww]);
        fmax[tid] = m;
    }
    __syncthreads();

    // ---- phase 3: exp + partial sums / low / high ----
    float sa[2] = {0.f, 0.f}, sb2[2] = {0.f, 0.f};
    float la[2] = {0.f, 0.f}, lb[2] = {0.f, 0.f};
    float ha[2] = {0.f, 0.f}, hb[2] = {0.f, 0.f};
    #pragma unroll
    for (int mt = 0; mt < 2; mt++) {
        const float ma2 = fmax[mt * 16 + g], mb2 = fmax[mt * 16 + g + 8];
        const int ia = i0 + mt * 16 + g, ib = ia + 8;
        #pragma unroll
        for (int nt = 0; nt < 16; nt++) {
            const int j0 = wp * 128 + nt * 8 + 2 * t;
            float4& a = acc[mt][nt];
            a.x = __expf(a.x - ma2); a.y = __expf(a.y - ma2);
            a.z = __expf(a.z - mb2); a.w = __expf(a.w - mb2);
            sa[mt] += a.x + a.y; sb2[mt] += a.z + a.w;
            const int d0 = j0 - ia, d1 = d0 + 1, d2 = j0 - ib, d3 = d2 + 1;
            if (d0 <= -32) la[mt] += a.x; else if (d0 >= 32) ha[mt] += a.x;
            if (d1 <= -32) la[mt] += a.y; else if (d1 >= 32) ha[mt] += a.y;
            if (d2 <= -32) lb[mt] += a.z; else if (d2 >= 32) hb[mt] += a.z;
            if (d3 <= -32) lb[mt] += a.w; else if (d3 >= 32) hb[mt] += a.w;
        }
    }
    #pragma unroll
    for (int o = 1; o <= 2; o <<= 1) {
        #pragma unroll
        for (int mt = 0; mt < 2; mt++) {
            sa[mt] += __shfl_xor_sync(0xFFFFFFFFu, sa[mt], o);
            sb2[mt] += __shfl_xor_sync(0xFFFFFFFFu, sb2[mt], o);
            la[mt] += __shfl_xor_sync(0xFFFFFFFFu, la[mt], o);
            lb[mt] += __shfl_xor_sync(0xFFFFFFFFu, lb[mt], o);
            ha[mt] += __shfl_xor_sync(0xFFFFFFFFu, ha[mt], o);
            hb[mt] += __shfl_xor_sync(0xFFFFFFFFu, hb[mt], o);
        }
    }
    if (t == 0) {
        #pragma unroll
        for (int mt = 0; mt < 2; mt++) {
            const int ra = (mt * 16 + g) * 8 + wp, rb = (mt * 16 + g + 8) * 8 + wp;
            psum[ra] = sa[mt]; psum[rb] = sb2[mt];
            plow[ra] = la[mt]; plow[rb] = lb[mt];
            phi[ra]  = ha[mt]; phi[rb]  = hb[mt];
        }
    }
    __syncthreads();
    if (tid < 32) {
        float s = 0.f, l = 0.f, hh = 0.f;
        #pragma unroll
        for (int ww = 0; ww < 8; ww++) {
            s += psum[tid * 8 + ww]; l += plow[tid * 8 + ww]; hh += phi[tid * 8 + ww];
        }
        const float inv = 1.f / s;
        finv[tid] = inv;
        sW[tid * 96 + 0]  = l * inv;
        sW[tid * 96 + 64] = hh * inv;
    }
    __syncthreads();

    // ---- phase 4: normalize, store probs, band buckets ----
    #pragma unroll
    for (int mt = 0; mt < 2; mt++) {
        const int ra = mt * 16 + g, rb = ra + 8;
        const int ia = i0 + ra, ib = i0 + rb;
        const float inva = finv[ra], invb = finv[rb];
        __half* rowa = &g_attnh[((size_t)bh * Sq + ia) * Sq];
        __half* rowb2 = &g_attnh[((size_t)bh * Sq + ib) * Sq];
        #pragma unroll
        for (int nt = 0; nt < 16; nt++) {
            const int j0 = wp * 128 + nt * 8 + 2 * t;
            float4& a = acc[mt][nt];
            a.x *= inva; a.y *= inva; a.z *= invb; a.w *= invb;
            *(__half2*)&rowa[j0]  = __floats2half2_rn(a.x, a.y);
            *(__half2*)&rowb2[j0] = __floats2half2_rn(a.z, a.w);
            const int d0 = j0 - ia, d1 = d0 + 1, d2 = j0 - ib, d3 = d2 + 1;
            if (d0 > -32 && d0 < 32) sW[ra * 96 + d0 + 32] = a.x;
            if (d1 > -32 && d1 < 32) sW[ra * 96 + d1 + 32] = a.y;
            if (d2 > -32 && d2 < 32) sW[rb * 96 + d2 + 32] = a.z;
            if (d3 > -32 && d3 < 32) sW[rb * 96 + d3 + 32] = a.w;
        }
    }
    __syncthreads();

    // ---- phase 5: store W ----
    for (int idx = tid; idx < 32 * 96; idx += 256) {
        const int r = idx / 96, c = idx - r * 96;
        g_Wh[(size_t)(bh * Sq + i0 + r) * WPAD + c] = __float2half(sW[idx]);
    }
}

// =====================================================================
// mean over heads: out_attn[b,i,j] = (1/16) sum_h probs[bh,i,j]
// =====================================================================
__global__ __launch_bounds__(256) void meanh_kernel(float* __restrict__ out_attn)
{
    const size_t idx = (size_t)blockIdx.x * 256 + threadIdx.x;   // uint4 (8 halves) index
    const size_t per_b = (size_t)Sq * Sq / 8;
    const int b = (int)(idx / per_b);
    const size_t rem = idx % per_b;
    const uint4* base = (const uint4*)(g_attnh + (size_t)b * Hh * Sq * Sq) + rem;

    float s[8] = {0.f, 0.f, 0.f, 0.f, 0.f, 0.f, 0.f, 0.f};
    #pragma unroll
    for (int h2 = 0; h2 < Hh; h2++) {
        const uint4 u = base[(size_t)h2 * per_b];
        float2 f;
        f = __half22float2(*(const __half2*)&u.x); s[0] += f.x; s[1] += f.y;
        f = __half22float2(*(const __half2*)&u.y); s[2] += f.x; s[3] += f.y;
        f = __half22float2(*(const __half2*)&u.z); s[4] += f.x; s[5] += f.y;
        f = __half22float2(*(const __half2*)&u.w); s[6] += f.x; s[7] += f.y;
    }
    float* o = &out_attn[(size_t)b * Sq * Sq + rem * 8];
    const float c = 1.0f / Hh;
    *(float4*)&o[0] = make_float4(s[0] * c, s[1] * c, s[2] * c, s[3] * c);
    *(float4*)&o[4] = make_float4(s[4] * c, s[5] * c, s[6] * c, s[7] * c);
}

// =====================================================================
// ctx = attn @ V + W @ rel_v  (fp16 mma + ldmatrix/.trans; BM=128,BN=64)
// =====================================================================
struct CtxStage { __half As[128][40]; __half Bs[32][72]; };
#define CTX_STAGE_SZ ((int)sizeof(CtxStage))   // 14848
#define CTX_SMEM (3 * CTX_STAGE_SZ)

__global__ __launch_bounds__(256, 2) void ctxh_kernel()
{
    extern __shared__ CtxStage cstages[];

    const int bh = blockIdx.y;
    const int b = bh >> 4, h = bh & 15;
    const int i0 = blockIdx.x * 128;
    const int tid = threadIdx.x;
    const int lane = tid & 31, wid = tid >> 5;
    const int g = lane >> 2, t = lane & 3;
    const int wm = (wid >> 2) * 64;
    const int wn = (wid & 3) * 16;

    const uint32_t sb = (uint32_t)__cvta_generic_to_shared(cstages);
    const uint32_t laneA = (uint32_t)(((lane & 7) + ((lane >> 3) & 1) * 8) * 80 + (lane >> 4) * 16);
    const uint32_t laneBt = (uint32_t)(((lane & 7) + ((lane >> 3) & 1) * 8) * 144 + (lane >> 4) * 16);
    const uint32_t warpA  = (uint32_t)(wm * 80) + laneA;
    const uint32_t warpBt = (uint32_t)(10240 + wn * 2) + laneBt;

    auto issue = [&](int kt, int s) {
        CtxStage& st = cstages[s];
        if (kt < 32) {
            const int kb = kt * 32;
            #pragma unroll
            for (int it = 0; it < 2; it++) {
                const int id = it * 256 + tid;
                const int row = id >> 2, seg = id & 3;
                cp16(&st.As[row][seg * 8],
                     &g_attnh[((size_t)bh * Sq + i0 + row) * Sq + kb + seg * 8]);
            }
            const int vr = tid >> 3, vs = tid & 7;
            cp16(&st.Bs[vr][vs * 8],
                 &g_Vh[(size_t)(b * Sq + kb + vr) * Dm + h * DK + vs * 8]);
        } else {
            const int kk = (kt - 32) * 32;
            #pragma unroll
            for (int it = 0; it < 2; it++) {
                const int id = it * 256 + tid;
                const int row = id >> 2, seg = id & 3;
                cp16(&st.As[row][seg * 8],
                     &g_Wh[(size_t)(bh * Sq + i0 + row) * WPAD + kk + seg * 8]);
            }
            const int vr = tid >> 3, vs = tid & 7;
            cp16(&st.Bs[vr][vs * 8], &g_relvh[(kk + vr) * DK + vs * 8]);
        }
    };

    float4 acc[4][2];
    #pragma unroll
    for (int i = 0; i < 4; i++)
        #pragma unroll
        for (int j = 0; j < 2; j++) acc[i][j] = make_float4(0.f, 0.f, 0.f, 0.f);

    issue(0, 0); CP_COMMIT();
    issue(1, 1); CP_COMMIT();

    int scur = 0, snxt = 2;
    #pragma unroll 1
    for (int kt = 0; kt < 35; kt++) {
        CP_WAIT1();
        __syncthreads();
        if (kt + 2 < 35) issue(kt + 2, snxt);
        CP_COMMIT();

        const uint32_t stb = sb + scur * CTX_STAGE_SZ;
        #pragma unroll
        for (int ks = 0; ks < 2; ks++) {
            uint32_t af[4][4], bf[2][2];
            #pragma unroll
            for (int ma = 0; ma < 4; ma++)
                ldm_x4(af[ma], stb + warpA + ma * 1280 + ks * 32);
            {
                uint32_t bq[4];
                ldm_x4_t(bq, stb + warpBt + ks * 16 * 144);
                bf[0][0] = bq[0]; bf[0][1] = bq[1]; bf[1][0] = bq[2]; bf[1][1] = bq[3];
            }
            #pragma unroll
            for (int ma = 0; ma < 4; ma++)
                #pragma unroll
                for (int na = 0; na < 2; na++)
                    mma16(acc[ma][na], af[ma], bf[na]);
        }
        scur = (scur + 1 == 3) ? 0 : scur + 1;
        snxt = (snxt + 1 == 3) ? 0 : snxt + 1;
    }

    #pragma unroll
    for (int ma = 0; ma < 4; ma++) {
        const int r = i0 + wm + ma * 16 + g;
        #pragma unroll
        for (int na = 0; na < 2; na++) {
            const int c = wn + na * 8 + 2 * t;
            *(__half2*)&g_ctxh[(size_t)(b * Sq + r) * Dm + h * DK + c] =
                __floats2half2_rn(acc[ma][na].x, acc[ma][na].y);
            *(__half2*)&g_ctxh[(size_t)(b * Sq + r + 8) * Dm + h * DK + c] =
                __floats2half2_rn(acc[ma][na].z, acc[ma][na].w);
        }
    }
}

// ---------------- launch ----------------
extern "C" void kernel_launch(void* const* d_in, const int* in_sizes, int n_in,
                              void* d_out, int out_size)
{
    const float* query = (const float*)d_in[0];
    const float* key   = (const float*)d_in[1];
    const float* value = (const float*)d_in[2];
    const float* Wq    = (const float*)d_in[3];
    const float* Wk    = (const float*)d_in[4];
    const float* Wv    = (const float*)d_in[5];
    const float* Wo    = (const float*)d_in[6];
    const float* bo    = (const float*)d_in[7];
    const float* rel_k = (const float*)d_in[8];
    const float* rel_v = (const float*)d_in[9];

    float* out      = (float*)d_out;                 // [B,S,D]
    float* out_attn = out + (size_t)Bb * Sq * Dm;    // [B,S,S]

    static bool attr_set = false;
    if (!attr_set) {
        cudaFuncSetAttribute(proj3h_kernel,
                             cudaFuncAttributeMaxDynamicSharedMemorySize, PROJ_SMEM);
        cudaFuncSetAttribute(outprojh_kernel,
                             cudaFuncAttributeMaxDynamicSharedMemorySize, PROJ_SMEM);
        cudaFuncSetAttribute(ctxh_kernel,
                             cudaFuncAttributeMaxDynamicSharedMemorySize, CTX_SMEM);
        cudaFuncSetAttribute(scoresmax_kernel,
                             cudaFuncAttributeMaxDynamicSharedMemorySize, SMX_SMEM);
        attr_set = true;
    }

    // 0. prep: fp16 conversions
    cvt_inputs_kernel<<<dim3(Mrows * Dm / 4 / 256, 3), 256>>>(query, key, value);
    cvt_w_kernel<<<dim3(Dm / 32, Dm / 32, 4), 256>>>(Wq, Wk, Wv, Wo);
    cvt_relv_kernel<<<1, 256>>>(rel_v);

    // 1. projections (fp16 mma + ldmatrix, BK=64)
    proj3h_kernel<<<dim3(Dm / 128, Mrows / 128, 3), 256, PROJ_SMEM>>>();

    // 2. rel_k dot products
    relk_kernel<<<dim3(Sq / 128, BH), 128>>>(rel_k);

    // 3. fused scores + softmax -> fp16 probs + bucket W (no fp32 logit DRAM trip)
    scoresmax_kernel<<<dim3(Sq / 32, BH), 256, SMX_SMEM>>>();

    // 4. head mean from fp16 probs
    meanh_kernel<<<(unsigned)(((size_t)Bb * Sq * Sq / 8) / 256), 256>>>(out_attn);

    // 5. context = attn@V + W@rel_v (fp16 mma + ldmatrix)
    ctxh_kernel<<<dim3(Sq / 128, BH), 256, CTX_SMEM>>>();

    // 6. output projection + bias (fp16 mma + ldmatrix, BK=64)
    outprojh_kernel<<<dim3(Dm / 128, Mrows / 128), 256, PROJ_SMEM>>>(bo, out);
}

// round 12
// speedup vs baseline: 6.0238x; 1.0527x over previous
#include <cuda_runtime.h>
#include <cuda_fp16.h>
#include <cstdint>
#include <cstddef>

#define Sq 1024
#define Bb 4
#define Dm 1024
#define Hh 16
#define DK 64
#define NR 65
#define WPAD 128
#define BH (Bb*Hh)
#define Mrows (Bb*Sq)

// ---------------- scratch (device globals; no allocation) ----------------
__device__ __align__(128) __half g_attnh[(size_t)BH * Sq * Sq];   // fp16 probs, 128 MB
__device__ __align__(128) __half g_Qh[(size_t)Mrows * Dm];
__device__ __align__(128) __half g_Kh[(size_t)Mrows * Dm];
__device__ __align__(128) __half g_Vh[(size_t)Mrows * Dm];
__device__ __align__(128) __half g_ctxh[(size_t)Mrows * Dm];
__device__ __align__(128) __half g_Xh[(size_t)3 * Mrows * Dm];    // fp16 inputs q,k,v
__device__ __align__(128) __half g_Wth[(size_t)4 * Dm * Dm];      // W^T fp16: q,k,v,o
__device__ __align__(128) __half g_Wh[(size_t)BH * Sq * WPAD];    // bucket sums fp16 (128-wide, zero tail)
__device__ __align__(128) __half g_relvh[128 * DK];               // rel_v fp16, zero-padded to 128 rows
__device__ __align__(128) float  g_Rt[(size_t)BH * NR * Sq];      // rel_k bias, transposed

// ---------------- helpers ----------------
__device__ __forceinline__ void mma16(float4& d, const uint32_t* a, const uint32_t* b) {
    asm volatile("mma.sync.aligned.m16n8k16.row.col.f32.f16.f16.f32 "
                 "{%0,%1,%2,%3},{%4,%5,%6,%7},{%8,%9},{%0,%1,%2,%3};"
                 : "+f"(d.x), "+f"(d.y), "+f"(d.z), "+f"(d.w)
                 : "r"(a[0]), "r"(a[1]), "r"(a[2]), "r"(a[3]), "r"(b[0]), "r"(b[1]));
}
__device__ __forceinline__ void ldm_x4(uint32_t* r, uint32_t a) {
    asm volatile("ldmatrix.sync.aligned.m8n8.x4.shared.b16 {%0,%1,%2,%3}, [%4];"
                 : "=r"(r[0]), "=r"(r[1]), "=r"(r[2]), "=r"(r[3]) : "r"(a));
}
__device__ __forceinline__ void ldm_x4_t(uint32_t* r, uint32_t a) {
    asm volatile("ldmatrix.sync.aligned.m8n8.x4.trans.shared.b16 {%0,%1,%2,%3}, [%4];"
                 : "=r"(r[0]), "=r"(r[1]), "=r"(r[2]), "=r"(r[3]) : "r"(a));
}
__device__ __forceinline__ void cp16(void* dst, const void* src) {
    uint32_t d = (uint32_t)__cvta_generic_to_shared(dst);
    asm volatile("cp.async.cg.shared.global [%0], [%1], 16;" :: "r"(d), "l"(src) : "memory");
}
__device__ __forceinline__ void cp16s(uint32_t dst, const void* src) {
    asm volatile("cp.async.cg.shared.global [%0], [%1], 16;" :: "r"(dst), "l"(src) : "memory");
}
#define CP_COMMIT() asm volatile("cp.async.commit_group;" ::: "memory")
#define CP_WAIT1()  asm volatile("cp.async.wait_group 1;" ::: "memory")
#define CP_WAIT0()  asm volatile("cp.async.wait_group 0;" ::: "memory")

// ---------------- prep kernels ----------------
__global__ __launch_bounds__(256) void cvt_inputs_kernel(
    const float* __restrict__ q, const float* __restrict__ k, const float* __restrict__ v)
{
    const int z = blockIdx.y;
    const float4* s = (const float4*)(z == 0 ? q : z == 1 ? k : v);
    const int idx = blockIdx.x * 256 + threadIdx.x;
    float4 a = s[idx];
    __half2* d = (__half2*)(g_Xh + (size_t)z * Mrows * Dm);
    d[idx * 2]     = __floats2half2_rn(a.x, a.y);
    d[idx * 2 + 1] = __floats2half2_rn(a.z, a.w);
}

__global__ __launch_bounds__(256) void cvt_w_kernel(
    const float* __restrict__ Wq, const float* __restrict__ Wk,
    const float* __restrict__ Wv, const float* __restrict__ Wo)
{
    __shared__ float t[32][33];
    const int z = blockIdx.z;
    const float* W = (z == 0) ? Wq : (z == 1) ? Wk : (z == 2) ? Wv : Wo;
    __half* Wt = g_Wth + (size_t)z * Dm * Dm;
    const int x0 = blockIdx.x * 32, y0 = blockIdx.y * 32;
    const int tx = threadIdx.x & 31, ty = threadIdx.x >> 5;
    #pragma unroll
    for (int i = 0; i < 4; i++)
        t[ty + 8 * i][tx] = W[(size_t)(y0 + ty + 8 * i) * Dm + x0 + tx];
    __syncthreads();
    #pragma unroll
    for (int i = 0; i < 4; i++)
        Wt[(size_t)(x0 + ty + 8 * i) * Dm + y0 + tx] = __float2half(t[tx][ty + 8 * i]);
}

__global__ __launch_bounds__(256) void cvt_relv_kernel(const float* __restrict__ rel_v)
{
    for (int idx = threadIdx.x; idx < 128 * DK; idx += 256) {
        const int row = idx / DK, col = idx % DK;
        g_relvh[idx] = __float2half(row < NR ? rel_v[row * DK + col] : 0.f);
    }
}

// =====================================================================
// fp16 GEMM: C[4096,1024](tile 128x128) = A[m][k] @ Bt[n][k]^T (+bias)
// BM=128, BN=128, BK=64; 3-stage cp.async ring; 8 warps 2x4; warp 64x32
// =====================================================================
struct ProjStage { __half As[128][72]; __half Bs[128][72]; };
#define PROJ_STAGE_SZ ((int)sizeof(ProjStage))   // 36864
#define PROJ_SMEM (3 * PROJ_STAGE_SZ)            // 110592

template<bool HALF_OUT>
__device__ __forceinline__ void gemm_h_body(const __half* __restrict__ A,
                                            const __half* __restrict__ Bt,
                                            const float* __restrict__ bias,
                                            void* __restrict__ Cv)
{
    extern __shared__ ProjStage pstages[];
    const int tid = threadIdx.x, lane = tid & 31, wid = tid >> 5;
    const int g = lane >> 2, t = lane & 3;
    const int wm = (wid >> 2) * 64, wn = (wid & 3) * 32;
    const int row0 = blockIdx.y * 128, col0 = blockIdx.x * 128;

    const uint32_t sb = (uint32_t)__cvta_generic_to_shared(pstages);
    const uint32_t laneA = (uint32_t)(((lane & 7) + ((lane >> 3) & 1) * 8) * 144 + (lane >> 4) * 16);
    const uint32_t laneB = (uint32_t)((lane & 7) * 144 + ((lane >> 3) & 1) * 16 + (lane >> 4) * 1152);
    const uint32_t warpA = (uint32_t)(wm * 144) + laneA;
    const uint32_t warpB = (uint32_t)(18432 + wn * 144) + laneB;

    auto issue = [&](int kt, int s) {
        ProjStage& st = pstages[s];
        const int kb = kt * 64;
        #pragma unroll
        for (int it = 0; it < 4; it++) {
            const int id = it * 256 + tid;
            const int row = id >> 3, seg = id & 7;
            cp16(&st.As[row][seg * 8], &A[(size_t)(row0 + row) * 1024 + kb + seg * 8]);
            cp16(&st.Bs[row][seg * 8], &Bt[(size_t)(col0 + row) * 1024 + kb + seg * 8]);
        }
    };

    float4 acc[4][4];
    #pragma unroll
    for (int i = 0; i < 4; i++)
        #pragma unroll
        for (int j = 0; j < 4; j++) acc[i][j] = make_float4(0.f, 0.f, 0.f, 0.f);

    issue(0, 0); CP_COMMIT();
    issue(1, 1); CP_COMMIT();

    int scur = 0, snxt = 2;
    #pragma unroll 1
    for (int kt = 0; kt < 16; kt++) {
        CP_WAIT1();
        __syncthreads();
        if (kt + 2 < 16) issue(kt + 2, snxt);
        CP_COMMIT();

        const uint32_t stb = sb + scur * PROJ_STAGE_SZ;
        #pragma unroll
        for (int ks = 0; ks < 4; ks++) {
            const uint32_t k0b = ks * 32;
            uint32_t af[4][4], bf[4][2];
            #pragma unroll
            for (int ma = 0; ma < 4; ma++)
                ldm_x4(af[ma], stb + warpA + ma * 2304 + k0b);
            #pragma unroll
            for (int p = 0; p < 2; p++) {
                uint32_t bq[4];
                ldm_x4(bq, stb + warpB + p * 2304 + k0b);
                bf[2 * p][0] = bq[0]; bf[2 * p][1] = bq[1];
                bf[2 * p + 1][0] = bq[2]; bf[2 * p + 1][1] = bq[3];
            }
            #pragma unroll
            for (int ma = 0; ma < 4; ma++)
                #pragma unroll
                for (int na = 0; na < 4; na++)
                    mma16(acc[ma][na], af[ma], bf[na]);
        }
        scur = (scur + 1 == 3) ? 0 : scur + 1;
        snxt = (snxt + 1 == 3) ? 0 : snxt + 1;
    }

    #pragma unroll
    for (int ma = 0; ma < 4; ma++) {
        const int r = row0 + wm + ma * 16 + g;
        #pragma unroll
        for (int na = 0; na < 4; na++) {
            const int c = col0 + wn + na * 8 + 2 * t;
            if (HALF_OUT) {
                __half* Ch = (__half*)Cv;
                *(__half2*)&Ch[(size_t)r * 1024 + c]       = __floats2half2_rn(acc[ma][na].x, acc[ma][na].y);
                *(__half2*)&Ch[(size_t)(r + 8) * 1024 + c] = __floats2half2_rn(acc[ma][na].z, acc[ma][na].w);
            } else {
                float* Cf = (float*)Cv;
                const float bx = bias[c], by = bias[c + 1];
                *(float2*)&Cf[(size_t)r * 1024 + c]       = make_float2(acc[ma][na].x + bx, acc[ma][na].y + by);
                *(float2*)&Cf[(size_t)(r + 8) * 1024 + c] = make_float2(acc[ma][na].z + bx, acc[ma][na].w + by);
            }
        }
    }
}

__global__ __launch_bounds__(256, 2) void proj3h_kernel()
{
    const int z = blockIdx.z;
    const __half* A = g_Xh + (size_t)z * Mrows * Dm;
    const __half* Bt = g_Wth + (size_t)z * Dm * Dm;
    __half* C = (z == 0) ? g_Qh : (z == 1) ? g_Kh : g_Vh;
    gemm_h_body<true>(A, Bt, nullptr, C);
}

__global__ __launch_bounds__(256, 2) void outprojh_kernel(
    const float* __restrict__ bo, float* __restrict__ out)
{
    gemm_h_body<false>(g_ctxh, g_Wth + (size_t)3 * Dm * Dm, bo, out);
}

// =====================================================================
// relk: Rt[bh][r][i] = dot(Q[b,i,h*64:], rel_k[r,:])
// =====================================================================
__global__ __launch_bounds__(128) void relk_kernel(const float* __restrict__ rel_k)
{
    __shared__ float4 RK[NR][16];
    const int bh = blockIdx.y;
    const int b = bh >> 4, h = bh & 15;
    const int i0 = blockIdx.x * 128;
    const int tid = threadIdx.x;

    for (int idx = tid; idx < NR * 16; idx += 128)
        RK[idx / 16][idx % 16] = ((const float4*)rel_k)[idx];
    __syncthreads();

    float2 q[32];
    const __half2* qrow = (const __half2*)&g_Qh[(size_t)(b * Sq + i0 + tid) * Dm + h * DK];
    #pragma unroll
    for (int d = 0; d < 32; d++) q[d] = __half22float2(qrow[d]);

    float* outp = &g_Rt[(size_t)bh * NR * Sq + i0 + tid];
    #pragma unroll 1
    for (int r = 0; r < NR; r++) {
        float s = 0.f;
        #pragma unroll
        for (int d = 0; d < 16; d++) {
            float4 rk = RK[r][d];
            s += q[2 * d].x * rk.x + q[2 * d].y * rk.y + q[2 * d + 1].x * rk.z + q[2 * d + 1].y * rk.w;
        }
        outp[(size_t)r * Sq] = s;
    }
}

// =====================================================================
// FUSED scores+softmax: logits live in registers only.
// Block = 32 query rows x 1 head x all 1024 keys. 512 threads (16 warps).
// Warp wp owns key cols [wp*64, wp*64+64); acc = 32x64 fp32 per warp.
// =====================================================================
#define SMX_K    0          // 1024 x 128B = 131072
#define SMX_Q    131072     // 32 x 128B = 4096
#define SMX_PMAX 135168     // [32][16] = 2048
#define SMX_PSUM 137216
#define SMX_PLOW 139264
#define SMX_PHI  141312
#define SMX_FMAX 143360     // [32]
#define SMX_FINV 143488     // [32]
#define SMX_SW   143616     // [32][128] = 16384
#define SMX_SMEM 160000

__global__ __launch_bounds__(512, 1) void scoresmax_kernel()
{
    extern __shared__ char smx[];
    float* pmax = (float*)(smx + SMX_PMAX);   // [32][16]
    float* psum = (float*)(smx + SMX_PSUM);
    float* plow = (float*)(smx + SMX_PLOW);
    float* phi  = (float*)(smx + SMX_PHI);
    float* fmax = (float*)(smx + SMX_FMAX);   // [32]
    float* finv = (float*)(smx + SMX_FINV);   // [32]
    float* sW   = (float*)(smx + SMX_SW);     // [32][128]

    const int bh = blockIdx.y;
    const int b = bh >> 4, h = bh & 15;
    const int i0 = blockIdx.x * 32;
    const int tid = threadIdx.x;
    const int lane = tid & 31, wp = tid >> 5;   // 16 warps
    const int g = lane >> 2, t = lane & 3;

    const uint32_t sbK = (uint32_t)__cvta_generic_to_shared(smx + SMX_K);
    const uint32_t sbQ = (uint32_t)__cvta_generic_to_shared(smx + SMX_Q);

    for (int idx = tid; idx < 32 * 128; idx += 512) sW[idx] = 0.f;

    // stage K: 1024 rows x 128B, swizzled
    for (int id = tid; id < 8192; id += 512) {
        const int row = id >> 3, seg = id & 7;
        const uint32_t dst = sbK + row * 128 + ((seg * 16) ^ ((row & 7) << 4));
        cp16s(dst, &g_Kh[(size_t)(b * Sq + row) * Dm + h * DK + seg * 8]);
    }
    if (tid < 256) {
        const int row = tid >> 3, seg = tid & 7;
        const uint32_t dst = sbQ + row * 128 + ((seg * 16) ^ ((row & 7) << 4));
        cp16s(dst, &g_Qh[(size_t)(b * Sq + i0 + row) * Dm + h * DK + seg * 8]);
    }
    CP_COMMIT(); CP_WAIT0();
    __syncthreads();

    // ---- phase 1: QK^T (dk=64, 4 k-steps) ----
    float4 acc[2][8];
    #pragma unroll
    for (int mt = 0; mt < 2; mt++)
        #pragma unroll
        for (int nt = 0; nt < 8; nt++) acc[mt][nt] = make_float4(0.f, 0.f, 0.f, 0.f);

    const int arow = (lane & 7) + ((lane >> 3) & 1) * 8;
    const int acolsel = (lane >> 4) * 16;
    const int brow7 = lane & 7;
    const int brow = (lane & 7) + ((lane >> 4) << 3);
    const int bcolsel = ((lane >> 3) & 1) * 16;

    #pragma unroll
    for (int ks = 0; ks < 4; ks++) {
        const int kb2 = ks * 32;
        uint32_t af[2][4];
        #pragma unroll
        for (int mt = 0; mt < 2; mt++) {
            const int row = mt * 16 + arow;
            const uint32_t col = (uint32_t)((kb2 + acolsel) ^ ((arow & 7) << 4));
            ldm_x4(af[mt], sbQ + row * 128 + col);
        }
        #pragma unroll
        for (int nt2 = 0; nt2 < 4; nt2++) {
            const int n0 = wp * 64 + nt2 * 16;
            const uint32_t colb = (uint32_t)((kb2 + bcolsel) ^ (brow7 << 4));
            uint32_t bq[4];
            ldm_x4(bq, sbK + (n0 + brow) * 128 + colb);
            uint32_t bf0[2] = { bq[0], bq[1] }, bf1[2] = { bq[2], bq[3] };
            #pragma unroll
            for (int mt = 0; mt < 2; mt++) {
                mma16(acc[mt][2 * nt2],     af[mt], bf0);
                mma16(acc[mt][2 * nt2 + 1], af[mt], bf1);
            }
        }
    }

    // ---- phase 2: bias + scale + row max ----
    const float* RtB = &g_Rt[(size_t)bh * NR * Sq];
    float mxa[2] = { -1e30f, -1e30f }, mxb[2] = { -1e30f, -1e30f };
    #pragma unroll
    for (int mt = 0; mt < 2; mt++) {
        const int ia = i0 + mt * 16 + g, ib = ia + 8;
        #pragma unroll
        for (int nt = 0; nt < 8; nt++) {
            const int j0 = wp * 64 + nt * 8 + 2 * t;
            float4& a = acc[mt][nt];
            int r0 = j0 - ia;     r0 = (r0 < -32 ? -32 : (r0 > 32 ? 32 : r0)) + 32;
            int r1 = j0 + 1 - ia; r1 = (r1 < -32 ? -32 : (r1 > 32 ? 32 : r1)) + 32;
            int r2 = j0 - ib;     r2 = (r2 < -32 ? -32 : (r2 > 32 ? 32 : r2)) + 32;
            int r3 = j0 + 1 - ib; r3 = (r3 < -32 ? -32 : (r3 > 32 ? 32 : r3)) + 32;
            a.x = a.x * 0.125f + RtB[(size_t)r0 * Sq + ia];
            a.y = a.y * 0.125f + RtB[(size_t)r1 * Sq + ia];
            a.z = a.z * 0.125f + RtB[(size_t)r2 * Sq + ib];
            a.w = a.w * 0.125f + RtB[(size_t)r3 * Sq + ib];
            mxa[mt] = fmaxf(mxa[mt], fmaxf(a.x, a.y));
            mxb[mt] = fmaxf(mxb[mt], fmaxf(a.z, a.w));
        }
    }
    #pragma unroll
    for (int o = 1; o <= 2; o <<= 1) {
        #pragma unroll
        for (int mt = 0; mt < 2; mt++) {
            mxa[mt] = fmaxf(mxa[mt], __shfl_xor_sync(0xFFFFFFFFu, mxa[mt], o));
            mxb[mt] = fmaxf(mxb[mt], __shfl_xor_sync(0xFFFFFFFFu, mxb[mt], o));
        }
    }
    if (t == 0) {
        #pragma unroll
        for (int mt = 0; mt < 2; mt++) {
            pmax[(mt * 16 + g) * 16 + wp]     = mxa[mt];
            pmax[(mt * 16 + g + 8) * 16 + wp] = mxb[mt];
        }
    }
    __syncthreads();
    if (tid < 32) {
        float m = -1e30f;
        #pragma unroll
        for (int ww = 0; ww < 16; ww++) m = fmaxf(m, pmax[tid * 16 + ww]);
        fmax[tid] = m;
    }
    __syncthreads();

    // ---- phase 3: exp + partial sums / low / high ----
    float sa[2] = {0.f, 0.f}, sb2[2] = {0.f, 0.f};
    float la[2] = {0.f, 0.f}, lb[2] = {0.f, 0.f};
    float ha[2] = {0.f, 0.f}, hb[2] = {0.f, 0.f};
    #pragma unroll
    for (int mt = 0; mt < 2; mt++) {
        const float ma2 = fmax[mt * 16 + g], mb2 = fmax[mt * 16 + g + 8];
        const int ia = i0 + mt * 16 + g, ib = ia + 8;
        #pragma unroll
        for (int nt = 0; nt < 8; nt++) {
            const int j0 = wp * 64 + nt * 8 + 2 * t;
            float4& a = acc[mt][nt];
            a.x = __expf(a.x - ma2); a.y = __expf(a.y - ma2);
            a.z = __expf(a.z - mb2); a.w = __expf(a.w - mb2);
            sa[mt] += a.x + a.y; sb2[mt] += a.z + a.w;
            const int d0 = j0 - ia, d1 = d0 + 1, d2 = j0 - ib, d3 = d2 + 1;
            if (d0 <= -32) la[mt] += a.x; else if (d0 >= 32) ha[mt] += a.x;
            if (d1 <= -32) la[mt] += a.y; else if (d1 >= 32) ha[mt] += a.y;
            if (d2 <= -32) lb[mt] += a.z; else if (d2 >= 32) hb[mt] += a.z;
            if (d3 <= -32) lb[mt] += a.w; else if (d3 >= 32) hb[mt] += a.w;
        }
    }
    #pragma unroll
    for (int o = 1; o <= 2; o <<= 1) {
        #pragma unroll
        for (int mt = 0; mt < 2; mt++) {
            sa[mt] += __shfl_xor_sync(0xFFFFFFFFu, sa[mt], o);
            sb2[mt] += __shfl_xor_sync(0xFFFFFFFFu, sb2[mt], o);
            la[mt] += __shfl_xor_sync(0xFFFFFFFFu, la[mt], o);
            lb[mt] += __shfl_xor_sync(0xFFFFFFFFu, lb[mt], o);
            ha[mt] += __shfl_xor_sync(0xFFFFFFFFu, ha[mt], o);
            hb[mt] += __shfl_xor_sync(0xFFFFFFFFu, hb[mt], o);
        }
    }
    if (t == 0) {
        #pragma unroll
        for (int mt = 0; mt < 2; mt++) {
            const int ra = (mt * 16 + g) * 16 + wp, rb = (mt * 16 + g + 8) * 16 + wp;
            psum[ra] = sa[mt]; psum[rb] = sb2[mt];
            plow[ra] = la[mt]; plow[rb] = lb[mt];
            phi[ra]  = ha[mt]; phi[rb]  = hb[mt];
        }
    }
    __syncthreads();
    if (tid < 32) {
        float s = 0.f, l = 0.f, hh = 0.f;
        #pragma unroll
        for (int ww = 0; ww < 16; ww++) {
            s += psum[tid * 16 + ww]; l += plow[tid * 16 + ww]; hh += phi[tid * 16 + ww];
        }
        const float inv = 1.f / s;
        finv[tid] = inv;
        sW[tid * 128 + 0]  = l * inv;
        sW[tid * 128 + 64] = hh * inv;
    }
    __syncthreads();

    // ---- phase 4: normalize, store probs, band buckets ----
    #pragma unroll
    for (int mt = 0; mt < 2; mt++) {
        const int ra = mt * 16 + g, rb = ra + 8;
        const int ia = i0 + ra, ib = i0 + rb;
        const float inva = finv[ra], invb = finv[rb];
        __half* rowa = &g_attnh[((size_t)bh * Sq + ia) * Sq];
        __half* rowb2 = &g_attnh[((size_t)bh * Sq + ib) * Sq];
        #pragma unroll
        for (int nt = 0; nt < 8; nt++) {
            const int j0 = wp * 64 + nt * 8 + 2 * t;
            float4& a = acc[mt][nt];
            a.x *= inva; a.y *= inva; a.z *= invb; a.w *= invb;
            *(__half2*)&rowa[j0]  = __floats2half2_rn(a.x, a.y);
            *(__half2*)&rowb2[j0] = __floats2half2_rn(a.z, a.w);
            const int d0 = j0 - ia, d1 = d0 + 1, d2 = j0 - ib, d3 = d2 + 1;
            if (d0 > -32 && d0 < 32) sW[ra * 128 + d0 + 32] = a.x;
            if (d1 > -32 && d1 < 32) sW[ra * 128 + d1 + 32] = a.y;
            if (d2 > -32 && d2 < 32) sW[rb * 128 + d2 + 32] = a.z;
            if (d3 > -32 && d3 < 32) sW[rb * 128 + d3 + 32] = a.w;
        }
    }
    __syncthreads();

    // ---- phase 5: store W (128-wide, zero tail beyond 96 kept zero) ----
    for (int idx = tid; idx < 32 * 128; idx += 512) {
        const int r = idx >> 7, c = idx & 127;
        g_Wh[(size_t)(bh * Sq + i0 + r) * WPAD + c] = __float2half(sW[idx]);
    }
}

// =====================================================================
// mean over heads
// =====================================================================
__global__ __launch_bounds__(256) void meanh_kernel(float* __restrict__ out_attn)
{
    const size_t idx = (size_t)blockIdx.x * 256 + threadIdx.x;
    const size_t per_b = (size_t)Sq * Sq / 8;
    const int b = (int)(idx / per_b);
    const size_t rem = idx % per_b;
    const uint4* base = (const uint4*)(g_attnh + (size_t)b * Hh * Sq * Sq) + rem;

    float s[8] = {0.f, 0.f, 0.f, 0.f, 0.f, 0.f, 0.f, 0.f};
    #pragma unroll
    for (int h2 = 0; h2 < Hh; h2++) {
        const uint4 u = base[(size_t)h2 * per_b];
        float2 f;
        f = __half22float2(*(const __half2*)&u.x); s[0] += f.x; s[1] += f.y;
        f = __half22float2(*(const __half2*)&u.y); s[2] += f.x; s[3] += f.y;
        f = __half22float2(*(const __half2*)&u.z); s[4] += f.x; s[5] += f.y;
        f = __half22float2(*(const __half2*)&u.w); s[6] += f.x; s[7] += f.y;
    }
    float* o = &out_attn[(size_t)b * Sq * Sq + rem * 8];
    const float c = 1.0f / Hh;
    *(float4*)&o[0] = make_float4(s[0] * c, s[1] * c, s[2] * c, s[3] * c);
    *(float4*)&o[4] = make_float4(s[4] * c, s[5] * c, s[6] * c, s[7] * c);
}

// =====================================================================
// ctx = attn @ V + W @ rel_v  (fp16 mma + ldmatrix/.trans; BM=128,BN=64,BK=64)
// 18 k-iterations (16 attn + 2 rel, zero-extended)
// =====================================================================
struct CtxStage { __half As[128][72]; __half Bs[64][72]; };
#define CTX_STAGE_SZ ((int)sizeof(CtxStage))   // 27648
#define CTX_SMEM (3 * CTX_STAGE_SZ)            // 82944

__global__ __launch_bounds__(256, 2) void ctxh_kernel()
{
    extern __shared__ CtxStage cstages[];

    const int bh = blockIdx.y;
    const int b = bh >> 4, h = bh & 15;
    const int i0 = blockIdx.x * 128;
    const int tid = threadIdx.x;
    const int lane = tid & 31, wid = tid >> 5;
    const int g = lane >> 2, t = lane & 3;
    const int wm = (wid >> 2) * 64;
    const int wn = (wid & 3) * 16;

    const uint32_t sb = (uint32_t)__cvta_generic_to_shared(cstages);
    const uint32_t laneA = (uint32_t)(((lane & 7) + ((lane >> 3) & 1) * 8) * 144 + (lane >> 4) * 16);
    const uint32_t laneBt = (uint32_t)(((lane & 7) + ((lane >> 3) & 1) * 8) * 144 + (lane >> 4) * 16);
    const uint32_t warpA  = (uint32_t)(wm * 144) + laneA;
    const uint32_t warpBt = (uint32_t)(18432 + wn * 2) + laneBt;

    auto issue = [&](int kt, int s) {
        CtxStage& st = cstages[s];
        if (kt < 16) {
            const int kb = kt * 64;
            #pragma unroll
            for (int it = 0; it < 4; it++) {
                const int id = it * 256 + tid;
                const int row = id >> 3, seg = id & 7;
                cp16(&st.As[row][seg * 8],
                     &g_attnh[((size_t)bh * Sq + i0 + row) * Sq + kb + seg * 8]);
            }
            #pragma unroll
            for (int it = 0; it < 2; it++) {
                const int id = it * 256 + tid;
                const int vr = id >> 3, vs = id & 7;
                cp16(&st.Bs[vr][vs * 8],
                     &g_Vh[(size_t)(b * Sq + kb + vr) * Dm + h * DK + vs * 8]);
            }
        } else {
            const int kk = (kt - 16) * 64;
            #pragma unroll
            for (int it = 0; it < 4; it++) {
                const int id = it * 256 + tid;
                const int row = id >> 3, seg = id & 7;
                cp16(&st.As[row][seg * 8],
                     &g_Wh[(size_t)(bh * Sq + i0 + row) * WPAD + kk + seg * 8]);
            }
            #pragma unroll
            for (int it = 0; it < 2; it++) {
                const int id = it * 256 + tid;
                const int vr = id >> 3, vs = id & 7;
                cp16(&st.Bs[vr][vs * 8], &g_relvh[(kk + vr) * DK + vs * 8]);
            }
        }
    };

    float4 acc[4][2];
    #pragma unroll
    for (int i = 0; i < 4; i++)
        #pragma unroll
        for (int j = 0; j < 2; j++) acc[i][j] = make_float4(0.f, 0.f, 0.f, 0.f);

    issue(0, 0); CP_COMMIT();
    issue(1, 1); CP_COMMIT();

    int scur = 0, snxt = 2;
    #pragma unroll 1
    for (int kt = 0; kt < 18; kt++) {
        CP_WAIT1();
        __syncthreads();
        if (kt + 2 < 18) issue(kt + 2, snxt);
        CP_COMMIT();

        const uint32_t stb = sb + scur * CTX_STAGE_SZ;
        #pragma unroll
        for (int ks = 0; ks < 4; ks++) {
            uint32_t af[4][4], bf[2][2];
            #pragma unroll
            for (int ma = 0; ma < 4; ma++)
                ldm_x4(af[ma], stb + warpA + ma * 2304 + ks * 32);
            {
                uint32_t bq[4];
                ldm_x4_t(bq, stb + warpBt + ks * 16 * 144);
                bf[0][0] = bq[0]; bf[0][1] = bq[1]; bf[1][0] = bq[2]; bf[1][1] = bq[3];
            }
            #pragma unroll
            for (int ma = 0; ma < 4; ma++)
                #pragma unroll
                for (int na = 0; na < 2; na++)
                    mma16(acc[ma][na], af[ma], bf[na]);
        }
        scur = (scur + 1 == 3) ? 0 : scur + 1;
        snxt = (snxt + 1 == 3) ? 0 : snxt + 1;
    }

    #pragma unroll
    for (int ma = 0; ma < 4; ma++) {
        const int r = i0 + wm + ma * 16 + g;
        #pragma unroll
        for (int na = 0; na < 2; na++) {
            const int c = wn + na * 8 + 2 * t;
            *(__half2*)&g_ctxh[(size_t)(b * Sq + r) * Dm + h * DK + c] =
                __floats2half2_rn(acc[ma][na].x, acc[ma][na].y);
            *(__half2*)&g_ctxh[(size_t)(b * Sq + r + 8) * Dm + h * DK + c] =
                __floats2half2_rn(acc[ma][na].z, acc[ma][na].w);
        }
    }
}

// ---------------- launch ----------------
extern "C" void kernel_launch(void* const* d_in, const int* in_sizes, int n_in,
                              void* d_out, int out_size)
{
    const float* query = (const float*)d_in[0];
    const float* key   = (const float*)d_in[1];
    const float* value = (const float*)d_in[2];
    const float* Wq    = (const float*)d_in[3];
    const float* Wk    = (const float*)d_in[4];
    const float* Wv    = (const float*)d_in[5];
    const float* Wo    = (const float*)d_in[6];
    const float* bo    = (const float*)d_in[7];
    const float* rel_k = (const float*)d_in[8];
    const float* rel_v = (const float*)d_in[9];

    float* out      = (float*)d_out;                 // [B,S,D]
    float* out_attn = out + (size_t)Bb * Sq * Dm;    // [B,S,S]

    static bool attr_set = false;
    if (!attr_set) {
        cudaFuncSetAttribute(proj3h_kernel,
                             cudaFuncAttributeMaxDynamicSharedMemorySize, PROJ_SMEM);
        cudaFuncSetAttribute(outprojh_kernel,
                             cudaFuncAttributeMaxDynamicSharedMemorySize, PROJ_SMEM);
        cudaFuncSetAttribute(ctxh_kernel,
                             cudaFuncAttributeMaxDynamicSharedMemorySize, CTX_SMEM);
        cudaFuncSetAttribute(scoresmax_kernel,
                             cudaFuncAttributeMaxDynamicSharedMemorySize, SMX_SMEM);
        attr_set = true;
    }

    // 0. prep: fp16 conversions
    cvt_inputs_kernel<<<dim3(Mrows * Dm / 4 / 256, 3), 256>>>(query, key, value);
    cvt_w_kernel<<<dim3(Dm / 32, Dm / 32, 4), 256>>>(Wq, Wk, Wv, Wo);
    cvt_relv_kernel<<<1, 256>>>(rel_v);

    // 1. projections (fp16 mma + ldmatrix, BK=64)
    proj3h_kernel<<<dim3(Dm / 128, Mrows / 128, 3), 256, PROJ_SMEM>>>();

    // 2. rel_k dot products
    relk_kernel<<<dim3(Sq / 128, BH), 128>>>(rel_k);

    // 3. fused scores + softmax (512 thr, 16 warps)
    scoresmax_kernel<<<dim3(Sq / 32, BH), 512, SMX_SMEM>>>();

    // 4. head mean from fp16 probs
    meanh_kernel<<<(unsigned)(((size_t)Bb * Sq * Sq / 8) / 256), 256>>>(out_attn);

    // 5. context = attn@V + W@rel_v (BK=64, 18 kt)
    ctxh_kernel<<<dim3(Sq / 128, BH), 256, CTX_SMEM>>>();

    // 6. output projection + bias (fp16 mma + ldmatrix, BK=64)
    outprojh_kernel<<<dim3(Dm / 128, Mrows / 128), 256, PROJ_SMEM>>>(bo, out);
}

// round 13
// speedup vs baseline: 6.2115x; 1.0312x over previous
#include <cuda_runtime.h>
#include <cuda_fp16.h>
#include <cstdint>
#include <cstddef>

#define Sq 1024
#define Bb 4
#define Dm 1024
#define Hh 16
#define DK 64
#define NR 65
#define WPAD 128
#define BH (Bb*Hh)
#define Mrows (Bb*Sq)

// ---------------- scratch (device globals; no allocation) ----------------
__device__ __align__(128) __half g_attnh[(size_t)BH * Sq * Sq];   // fp16 probs, 128 MB
__device__ __align__(128) __half g_Qh[(size_t)Mrows * Dm];
__device__ __align__(128) __half g_Kh[(size_t)Mrows * Dm];
__device__ __align__(128) __half g_Vh[(size_t)Mrows * Dm];
__device__ __align__(128) __half g_ctxh[(size_t)Mrows * Dm];
__device__ __align__(128) __half g_Xh[(size_t)3 * Mrows * Dm];    // fp16 inputs q,k,v
__device__ __align__(128) __half g_Wth[(size_t)4 * Dm * Dm];      // W^T fp16: q,k,v,o
__device__ __align__(128) __half g_Wh[(size_t)BH * Sq * WPAD];    // bucket sums fp16 (128-wide, zero tail)
__device__ __align__(128) __half g_relvh[128 * DK];               // rel_v fp16, zero-padded to 128 rows
__device__ __align__(128) float  g_Rt[(size_t)BH * NR * Sq];      // rel_k bias, transposed

// ---------------- helpers ----------------
__device__ __forceinline__ void mma16(float4& d, const uint32_t* a, const uint32_t* b) {
    asm volatile("mma.sync.aligned.m16n8k16.row.col.f32.f16.f16.f32 "
                 "{%0,%1,%2,%3},{%4,%5,%6,%7},{%8,%9},{%0,%1,%2,%3};"
                 : "+f"(d.x), "+f"(d.y), "+f"(d.z), "+f"(d.w)
                 : "r"(a[0]), "r"(a[1]), "r"(a[2]), "r"(a[3]), "r"(b[0]), "r"(b[1]));
}
__device__ __forceinline__ void ldm_x4(uint32_t* r, uint32_t a) {
    asm volatile("ldmatrix.sync.aligned.m8n8.x4.shared.b16 {%0,%1,%2,%3}, [%4];"
                 : "=r"(r[0]), "=r"(r[1]), "=r"(r[2]), "=r"(r[3]) : "r"(a));
}
__device__ __forceinline__ void ldm_x4_t(uint32_t* r, uint32_t a) {
    asm volatile("ldmatrix.sync.aligned.m8n8.x4.trans.shared.b16 {%0,%1,%2,%3}, [%4];"
                 : "=r"(r[0]), "=r"(r[1]), "=r"(r[2]), "=r"(r[3]) : "r"(a));
}
__device__ __forceinline__ void cp16(void* dst, const void* src) {
    uint32_t d = (uint32_t)__cvta_generic_to_shared(dst);
    asm volatile("cp.async.cg.shared.global [%0], [%1], 16;" :: "r"(d), "l"(src) : "memory");
}
__device__ __forceinline__ void cp16s(uint32_t dst, const void* src) {
    asm volatile("cp.async.cg.shared.global [%0], [%1], 16;" :: "r"(dst), "l"(src) : "memory");
}
#define CP_COMMIT() asm volatile("cp.async.commit_group;" ::: "memory")
#define CP_WAIT1()  asm volatile("cp.async.wait_group 1;" ::: "memory")
#define CP_WAIT0()  asm volatile("cp.async.wait_group 0;" ::: "memory")

// ---------------- prep kernels ----------------
__global__ __launch_bounds__(256) void cvt_inputs_kernel(
    const float* __restrict__ q, const float* __restrict__ k, const float* __restrict__ v)
{
    const int z = blockIdx.y;
    const float4* s = (const float4*)(z == 0 ? q : z == 1 ? k : v);
    const int idx = blockIdx.x * 256 + threadIdx.x;
    float4 a = s[idx];
    __half2* d = (__half2*)(g_Xh + (size_t)z * Mrows * Dm);
    d[idx * 2]     = __floats2half2_rn(a.x, a.y);
    d[idx * 2 + 1] = __floats2half2_rn(a.z, a.w);
}

__global__ __launch_bounds__(256) void cvt_w_kernel(
    const float* __restrict__ Wq, const float* __restrict__ Wk,
    const float* __restrict__ Wv, const float* __restrict__ Wo)
{
    __shared__ float t[32][33];
    const int z = blockIdx.z;
    const float* W = (z == 0) ? Wq : (z == 1) ? Wk : (z == 2) ? Wv : Wo;
    __half* Wt = g_Wth + (size_t)z * Dm * Dm;
    const int x0 = blockIdx.x * 32, y0 = blockIdx.y * 32;
    const int tx = threadIdx.x & 31, ty = threadIdx.x >> 5;
    #pragma unroll
    for (int i = 0; i < 4; i++)
        t[ty + 8 * i][tx] = W[(size_t)(y0 + ty + 8 * i) * Dm + x0 + tx];
    __syncthreads();
    #pragma unroll
    for (int i = 0; i < 4; i++)
        Wt[(size_t)(x0 + ty + 8 * i) * Dm + y0 + tx] = __float2half(t[tx][ty + 8 * i]);
}

__global__ __launch_bounds__(256) void cvt_relv_kernel(const float* __restrict__ rel_v)
{
    for (int idx = threadIdx.x; idx < 128 * DK; idx += 256) {
        const int row = idx / DK, col = idx % DK;
        g_relvh[idx] = __float2half(row < NR ? rel_v[row * DK + col] : 0.f);
    }
}

// =====================================================================
// fp16 GEMM: C[4096,1024](tile 128x128) = A[m][k] @ Bt[n][k]^T (+bias)
// BM=128, BN=128, BK=64; 3-stage cp.async ring; 8 warps 2x4; warp 64x32
// =====================================================================
struct ProjStage { __half As[128][72]; __half Bs[128][72]; };
#define PROJ_STAGE_SZ ((int)sizeof(ProjStage))   // 36864
#define PROJ_SMEM (3 * PROJ_STAGE_SZ)            // 110592

template<bool HALF_OUT>
__device__ __forceinline__ void gemm_h_body(const __half* __restrict__ A,
                                            const __half* __restrict__ Bt,
                                            const float* __restrict__ bias,
                                            void* __restrict__ Cv)
{
    extern __shared__ ProjStage pstages[];
    const int tid = threadIdx.x, lane = tid & 31, wid = tid >> 5;
    const int g = lane >> 2, t = lane & 3;
    const int wm = (wid >> 2) * 64, wn = (wid & 3) * 32;
    const int row0 = blockIdx.y * 128, col0 = blockIdx.x * 128;

    const uint32_t sb = (uint32_t)__cvta_generic_to_shared(pstages);
    const uint32_t laneA = (uint32_t)(((lane & 7) + ((lane >> 3) & 1) * 8) * 144 + (lane >> 4) * 16);
    const uint32_t laneB = (uint32_t)((lane & 7) * 144 + ((lane >> 3) & 1) * 16 + (lane >> 4) * 1152);
    const uint32_t warpA = (uint32_t)(wm * 144) + laneA;
    const uint32_t warpB = (uint32_t)(18432 + wn * 144) + laneB;

    auto issue = [&](int kt, int s) {
        ProjStage& st = pstages[s];
        const int kb = kt * 64;
        #pragma unroll
        for (int it = 0; it < 4; it++) {
            const int id = it * 256 + tid;
            const int row = id >> 3, seg = id & 7;
            cp16(&st.As[row][seg * 8], &A[(size_t)(row0 + row) * 1024 + kb + seg * 8]);
            cp16(&st.Bs[row][seg * 8], &Bt[(size_t)(col0 + row) * 1024 + kb + seg * 8]);
        }
    };

    float4 acc[4][4];
    #pragma unroll
    for (int i = 0; i < 4; i++)
        #pragma unroll
        for (int j = 0; j < 4; j++) acc[i][j] = make_float4(0.f, 0.f, 0.f, 0.f);

    issue(0, 0); CP_COMMIT();
    issue(1, 1); CP_COMMIT();

    int scur = 0, snxt = 2;
    #pragma unroll 1
    for (int kt = 0; kt < 16; kt++) {
        CP_WAIT1();
        __syncthreads();
        if (kt + 2 < 16) issue(kt + 2, snxt);
        CP_COMMIT();

        const uint32_t stb = sb + scur * PROJ_STAGE_SZ;
        #pragma unroll
        for (int ks = 0; ks < 4; ks++) {
            const uint32_t k0b = ks * 32;
            uint32_t af[4][4], bf[4][2];
            #pragma unroll
            for (int ma = 0; ma < 4; ma++)
                ldm_x4(af[ma], stb + warpA + ma * 2304 + k0b);
            #pragma unroll
            for (int p = 0; p < 2; p++) {
                uint32_t bq[4];
                ldm_x4(bq, stb + warpB + p * 2304 + k0b);
                bf[2 * p][0] = bq[0]; bf[2 * p][1] = bq[1];
                bf[2 * p + 1][0] = bq[2]; bf[2 * p + 1][1] = bq[3];
            }
            #pragma unroll
            for (int ma = 0; ma < 4; ma++)
                #pragma unroll
                for (int na = 0; na < 4; na++)
                    mma16(acc[ma][na], af[ma], bf[na]);
        }
        scur = (scur + 1 == 3) ? 0 : scur + 1;
        snxt = (snxt + 1 == 3) ? 0 : snxt + 1;
    }

    #pragma unroll
    for (int ma = 0; ma < 4; ma++) {
        const int r = row0 + wm + ma * 16 + g;
        #pragma unroll
        for (int na = 0; na < 4; na++) {
            const int c = col0 + wn + na * 8 + 2 * t;
            if (HALF_OUT) {
                __half* Ch = (__half*)Cv;
                *(__half2*)&Ch[(size_t)r * 1024 + c]       = __floats2half2_rn(acc[ma][na].x, acc[ma][na].y);
                *(__half2*)&Ch[(size_t)(r + 8) * 1024 + c] = __floats2half2_rn(acc[ma][na].z, acc[ma][na].w);
            } else {
                float* Cf = (float*)Cv;
                const float bx = bias[c], by = bias[c + 1];
                *(float2*)&Cf[(size_t)r * 1024 + c]       = make_float2(acc[ma][na].x + bx, acc[ma][na].y + by);
                *(float2*)&Cf[(size_t)(r + 8) * 1024 + c] = make_float2(acc[ma][na].z + bx, acc[ma][na].w + by);
            }
        }
    }
}

__global__ __launch_bounds__(256, 2) void proj3h_kernel()
{
    const int z = blockIdx.z;
    const __half* A = g_Xh + (size_t)z * Mrows * Dm;
    const __half* Bt = g_Wth + (size_t)z * Dm * Dm;
    __half* C = (z == 0) ? g_Qh : (z == 1) ? g_Kh : g_Vh;
    gemm_h_body<true>(A, Bt, nullptr, C);
}

__global__ __launch_bounds__(256, 2) void outprojh_kernel(
    const float* __restrict__ bo, float* __restrict__ out)
{
    gemm_h_body<false>(g_ctxh, g_Wth + (size_t)3 * Dm * Dm, bo, out);
}

// =====================================================================
// relk: Rt[bh][r][i] = dot(Q[b,i,h*64:], rel_k[r,:])
// =====================================================================
__global__ __launch_bounds__(128) void relk_kernel(const float* __restrict__ rel_k)
{
    __shared__ float4 RK[NR][16];
    const int bh = blockIdx.y;
    const int b = bh >> 4, h = bh & 15;
    const int i0 = blockIdx.x * 128;
    const int tid = threadIdx.x;

    for (int idx = tid; idx < NR * 16; idx += 128)
        RK[idx / 16][idx % 16] = ((const float4*)rel_k)[idx];
    __syncthreads();

    float2 q[32];
    const __half2* qrow = (const __half2*)&g_Qh[(size_t)(b * Sq + i0 + tid) * Dm + h * DK];
    #pragma unroll
    for (int d = 0; d < 32; d++) q[d] = __half22float2(qrow[d]);

    float* outp = &g_Rt[(size_t)bh * NR * Sq + i0 + tid];
    #pragma unroll 1
    for (int r = 0; r < NR; r++) {
        float s = 0.f;
        #pragma unroll
        for (int d = 0; d < 16; d++) {
            float4 rk = RK[r][d];
            s += q[2 * d].x * rk.x + q[2 * d].y * rk.y + q[2 * d + 1].x * rk.z + q[2 * d + 1].y * rk.w;
        }
        outp[(size_t)r * Sq] = s;
    }
}

// =====================================================================
// FUSED scores+softmax: logits live in registers only.
// Block = 32 query rows x 1 head x all 1024 keys. 512 threads (16 warps).
// =====================================================================
#define SMX_K    0
#define SMX_Q    131072
#define SMX_PMAX 135168
#define SMX_PSUM 137216
#define SMX_PLOW 139264
#define SMX_PHI  141312
#define SMX_FMAX 143360
#define SMX_FINV 143488
#define SMX_SW   143616
#define SMX_SMEM 160000

__global__ __launch_bounds__(512, 1) void scoresmax_kernel()
{
    extern __shared__ char smx[];
    float* pmax = (float*)(smx + SMX_PMAX);
    float* psum = (float*)(smx + SMX_PSUM);
    float* plow = (float*)(smx + SMX_PLOW);
    float* phi  = (float*)(smx + SMX_PHI);
    float* fmax = (float*)(smx + SMX_FMAX);
    float* finv = (float*)(smx + SMX_FINV);
    float* sW   = (float*)(smx + SMX_SW);

    const int bh = blockIdx.y;
    const int b = bh >> 4, h = bh & 15;
    const int i0 = blockIdx.x * 32;
    const int tid = threadIdx.x;
    const int lane = tid & 31, wp = tid >> 5;
    const int g = lane >> 2, t = lane & 3;

    const uint32_t sbK = (uint32_t)__cvta_generic_to_shared(smx + SMX_K);
    const uint32_t sbQ = (uint32_t)__cvta_generic_to_shared(smx + SMX_Q);

    for (int idx = tid; idx < 32 * 128; idx += 512) sW[idx] = 0.f;

    for (int id = tid; id < 8192; id += 512) {
        const int row = id >> 3, seg = id & 7;
        const uint32_t dst = sbK + row * 128 + ((seg * 16) ^ ((row & 7) << 4));
        cp16s(dst, &g_Kh[(size_t)(b * Sq + row) * Dm + h * DK + seg * 8]);
    }
    if (tid < 256) {
        const int row = tid >> 3, seg = tid & 7;
        const uint32_t dst = sbQ + row * 128 + ((seg * 16) ^ ((row & 7) << 4));
        cp16s(dst, &g_Qh[(size_t)(b * Sq + i0 + row) * Dm + h * DK + seg * 8]);
    }
    CP_COMMIT(); CP_WAIT0();
    __syncthreads();

    float4 acc[2][8];
    #pragma unroll
    for (int mt = 0; mt < 2; mt++)
        #pragma unroll
        for (int nt = 0; nt < 8; nt++) acc[mt][nt] = make_float4(0.f, 0.f, 0.f, 0.f);

    const int arow = (lane & 7) + ((lane >> 3) & 1) * 8;
    const int acolsel = (lane >> 4) * 16;
    const int brow7 = lane & 7;
    const int brow = (lane & 7) + ((lane >> 4) << 3);
    const int bcolsel = ((lane >> 3) & 1) * 16;

    #pragma unroll
    for (int ks = 0; ks < 4; ks++) {
        const int kb2 = ks * 32;
        uint32_t af[2][4];
        #pragma unroll
        for (int mt = 0; mt < 2; mt++) {
            const int row = mt * 16 + arow;
            const uint32_t col = (uint32_t)((kb2 + acolsel) ^ ((arow & 7) << 4));
            ldm_x4(af[mt], sbQ + row * 128 + col);
        }
        #pragma unroll
        for (int nt2 = 0; nt2 < 4; nt2++) {
            const int n0 = wp * 64 + nt2 * 16;
            const uint32_t colb = (uint32_t)((kb2 + bcolsel) ^ (brow7 << 4));
            uint32_t bq[4];
            ldm_x4(bq, sbK + (n0 + brow) * 128 + colb);
            uint32_t bf0[2] = { bq[0], bq[1] }, bf1[2] = { bq[2], bq[3] };
            #pragma unroll
            for (int mt = 0; mt < 2; mt++) {
                mma16(acc[mt][2 * nt2],     af[mt], bf0);
                mma16(acc[mt][2 * nt2 + 1], af[mt], bf1);
            }
        }
    }

    const float* RtB = &g_Rt[(size_t)bh * NR * Sq];
    float mxa[2] = { -1e30f, -1e30f }, mxb[2] = { -1e30f, -1e30f };
    #pragma unroll
    for (int mt = 0; mt < 2; mt++) {
        const int ia = i0 + mt * 16 + g, ib = ia + 8;
        #pragma unroll
        for (int nt = 0; nt < 8; nt++) {
            const int j0 = wp * 64 + nt * 8 + 2 * t;
            float4& a = acc[mt][nt];
            int r0 = j0 - ia;     r0 = (r0 < -32 ? -32 : (r0 > 32 ? 32 : r0)) + 32;
            int r1 = j0 + 1 - ia; r1 = (r1 < -32 ? -32 : (r1 > 32 ? 32 : r1)) + 32;
            int r2 = j0 - ib;     r2 = (r2 < -32 ? -32 : (r2 > 32 ? 32 : r2)) + 32;
            int r3 = j0 + 1 - ib; r3 = (r3 < -32 ? -32 : (r3 > 32 ? 32 : r3)) + 32;
            a.x = a.x * 0.125f + RtB[(size_t)r0 * Sq + ia];
            a.y = a.y * 0.125f + RtB[(size_t)r1 * Sq + ia];
            a.z = a.z * 0.125f + RtB[(size_t)r2 * Sq + ib];
            a.w = a.w * 0.125f + RtB[(size_t)r3 * Sq + ib];
            mxa[mt] = fmaxf(mxa[mt], fmaxf(a.x, a.y));
            mxb[mt] = fmaxf(mxb[mt], fmaxf(a.z, a.w));
        }
    }
    #pragma unroll
    for (int o = 1; o <= 2; o <<= 1) {
        #pragma unroll
        for (int mt = 0; mt < 2; mt++) {
            mxa[mt] = fmaxf(mxa[mt], __shfl_xor_sync(0xFFFFFFFFu, mxa[mt], o));
            mxb[mt] = fmaxf(mxb[mt], __shfl_xor_sync(0xFFFFFFFFu, mxb[mt], o));
        }
    }
    if (t == 0) {
        #pragma unroll
        for (int mt = 0; mt < 2; mt++) {
            pmax[(mt * 16 + g) * 16 + wp]     = mxa[mt];
            pmax[(mt * 16 + g + 8) * 16 + wp] = mxb[mt];
        }
    }
    __syncthreads();
    if (tid < 32) {
        float m = -1e30f;
        #pragma unroll
        for (int ww = 0; ww < 16; ww++) m = fmaxf(m, pmax[tid * 16 + ww]);
        fmax[tid] = m;
    }
    __syncthreads();

    float sa[2] = {0.f, 0.f}, sb2[2] = {0.f, 0.f};
    float la[2] = {0.f, 0.f}, lb[2] = {0.f, 0.f};
    float ha[2] = {0.f, 0.f}, hb[2] = {0.f, 0.f};
    #pragma unroll
    for (int mt = 0; mt < 2; mt++) {
        const float ma2 = fmax[mt * 16 + g], mb2 = fmax[mt * 16 + g + 8];
        const int ia = i0 + mt * 16 + g, ib = ia + 8;
        #pragma unroll
        for (int nt = 0; nt < 8; nt++) {
            const int j0 = wp * 64 + nt * 8 + 2 * t;
            float4& a = acc[mt][nt];
            a.x = __expf(a.x - ma2); a.y = __expf(a.y - ma2);
            a.z = __expf(a.z - mb2); a.w = __expf(a.w - mb2);
            sa[mt] += a.x + a.y; sb2[mt] += a.z + a.w;
            const int d0 = j0 - ia, d1 = d0 + 1, d2 = j0 - ib, d3 = d2 + 1;
            if (d0 <= -32) la[mt] += a.x; else if (d0 >= 32) ha[mt] += a.x;
            if (d1 <= -32) la[mt] += a.y; else if (d1 >= 32) ha[mt] += a.y;
            if (d2 <= -32) lb[mt] += a.z; else if (d2 >= 32) hb[mt] += a.z;
            if (d3 <= -32) lb[mt] += a.w; else if (d3 >= 32) hb[mt] += a.w;
        }
    }
    #pragma unroll
    for (int o = 1; o <= 2; o <<= 1) {
        #pragma unroll
        for (int mt = 0; mt < 2; mt++) {
            sa[mt] += __shfl_xor_sync(0xFFFFFFFFu, sa[mt], o);
            sb2[mt] += __shfl_xor_sync(0xFFFFFFFFu, sb2[mt], o);
            la[mt] += __shfl_xor_sync(0xFFFFFFFFu, la[mt], o);
            lb[mt] += __shfl_xor_sync(0xFFFFFFFFu, lb[mt], o);
            ha[mt] += __shfl_xor_sync(0xFFFFFFFFu, ha[mt], o);
            hb[mt] += __shfl_xor_sync(0xFFFFFFFFu, hb[mt], o);
        }
    }
    if (t == 0) {
        #pragma unroll
        for (int mt = 0; mt < 2; mt++) {
            const int ra = (mt * 16 + g) * 16 + wp, rb = (mt * 16 + g + 8) * 16 + wp;
            psum[ra] = sa[mt]; psum[rb] = sb2[mt];
            plow[ra] = la[mt]; plow[rb] = lb[mt];
            phi[ra]  = ha[mt]; phi[rb]  = hb[mt];
        }
    }
    __syncthreads();
    if (tid < 32) {
        float s = 0.f, l = 0.f, hh = 0.f;
        #pragma unroll
        for (int ww = 0; ww < 16; ww++) {
            s += psum[tid * 16 + ww]; l += plow[tid * 16 + ww]; hh += phi[tid * 16 + ww];
        }
        const float inv = 1.f / s;
        finv[tid] = inv;
        sW[tid * 128 + 0]  = l * inv;
        sW[tid * 128 + 64] = hh * inv;
    }
    __syncthreads();

    #pragma unroll
    for (int mt = 0; mt < 2; mt++) {
        const int ra = mt * 16 + g, rb = ra + 8;
        const int ia = i0 + ra, ib = i0 + rb;
        const float inva = finv[ra], invb = finv[rb];
        __half* rowa = &g_attnh[((size_t)bh * Sq + ia) * Sq];
        __half* rowb2 = &g_attnh[((size_t)bh * Sq + ib) * Sq];
        #pragma unroll
        for (int nt = 0; nt < 8; nt++) {
            const int j0 = wp * 64 + nt * 8 + 2 * t;
            float4& a = acc[mt][nt];
            a.x *= inva; a.y *= inva; a.z *= invb; a.w *= invb;
            *(__half2*)&rowa[j0]  = __floats2half2_rn(a.x, a.y);
            *(__half2*)&rowb2[j0] = __floats2half2_rn(a.z, a.w);
            const int d0 = j0 - ia, d1 = d0 + 1, d2 = j0 - ib, d3 = d2 + 1;
            if (d0 > -32 && d0 < 32) sW[ra * 128 + d0 + 32] = a.x;
            if (d1 > -32 && d1 < 32) sW[ra * 128 + d1 + 32] = a.y;
            if (d2 > -32 && d2 < 32) sW[rb * 128 + d2 + 32] = a.z;
            if (d3 > -32 && d3 < 32) sW[rb * 128 + d3 + 32] = a.w;
        }
    }
    __syncthreads();

    for (int idx = tid; idx < 32 * 128; idx += 512) {
        const int r = idx >> 7, c = idx & 127;
        g_Wh[(size_t)(bh * Sq + i0 + r) * WPAD + c] = __float2half(sW[idx]);
    }
}

// =====================================================================
// FAT kernel: blocks [0,512) run ctx GEMM; blocks [512,2560) run head-mean.
// ctx: attn @ V + W @ rel_v (fp16 mma + ldmatrix/.trans; BM=128,BN=64,BK=64)
// mean: out_attn[b,i,j] = (1/16) sum_h probs  (DRAM-bound, fills idle BW)
// =====================================================================
struct CtxStage { __half As[128][72]; __half Bs[64][72]; };
#define CTX_STAGE_SZ ((int)sizeof(CtxStage))   // 27648
#define CTX_SMEM (3 * CTX_STAGE_SZ)            // 82944
#define CTX_BLOCKS 512                          // 8 x 64
#define MEAN_BLOCKS 2048

__global__ __launch_bounds__(256, 2) void ctxmean_kernel(float* __restrict__ out_attn)
{
    const int tid = threadIdx.x;

    if (blockIdx.x >= CTX_BLOCKS) {
        // ---------------- mean path ----------------
        const int mb = blockIdx.x - CTX_BLOCKS;
        const size_t idx = (size_t)mb * 256 + tid;
        const size_t per_b = (size_t)Sq * Sq / 8;
        const int b = (int)(idx / per_b);
        const size_t rem = idx % per_b;
        const uint4* base = (const uint4*)(g_attnh + (size_t)b * Hh * Sq * Sq) + rem;

        float s[8] = {0.f, 0.f, 0.f, 0.f, 0.f, 0.f, 0.f, 0.f};
        #pragma unroll
        for (int h2 = 0; h2 < Hh; h2++) {
            const uint4 u = base[(size_t)h2 * per_b];
            float2 f;
            f = __half22float2(*(const __half2*)&u.x); s[0] += f.x; s[1] += f.y;
            f = __half22float2(*(const __half2*)&u.y); s[2] += f.x; s[3] += f.y;
            f = __half22float2(*(const __half2*)&u.z); s[4] += f.x; s[5] += f.y;
            f = __half22float2(*(const __half2*)&u.w); s[6] += f.x; s[7] += f.y;
        }
        float* o = &out_attn[(size_t)b * Sq * Sq + rem * 8];
        const float c = 1.0f / Hh;
        *(float4*)&o[0] = make_float4(s[0] * c, s[1] * c, s[2] * c, s[3] * c);
        *(float4*)&o[4] = make_float4(s[4] * c, s[5] * c, s[6] * c, s[7] * c);
        return;
    }

    // ---------------- ctx path ----------------
    extern __shared__ CtxStage cstages[];
    const int bh = blockIdx.x >> 3;
    const int b = bh >> 4, h = bh & 15;
    const int i0 = (blockIdx.x & 7) * 128;
    const int lane = tid & 31, wid = tid >> 5;
    const int g = lane >> 2, t = lane & 3;
    const int wm = (wid >> 2) * 64;
    const int wn = (wid & 3) * 16;

    const uint32_t sb = (uint32_t)__cvta_generic_to_shared(cstages);
    const uint32_t laneA = (uint32_t)(((lane & 7) + ((lane >> 3) & 1) * 8) * 144 + (lane >> 4) * 16);
    const uint32_t laneBt = (uint32_t)(((lane & 7) + ((lane >> 3) & 1) * 8) * 144 + (lane >> 4) * 16);
    const uint32_t warpA  = (uint32_t)(wm * 144) + laneA;
    const uint32_t warpBt = (uint32_t)(18432 + wn * 2) + laneBt;

    auto issue = [&](int kt, int s) {
        CtxStage& st = cstages[s];
        if (kt < 16) {
            const int kb = kt * 64;
            #pragma unroll
            for (int it = 0; it < 4; it++) {
                const int id = it * 256 + tid;
                const int row = id >> 3, seg = id & 7;
                cp16(&st.As[row][seg * 8],
                     &g_attnh[((size_t)bh * Sq + i0 + row) * Sq + kb + seg * 8]);
            }
            #pragma unroll
            for (int it = 0; it < 2; it++) {
                const int id = it * 256 + tid;
                const int vr = id >> 3, vs = id & 7;
                cp16(&st.Bs[vr][vs * 8],
                     &g_Vh[(size_t)(b * Sq + kb + vr) * Dm + h * DK + vs * 8]);
            }
        } else {
            const int kk = (kt - 16) * 64;
            #pragma unroll
            for (int it = 0; it < 4; it++) {
                const int id = it * 256 + tid;
                const int row = id >> 3, seg = id & 7;
                cp16(&st.As[row][seg * 8],
                     &g_Wh[(size_t)(bh * Sq + i0 + row) * WPAD + kk + seg * 8]);
            }
            #pragma unroll
            for (int it = 0; it < 2; it++) {
                const int id = it * 256 + tid;
                const int vr = id >> 3, vs = id & 7;
                cp16(&st.Bs[vr][vs * 8], &g_relvh[(kk + vr) * DK + vs * 8]);
            }
        }
    };

    float4 acc[4][2];
    #pragma unroll
    for (int i = 0; i < 4; i++)
        #pragma unroll
        for (int j = 0; j < 2; j++) acc[i][j] = make_float4(0.f, 0.f, 0.f, 0.f);

    issue(0, 0); CP_COMMIT();
    issue(1, 1); CP_COMMIT();

    int scur = 0, snxt = 2;
    #pragma unroll 1
    for (int kt = 0; kt < 18; kt++) {
        CP_WAIT1();
        __syncthreads();
        if (kt + 2 < 18) issue(kt + 2, snxt);
        CP_COMMIT();

        const uint32_t stb = sb + scur * CTX_STAGE_SZ;
        #pragma unroll
        for (int ks = 0; ks < 4; ks++) {
            uint32_t af[4][4], bf[2][2];
            #pragma unroll
            for (int ma = 0; ma < 4; ma++)
                ldm_x4(af[ma], stb + warpA + ma * 2304 + ks * 32);
            {
                uint32_t bq[4];
                ldm_x4_t(bq, stb + warpBt + ks * 16 * 144);
                bf[0][0] = bq[0]; bf[0][1] = bq[1]; bf[1][0] = bq[2]; bf[1][1] = bq[3];
            }
            #pragma unroll
            for (int ma = 0; ma < 4; ma++)
                #pragma unroll
                for (int na = 0; na < 2; na++)
                    mma16(acc[ma][na], af[ma], bf[na]);
        }
        scur = (scur + 1 == 3) ? 0 : scur + 1;
        snxt = (snxt + 1 == 3) ? 0 : snxt + 1;
    }

    #pragma unroll
    for (int ma = 0; ma < 4; ma++) {
        const int r = i0 + wm + ma * 16 + g;
        #pragma unroll
        for (int na = 0; na < 2; na++) {
            const int c = wn + na * 8 + 2 * t;
            *(__half2*)&g_ctxh[(size_t)(b * Sq + r) * Dm + h * DK + c] =
                __floats2half2_rn(acc[ma][na].x, acc[ma][na].y);
            *(__half2*)&g_ctxh[(size_t)(b * Sq + r + 8) * Dm + h * DK + c] =
                __floats2half2_rn(acc[ma][na].z, acc[ma][na].w);
        }
    }
}

// ---------------- launch ----------------
extern "C" void kernel_launch(void* const* d_in, const int* in_sizes, int n_in,
                              void* d_out, int out_size)
{
    const float* query = (const float*)d_in[0];
    const float* key   = (const float*)d_in[1];
    const float* value = (const float*)d_in[2];
    const float* Wq    = (const float*)d_in[3];
    const float* Wk    = (const float*)d_in[4];
    const float* Wv    = (const float*)d_in[5];
    const float* Wo    = (const float*)d_in[6];
    const float* bo    = (const float*)d_in[7];
    const float* rel_k = (const float*)d_in[8];
    const float* rel_v = (const float*)d_in[9];

    float* out      = (float*)d_out;                 // [B,S,D]
    float* out_attn = out + (size_t)Bb * Sq * Dm;    // [B,S,S]

    static bool attr_set = false;
    if (!attr_set) {
        cudaFuncSetAttribute(proj3h_kernel,
                             cudaFuncAttributeMaxDynamicSharedMemorySize, PROJ_SMEM);
        cudaFuncSetAttribute(outprojh_kernel,
                             cudaFuncAttributeMaxDynamicSharedMemorySize, PROJ_SMEM);
        cudaFuncSetAttribute(ctxmean_kernel,
                             cudaFuncAttributeMaxDynamicSharedMemorySize, CTX_SMEM);
        cudaFuncSetAttribute(scoresmax_kernel,
                             cudaFuncAttributeMaxDynamicSharedMemorySize, SMX_SMEM);
        attr_set = true;
    }

    // 0. prep: fp16 conversions
    cvt_inputs_kernel<<<dim3(Mrows * Dm / 4 / 256, 3), 256>>>(query, key, value);
    cvt_w_kernel<<<dim3(Dm / 32, Dm / 32, 4), 256>>>(Wq, Wk, Wv, Wo);
    cvt_relv_kernel<<<1, 256>>>(rel_v);

    // 1. projections (fp16 mma + ldmatrix, BK=64)
    proj3h_kernel<<<dim3(Dm / 128, Mrows / 128, 3), 256, PROJ_SMEM>>>();

    // 2. rel_k dot products
    relk_kernel<<<dim3(Sq / 128, BH), 128>>>(rel_k);

    // 3. fused scores + softmax (512 thr, 16 warps)
    scoresmax_kernel<<<dim3(Sq / 32, BH), 512, SMX_SMEM>>>();

    // 4+5. FAT kernel: ctx GEMM blocks + head-mean blocks run concurrently
    ctxmean_kernel<<<CTX_BLOCKS + MEAN_BLOCKS, 256, CTX_SMEM>>>(out_attn);

    // 6. output projection + bias (fp16 mma + ldmatrix, BK=64)
    outprojh_kernel<<<dim3(Dm / 128, Mrows / 128), 256, PROJ_SMEM>>>(bo, out);
}

// round 14
// speedup vs baseline: 6.2130x; 1.0002x over previous
#include <cuda_runtime.h>
#include <cuda_fp16.h>
#include <cstdint>
#include <cstddef>

#define Sq 1024
#define Bb 4
#define Dm 1024
#define Hh 16
#define DK 64
#define NR 65
#define WPAD 128
#define BH (Bb*Hh)
#define Mrows (Bb*Sq)

// ---------------- scratch (device globals; no allocation) ----------------
__device__ __align__(128) __half g_attnh[(size_t)BH * Sq * Sq];   // fp16 probs, 128 MB
__device__ __align__(128) __half g_Qh[(size_t)Mrows * Dm];
__device__ __align__(128) __half g_Kh[(size_t)Mrows * Dm];
__device__ __align__(128) __half g_Vh[(size_t)Mrows * Dm];
__device__ __align__(128) __half g_ctxh[(size_t)Mrows * Dm];
__device__ __align__(128) __half g_Xh[(size_t)3 * Mrows * Dm];    // fp16 inputs q,k,v
__device__ __align__(128) __half g_Wth[(size_t)4 * Dm * Dm];      // W^T fp16: q,k,v,o
__device__ __align__(128) __half g_Wh[(size_t)BH * Sq * WPAD];    // bucket sums fp16 (128-wide, zero tail)
__device__ __align__(128) __half g_relvh[128 * DK];               // rel_v fp16, zero-padded to 128 rows
__device__ __align__(128) float  g_Rt[(size_t)BH * NR * Sq];      // rel_k bias, transposed

// ---------------- helpers ----------------
__device__ __forceinline__ void mma16(float4& d, const uint32_t* a, const uint32_t* b) {
    asm volatile("mma.sync.aligned.m16n8k16.row.col.f32.f16.f16.f32 "
                 "{%0,%1,%2,%3},{%4,%5,%6,%7},{%8,%9},{%0,%1,%2,%3};"
                 : "+f"(d.x), "+f"(d.y), "+f"(d.z), "+f"(d.w)
                 : "r"(a[0]), "r"(a[1]), "r"(a[2]), "r"(a[3]), "r"(b[0]), "r"(b[1]));
}
__device__ __forceinline__ void ldm_x4(uint32_t* r, uint32_t a) {
    asm volatile("ldmatrix.sync.aligned.m8n8.x4.shared.b16 {%0,%1,%2,%3}, [%4];"
                 : "=r"(r[0]), "=r"(r[1]), "=r"(r[2]), "=r"(r[3]) : "r"(a));
}
__device__ __forceinline__ void ldm_x4_t(uint32_t* r, uint32_t a) {
    asm volatile("ldmatrix.sync.aligned.m8n8.x4.trans.shared.b16 {%0,%1,%2,%3}, [%4];"
                 : "=r"(r[0]), "=r"(r[1]), "=r"(r[2]), "=r"(r[3]) : "r"(a));
}
__device__ __forceinline__ void cp16(void* dst, const void* src) {
    uint32_t d = (uint32_t)__cvta_generic_to_shared(dst);
    asm volatile("cp.async.cg.shared.global [%0], [%1], 16;" :: "r"(d), "l"(src) : "memory");
}
__device__ __forceinline__ void cp16s(uint32_t dst, const void* src) {
    asm volatile("cp.async.cg.shared.global [%0], [%1], 16;" :: "r"(dst), "l"(src) : "memory");
}
#define CP_COMMIT() asm volatile("cp.async.commit_group;" ::: "memory")
#define CP_WAIT1()  asm volatile("cp.async.wait_group 1;" ::: "memory")
#define CP_WAIT0()  asm volatile("cp.async.wait_group 0;" ::: "memory")

// ---------------- prep kernels ----------------
__global__ __launch_bounds__(256) void cvt_inputs_kernel(
    const float* __restrict__ q, const float* __restrict__ k, const float* __restrict__ v)
{
    const int z = blockIdx.y;
    const float4* s = (const float4*)(z == 0 ? q : z == 1 ? k : v);
    const int idx = blockIdx.x * 256 + threadIdx.x;
    float4 a = s[idx];
    __half2* d = (__half2*)(g_Xh + (size_t)z * Mrows * Dm);
    d[idx * 2]     = __floats2half2_rn(a.x, a.y);
    d[idx * 2 + 1] = __floats2half2_rn(a.z, a.w);
}

__global__ __launch_bounds__(256) void cvt_w_kernel(
    const float* __restrict__ Wq, const float* __restrict__ Wk,
    const float* __restrict__ Wv, const float* __restrict__ Wo)
{
    __shared__ float t[32][33];
    const int z = blockIdx.z;
    const float* W = (z == 0) ? Wq : (z == 1) ? Wk : (z == 2) ? Wv : Wo;
    __half* Wt = g_Wth + (size_t)z * Dm * Dm;
    const int x0 = blockIdx.x * 32, y0 = blockIdx.y * 32;
    const int tx = threadIdx.x & 31, ty = threadIdx.x >> 5;
    #pragma unroll
    for (int i = 0; i < 4; i++)
        t[ty + 8 * i][tx] = W[(size_t)(y0 + ty + 8 * i) * Dm + x0 + tx];
    __syncthreads();
    #pragma unroll
    for (int i = 0; i < 4; i++)
        Wt[(size_t)(x0 + ty + 8 * i) * Dm + y0 + tx] = __float2half(t[tx][ty + 8 * i]);
}

__global__ __launch_bounds__(256) void cvt_relv_kernel(const float* __restrict__ rel_v)
{
    for (int idx = threadIdx.x; idx < 128 * DK; idx += 256) {
        const int row = idx / DK, col = idx % DK;
        g_relvh[idx] = __float2half(row < NR ? rel_v[row * DK + col] : 0.f);
    }
}

// =====================================================================
// fp16 GEMM: C[4096,1024](tile 128x128) = A[m][k] @ Bt[n][k]^T (+bias)
// BM=128, BN=128, BK=64; 3-stage cp.async ring; 8 warps 2x4; warp 64x32
// =====================================================================
struct ProjStage { __half As[128][72]; __half Bs[128][72]; };
#define PROJ_STAGE_SZ ((int)sizeof(ProjStage))   // 36864
#define PROJ_SMEM (3 * PROJ_STAGE_SZ)            // 110592

template<bool HALF_OUT>
__device__ __forceinline__ void gemm_h_body(const __half* __restrict__ A,
                                            const __half* __restrict__ Bt,
                                            const float* __restrict__ bias,
                                            void* __restrict__ Cv)
{
    extern __shared__ ProjStage pstages[];
    const int tid = threadIdx.x, lane = tid & 31, wid = tid >> 5;
    const int g = lane >> 2, t = lane & 3;
    const int wm = (wid >> 2) * 64, wn = (wid & 3) * 32;
    const int row0 = blockIdx.y * 128, col0 = blockIdx.x * 128;

    const uint32_t sb = (uint32_t)__cvta_generic_to_shared(pstages);
    const uint32_t laneA = (uint32_t)(((lane & 7) + ((lane >> 3) & 1) * 8) * 144 + (lane >> 4) * 16);
    const uint32_t laneB = (uint32_t)((lane & 7) * 144 + ((lane >> 3) & 1) * 16 + (lane >> 4) * 1152);
    const uint32_t warpA = (uint32_t)(wm * 144) + laneA;
    const uint32_t warpB = (uint32_t)(18432 + wn * 144) + laneB;

    auto issue = [&](int kt, int s) {
        ProjStage& st = pstages[s];
        const int kb = kt * 64;
        #pragma unroll
        for (int it = 0; it < 4; it++) {
            const int id = it * 256 + tid;
            const int row = id >> 3, seg = id & 7;
            cp16(&st.As[row][seg * 8], &A[(size_t)(row0 + row) * 1024 + kb + seg * 8]);
            cp16(&st.Bs[row][seg * 8], &Bt[(size_t)(col0 + row) * 1024 + kb + seg * 8]);
        }
    };

    float4 acc[4][4];
    #pragma unroll
    for (int i = 0; i < 4; i++)
        #pragma unroll
        for (int j = 0; j < 4; j++) acc[i][j] = make_float4(0.f, 0.f, 0.f, 0.f);

    issue(0, 0); CP_COMMIT();
    issue(1, 1); CP_COMMIT();

    int scur = 0, snxt = 2;
    #pragma unroll 1
    for (int kt = 0; kt < 16; kt++) {
        CP_WAIT1();
        __syncthreads();
        if (kt + 2 < 16) issue(kt + 2, snxt);
        CP_COMMIT();

        const uint32_t stb = sb + scur * PROJ_STAGE_SZ;
        #pragma unroll
        for (int ks = 0; ks < 4; ks++) {
            const uint32_t k0b = ks * 32;
            uint32_t af[4][4], bf[4][2];
            #pragma unroll
            for (int ma = 0; ma < 4; ma++)
                ldm_x4(af[ma], stb + warpA + ma * 2304 + k0b);
            #pragma unroll
            for (int p = 0; p < 2; p++) {
                uint32_t bq[4];
                ldm_x4(bq, stb + warpB + p * 2304 + k0b);
                bf[2 * p][0] = bq[0]; bf[2 * p][1] = bq[1];
                bf[2 * p + 1][0] = bq[2]; bf[2 * p + 1][1] = bq[3];
            }
            #pragma unroll
            for (int ma = 0; ma < 4; ma++)
                #pragma unroll
                for (int na = 0; na < 4; na++)
                    mma16(acc[ma][na], af[ma], bf[na]);
        }
        scur = (scur + 1 == 3) ? 0 : scur + 1;
        snxt = (snxt + 1 == 3) ? 0 : snxt + 1;
    }

    #pragma unroll
    for (int ma = 0; ma < 4; ma++) {
        const int r = row0 + wm + ma * 16 + g;
        #pragma unroll
        for (int na = 0; na < 4; na++) {
            const int c = col0 + wn + na * 8 + 2 * t;
            if (HALF_OUT) {
                __half* Ch = (__half*)Cv;
                *(__half2*)&Ch[(size_t)r * 1024 + c]       = __floats2half2_rn(acc[ma][na].x, acc[ma][na].y);
                *(__half2*)&Ch[(size_t)(r + 8) * 1024 + c] = __floats2half2_rn(acc[ma][na].z, acc[ma][na].w);
            } else {
                float* Cf = (float*)Cv;
                const float bx = bias[c], by = bias[c + 1];
                *(float2*)&Cf[(size_t)r * 1024 + c]       = make_float2(acc[ma][na].x + bx, acc[ma][na].y + by);
                *(float2*)&Cf[(size_t)(r + 8) * 1024 + c] = make_float2(acc[ma][na].z + bx, acc[ma][na].w + by);
            }
        }
    }
}

__global__ __launch_bounds__(256, 2) void proj3h_kernel()
{
    const int z = blockIdx.z;
    const __half* A = g_Xh + (size_t)z * Mrows * Dm;
    const __half* Bt = g_Wth + (size_t)z * Dm * Dm;
    __half* C = (z == 0) ? g_Qh : (z == 1) ? g_Kh : g_Vh;
    gemm_h_body<true>(A, Bt, nullptr, C);
}

__global__ __launch_bounds__(256, 2) void outprojh_kernel(
    const float* __restrict__ bo, float* __restrict__ out)
{
    gemm_h_body<false>(g_ctxh, g_Wth + (size_t)3 * Dm * Dm, bo, out);
}

// =====================================================================
// relk: Rt[bh][r][i] = dot(Q[b,i,h*64:], rel_k[r,:])
// =====================================================================
__global__ __launch_bounds__(128) void relk_kernel(const float* __restrict__ rel_k)
{
    __shared__ float4 RK[NR][16];
    const int bh = blockIdx.y;
    const int b = bh >> 4, h = bh & 15;
    const int i0 = blockIdx.x * 128;
    const int tid = threadIdx.x;

    for (int idx = tid; idx < NR * 16; idx += 128)
        RK[idx / 16][idx % 16] = ((const float4*)rel_k)[idx];
    __syncthreads();

    float2 q[32];
    const __half2* qrow = (const __half2*)&g_Qh[(size_t)(b * Sq + i0 + tid) * Dm + h * DK];
    #pragma unroll
    for (int d = 0; d < 32; d++) q[d] = __half22float2(qrow[d]);

    float* outp = &g_Rt[(size_t)bh * NR * Sq + i0 + tid];
    #pragma unroll 1
    for (int r = 0; r < NR; r++) {
        float s = 0.f;
        #pragma unroll
        for (int d = 0; d < 16; d++) {
            float4 rk = RK[r][d];
            s += q[2 * d].x * rk.x + q[2 * d].y * rk.y + q[2 * d + 1].x * rk.z + q[2 * d + 1].y * rk.w;
        }
        outp[(size_t)r * Sq] = s;
    }
}

// =====================================================================
// FUSED scores+softmax: logits live in registers only.
// Block = 32 query rows x 1 head x all 1024 keys. 512 threads (16 warps).
// =====================================================================
#define SMX_K    0
#define SMX_Q    131072
#define SMX_PMAX 135168
#define SMX_PSUM 137216
#define SMX_PLOW 139264
#define SMX_PHI  141312
#define SMX_FMAX 143360
#define SMX_FINV 143488
#define SMX_SW   143616
#define SMX_SMEM 160000

__global__ __launch_bounds__(512, 1) void scoresmax_kernel()
{
    extern __shared__ char smx[];
    float* pmax = (float*)(smx + SMX_PMAX);
    float* psum = (float*)(smx + SMX_PSUM);
    float* plow = (float*)(smx + SMX_PLOW);
    float* phi  = (float*)(smx + SMX_PHI);
    float* fmax = (float*)(smx + SMX_FMAX);
    float* finv = (float*)(smx + SMX_FINV);
    float* sW   = (float*)(smx + SMX_SW);

    const int bh = blockIdx.y;
    const int b = bh >> 4, h = bh & 15;
    const int i0 = blockIdx.x * 32;
    const int tid = threadIdx.x;
    const int lane = tid & 31, wp = tid >> 5;
    const int g = lane >> 2, t = lane & 3;

    const uint32_t sbK = (uint32_t)__cvta_generic_to_shared(smx + SMX_K);
    const uint32_t sbQ = (uint32_t)__cvta_generic_to_shared(smx + SMX_Q);

    for (int idx = tid; idx < 32 * 128; idx += 512) sW[idx] = 0.f;

    for (int id = tid; id < 8192; id += 512) {
        const int row = id >> 3, seg = id & 7;
        const uint32_t dst = sbK + row * 128 + ((seg * 16) ^ ((row & 7) << 4));
        cp16s(dst, &g_Kh[(size_t)(b * Sq + row) * Dm + h * DK + seg * 8]);
    }
    if (tid < 256) {
        const int row = tid >> 3, seg = tid & 7;
        const uint32_t dst = sbQ + row * 128 + ((seg * 16) ^ ((row & 7) << 4));
        cp16s(dst, &g_Qh[(size_t)(b * Sq + i0 + row) * Dm + h * DK + seg * 8]);
    }
    CP_COMMIT(); CP_WAIT0();
    __syncthreads();

    float4 acc[2][8];
    #pragma unroll
    for (int mt = 0; mt < 2; mt++)
        #pragma unroll
        for (int nt = 0; nt < 8; nt++) acc[mt][nt] = make_float4(0.f, 0.f, 0.f, 0.f);

    const int arow = (lane & 7) + ((lane >> 3) & 1) * 8;
    const int acolsel = (lane >> 4) * 16;
    const int brow7 = lane & 7;
    const int brow = (lane & 7) + ((lane >> 4) << 3);
    const int bcolsel = ((lane >> 3) & 1) * 16;

    #pragma unroll
    for (int ks = 0; ks < 4; ks++) {
        const int kb2 = ks * 32;
        uint32_t af[2][4];
        #pragma unroll
        for (int mt = 0; mt < 2; mt++) {
            const int row = mt * 16 + arow;
            const uint32_t col = (uint32_t)((kb2 + acolsel) ^ ((arow & 7) << 4));
            ldm_x4(af[mt], sbQ + row * 128 + col);
        }
        #pragma unroll
        for (int nt2 = 0; nt2 < 4; nt2++) {
            const int n0 = wp * 64 + nt2 * 16;
            const uint32_t colb = (uint32_t)((kb2 + bcolsel) ^ (brow7 << 4));
            uint32_t bq[4];
            ldm_x4(bq, sbK + (n0 + brow) * 128 + colb);
            uint32_t bf0[2] = { bq[0], bq[1] }, bf1[2] = { bq[2], bq[3] };
            #pragma unroll
            for (int mt = 0; mt < 2; mt++) {
                mma16(acc[mt][2 * nt2],     af[mt], bf0);
                mma16(acc[mt][2 * nt2 + 1], af[mt], bf1);
            }
        }
    }

    const float* RtB = &g_Rt[(size_t)bh * NR * Sq];
    float mxa[2] = { -1e30f, -1e30f }, mxb[2] = { -1e30f, -1e30f };
    #pragma unroll
    for (int mt = 0; mt < 2; mt++) {
        const int ia = i0 + mt * 16 + g, ib = ia + 8;
        #pragma unroll
        for (int nt = 0; nt < 8; nt++) {
            const int j0 = wp * 64 + nt * 8 + 2 * t;
            float4& a = acc[mt][nt];
            int r0 = j0 - ia;     r0 = (r0 < -32 ? -32 : (r0 > 32 ? 32 : r0)) + 32;
            int r1 = j0 + 1 - ia; r1 = (r1 < -32 ? -32 : (r1 > 32 ? 32 : r1)) + 32;
            int r2 = j0 - ib;     r2 = (r2 < -32 ? -32 : (r2 > 32 ? 32 : r2)) + 32;
            int r3 = j0 + 1 - ib; r3 = (r3 < -32 ? -32 : (r3 > 32 ? 32 : r3)) + 32;
            a.x = a.x * 0.125f + RtB[(size_t)r0 * Sq + ia];
            a.y = a.y * 0.125f + RtB[(size_t)r1 * Sq + ia];
            a.z = a.z * 0.125f + RtB[(size_t)r2 * Sq + ib];
            a.w = a.w * 0.125f + RtB[(size_t)r3 * Sq + ib];
            mxa[mt] = fmaxf(mxa[mt], fmaxf(a.x, a.y));
            mxb[mt] = fmaxf(mxb[mt], fmaxf(a.z, a.w));
        }
    }
    #pragma unroll
    for (int o = 1; o <= 2; o <<= 1) {
        #pragma unroll
        for (int mt = 0; mt < 2; mt++) {
            mxa[mt] = fmaxf(mxa[mt], __shfl_xor_sync(0xFFFFFFFFu, mxa[mt], o));
            mxb[mt] = fmaxf(mxb[mt], __shfl_xor_sync(0xFFFFFFFFu, mxb[mt], o));
        }
    }
    if (t == 0) {
        #pragma unroll
        for (int mt = 0; mt < 2; mt++) {
            pmax[(mt * 16 + g) * 16 + wp]     = mxa[mt];
            pmax[(mt * 16 + g + 8) * 16 + wp] = mxb[mt];
        }
    }
    __syncthreads();
    if (tid < 32) {
        float m = -1e30f;
        #pragma unroll
        for (int ww = 0; ww < 16; ww++) m = fmaxf(m, pmax[tid * 16 + ww]);
        fmax[tid] = m;
    }
    __syncthreads();

    float sa[2] = {0.f, 0.f}, sb2[2] = {0.f, 0.f};
    float la[2] = {0.f, 0.f}, lb[2] = {0.f, 0.f};
    float ha[2] = {0.f, 0.f}, hb[2] = {0.f, 0.f};
    #pragma unroll
    for (int mt = 0; mt < 2; mt++) {
        const float ma2 = fmax[mt * 16 + g], mb2 = fmax[mt * 16 + g + 8];
        const int ia = i0 + mt * 16 + g, ib = ia + 8;
        #pragma unroll
        for (int nt = 0; nt < 8; nt++) {
            const int j0 = wp * 64 + nt * 8 + 2 * t;
            float4& a = acc[mt][nt];
            a.x = __expf(a.x - ma2); a.y = __expf(a.y - ma2);
            a.z = __expf(a.z - mb2); a.w = __expf(a.w - mb2);
            sa[mt] += a.x + a.y; sb2[mt] += a.z + a.w;
            const int d0 = j0 - ia, d1 = d0 + 1, d2 = j0 - ib, d3 = d2 + 1;
            if (d0 <= -32) la[mt] += a.x; else if (d0 >= 32) ha[mt] += a.x;
            if (d1 <= -32) la[mt] += a.y; else if (d1 >= 32) ha[mt] += a.y;
            if (d2 <= -32) lb[mt] += a.z; else if (d2 >= 32) hb[mt] += a.z;
            if (d3 <= -32) lb[mt] += a.w; else if (d3 >= 32) hb[mt] += a.w;
        }
    }
    #pragma unroll
    for (int o = 1; o <= 2; o <<= 1) {
        #pragma unroll
        for (int mt = 0; mt < 2; mt++) {
            sa[mt] += __shfl_xor_sync(0xFFFFFFFFu, sa[mt], o);
            sb2[mt] += __shfl_xor_sync(0xFFFFFFFFu, sb2[mt], o);
            la[mt] += __shfl_xor_sync(0xFFFFFFFFu, la[mt], o);
            lb[mt] += __shfl_xor_sync(0xFFFFFFFFu, lb[mt], o);
            ha[mt] += __shfl_xor_sync(0xFFFFFFFFu, ha[mt], o);
            hb[mt] += __shfl_xor_sync(0xFFFFFFFFu, hb[mt], o);
        }
    }
    if (t == 0) {
        #pragma unroll
        for (int mt = 0; mt < 2; mt++) {
            const int ra = (mt * 16 + g) * 16 + wp, rb = (mt * 16 + g + 8) * 16 + wp;
            psum[ra] = sa[mt]; psum[rb] = sb2[mt];
            plow[ra] = la[mt]; plow[rb] = lb[mt];
            phi[ra]  = ha[mt]; phi[rb]  = hb[mt];
        }
    }
    __syncthreads();
    if (tid < 32) {
        float s = 0.f, l = 0.f, hh = 0.f;
        #pragma unroll
        for (int ww = 0; ww < 16; ww++) {
            s += psum[tid * 16 + ww]; l += plow[tid * 16 + ww]; hh += phi[tid * 16 + ww];
        }
        const float inv = 1.f / s;
        finv[tid] = inv;
        sW[tid * 128 + 0]  = l * inv;
        sW[tid * 128 + 64] = hh * inv;
    }
    __syncthreads();

    #pragma unroll
    for (int mt = 0; mt < 2; mt++) {
        const int ra = mt * 16 + g, rb = ra + 8;
        const int ia = i0 + ra, ib = i0 + rb;
        const float inva = finv[ra], invb = finv[rb];
        __half* rowa = &g_attnh[((size_t)bh * Sq + ia) * Sq];
        __half* rowb2 = &g_attnh[((size_t)bh * Sq + ib) * Sq];
        #pragma unroll
        for (int nt = 0; nt < 8; nt++) {
            const int j0 = wp * 64 + nt * 8 + 2 * t;
            float4& a = acc[mt][nt];
            a.x *= inva; a.y *= inva; a.z *= invb; a.w *= invb;
            *(__half2*)&rowa[j0]  = __floats2half2_rn(a.x, a.y);
            *(__half2*)&rowb2[j0] = __floats2half2_rn(a.z, a.w);
            const int d0 = j0 - ia, d1 = d0 + 1, d2 = j0 - ib, d3 = d2 + 1;
            if (d0 > -32 && d0 < 32) sW[ra * 128 + d0 + 32] = a.x;
            if (d1 > -32 && d1 < 32) sW[ra * 128 + d1 + 32] = a.y;
            if (d2 > -32 && d2 < 32) sW[rb * 128 + d2 + 32] = a.z;
            if (d3 > -32 && d3 < 32) sW[rb * 128 + d3 + 32] = a.w;
        }
    }
    __syncthreads();

    for (int idx = tid; idx < 32 * 128; idx += 512) {
        const int r = idx >> 7, c = idx & 127;
        g_Wh[(size_t)(bh * Sq + i0 + r) * WPAD + c] = __float2half(sW[idx]);
    }
}

// =====================================================================
// FAT kernel: blocks [0,512) run ctx GEMM; blocks [512,2560) run head-mean.
// ctx: attn @ V + W @ rel_v (fp16 mma + ldmatrix/.trans; BM=128,BN=64,BK=64)
// mean: out_attn[b,i,j] = (1/16) sum_h probs  (DRAM-bound, fills idle BW)
// =====================================================================
struct CtxStage { __half As[128][72]; __half Bs[64][72]; };
#define CTX_STAGE_SZ ((int)sizeof(CtxStage))   // 27648
#define CTX_SMEM (3 * CTX_STAGE_SZ)            // 82944
#define CTX_BLOCKS 512                          // 8 x 64
#define MEAN_BLOCKS 2048

__global__ __launch_bounds__(256, 2) void ctxmean_kernel(float* __restrict__ out_attn)
{
    const int tid = threadIdx.x;

    if (blockIdx.x >= CTX_BLOCKS) {
        // ---------------- mean path ----------------
        const int mb = blockIdx.x - CTX_BLOCKS;
        const size_t idx = (size_t)mb * 256 + tid;
        const size_t per_b = (size_t)Sq * Sq / 8;
        const int b = (int)(idx / per_b);
        const size_t rem = idx % per_b;
        const uint4* base = (const uint4*)(g_attnh + (size_t)b * Hh * Sq * Sq) + rem;

        float s[8] = {0.f, 0.f, 0.f, 0.f, 0.f, 0.f, 0.f, 0.f};
        #pragma unroll
        for (int h2 = 0; h2 < Hh; h2++) {
            const uint4 u = base[(size_t)h2 * per_b];
            float2 f;
            f = __half22float2(*(const __half2*)&u.x); s[0] += f.x; s[1] += f.y;
            f = __half22float2(*(const __half2*)&u.y); s[2] += f.x; s[3] += f.y;
            f = __half22float2(*(const __half2*)&u.z); s[4] += f.x; s[5] += f.y;
            f = __half22float2(*(const __half2*)&u.w); s[6] += f.x; s[7] += f.y;
        }
        float* o = &out_attn[(size_t)b * Sq * Sq + rem * 8];
        const float c = 1.0f / Hh;
        *(float4*)&o[0] = make_float4(s[0] * c, s[1] * c, s[2] * c, s[3] * c);
        *(float4*)&o[4] = make_float4(s[4] * c, s[5] * c, s[6] * c, s[7] * c);
        return;
    }

    // ---------------- ctx path ----------------
    extern __shared__ CtxStage cstages[];
    const int bh = blockIdx.x >> 3;
    const int b = bh >> 4, h = bh & 15;
    const int i0 = (blockIdx.x & 7) * 128;
    const int lane = tid & 31, wid = tid >> 5;
    const int g = lane >> 2, t = lane & 3;
    const int wm = (wid >> 2) * 64;
    const int wn = (wid & 3) * 16;

    const uint32_t sb = (uint32_t)__cvta_generic_to_shared(cstages);
    const uint32_t laneA = (uint32_t)(((lane & 7) + ((lane >> 3) & 1) * 8) * 144 + (lane >> 4) * 16);
    const uint32_t laneBt = (uint32_t)(((lane & 7) + ((lane >> 3) & 1) * 8) * 144 + (lane >> 4) * 16);
    const uint32_t warpA  = (uint32_t)(wm * 144) + laneA;
    const uint32_t warpBt = (uint32_t)(18432 + wn * 2) + laneBt;

    auto issue = [&](int kt, int s) {
        CtxStage& st = cstages[s];
        if (kt < 16) {
            const int kb = kt * 64;
            #pragma unroll
            for (int it = 0; it < 4; it++) {
                const int id = it * 256 + tid;
                const int row = id >> 3, seg = id & 7;
                cp16(&st.As[row][seg * 8],
                     &g_attnh[((size_t)bh * Sq + i0 + row) * Sq + kb + seg * 8]);
            }
            #pragma unroll
            for (int it = 0; it < 2; it++) {
                const int id = it * 256 + tid;
                const int vr = id >> 3, vs = id & 7;
                cp16(&st.Bs[vr][vs * 8],
                     &g_Vh[(size_t)(b * Sq + kb + vr) * Dm + h * DK + vs * 8]);
            }
        } else {
            const int kk = (kt - 16) * 64;
            #pragma unroll
            for (int it = 0; it < 4; it++) {
                const int id = it * 256 + tid;
                const int row = id >> 3, seg = id & 7;
                cp16(&st.As[row][seg * 8],
                     &g_Wh[(size_t)(bh * Sq + i0 + row) * WPAD + kk + seg * 8]);
            }
            #pragma unroll
            for (int it = 0; it < 2; it++) {
                const int id = it * 256 + tid;
                const int vr = id >> 3, vs = id & 7;
                cp16(&st.Bs[vr][vs * 8], &g_relvh[(kk + vr) * DK + vs * 8]);
            }
        }
    };

    float4 acc[4][2];
    #pragma unroll
    for (int i = 0; i < 4; i++)
        #pragma unroll
        for (int j = 0; j < 2; j++) acc[i][j] = make_float4(0.f, 0.f, 0.f, 0.f);

    issue(0, 0); CP_COMMIT();
    issue(1, 1); CP_COMMIT();

    int scur = 0, snxt = 2;
    #pragma unroll 1
    for (int kt = 0; kt < 18; kt++) {
        CP_WAIT1();
        __syncthreads();
        if (kt + 2 < 18) issue(kt + 2, snxt);
        CP_COMMIT();

        const uint32_t stb = sb + scur * CTX_STAGE_SZ;
        #pragma unroll
        for (int ks = 0; ks < 4; ks++) {
            uint32_t af[4][4], bf[2][2];
            #pragma unroll
            for (int ma = 0; ma < 4; ma++)
                ldm_x4(af[ma], stb + warpA + ma * 2304 + ks * 32);
            {
                uint32_t bq[4];
                ldm_x4_t(bq, stb + warpBt + ks * 16 * 144);
                bf[0][0] = bq[0]; bf[0][1] = bq[1]; bf[1][0] = bq[2]; bf[1][1] = bq[3];
            }
            #pragma unroll
            for (int ma = 0; ma < 4; ma++)
                #pragma unroll
                for (int na = 0; na < 2; na++)
                    mma16(acc[ma][na], af[ma], bf[na]);
        }
        scur = (scur + 1 == 3) ? 0 : scur + 1;
        snxt = (snxt + 1 == 3) ? 0 : snxt + 1;
    }

    #pragma unroll
    for (int ma = 0; ma < 4; ma++) {
        const int r = i0 + wm + ma * 16 + g;
        #pragma unroll
        for (int na = 0; na < 2; na++) {
            const int c = wn + na * 8 + 2 * t;
            *(__half2*)&g_ctxh[(size_t)(b * Sq + r) * Dm + h * DK + c] =
                __floats2half2_rn(acc[ma][na].x, acc[ma][na].y);
            *(__half2*)&g_ctxh[(size_t)(b * Sq + r + 8) * Dm + h * DK + c] =
                __floats2half2_rn(acc[ma][na].z, acc[ma][na].w);
        }
    }
}

// ---------------- launch ----------------
extern "C" void kernel_launch(void* const* d_in, const int* in_sizes, int n_in,
                              void* d_out, int out_size)
{
    const float* query = (const float*)d_in[0];
    const float* key   = (const float*)d_in[1];
    const float* value = (const float*)d_in[2];
    const float* Wq    = (const float*)d_in[3];
    const float* Wk    = (const float*)d_in[4];
    const float* Wv    = (const float*)d_in[5];
    const float* Wo    = (const float*)d_in[6];
    const float* bo    = (const float*)d_in[7];
    const float* rel_k = (const float*)d_in[8];
    const float* rel_v = (const float*)d_in[9];

    float* out      = (float*)d_out;                 // [B,S,D]
    float* out_attn = out + (size_t)Bb * Sq * Dm;    // [B,S,S]

    static bool attr_set = false;
    if (!attr_set) {
        cudaFuncSetAttribute(proj3h_kernel,
                             cudaFuncAttributeMaxDynamicSharedMemorySize, PROJ_SMEM);
        cudaFuncSetAttribute(outprojh_kernel,
                             cudaFuncAttributeMaxDynamicSharedMemorySize, PROJ_SMEM);
        cudaFuncSetAttribute(ctxmean_kernel,
                             cudaFuncAttributeMaxDynamicSharedMemorySize, CTX_SMEM);
        cudaFuncSetAttribute(scoresmax_kernel,
                             cudaFuncAttributeMaxDynamicSharedMemorySize, SMX_SMEM);
        attr_set = true;
    }

    // 0. prep: fp16 conversions
    cvt_inputs_kernel<<<dim3(Mrows * Dm / 4 / 256, 3), 256>>>(query, key, value);
    cvt_w_kernel<<<dim3(Dm / 32, Dm / 32, 4), 256>>>(Wq, Wk, Wv, Wo);
    cvt_relv_kernel<<<1, 256>>>(rel_v);

    // 1. projections (fp16 mma + ldmatrix, BK=64)
    proj3h_kernel<<<dim3(Dm / 128, Mrows / 128, 3), 256, PROJ_SMEM>>>();

    // 2. rel_k dot products
    relk_kernel<<<dim3(Sq / 128, BH), 128>>>(rel_k);

    // 3. fused scores + softmax (512 thr, 16 warps)
    scoresmax_kernel<<<dim3(Sq / 32, BH), 512, SMX_SMEM>>>();

    // 4+5. FAT kernel: ctx GEMM blocks + head-mean blocks run concurrently
    ctxmean_kernel<<<CTX_BLOCKS + MEAN_BLOCKS, 256, CTX_SMEM>>>(out_attn);

    // 6. output projection + bias (fp16 mma + ldmatrix, BK=64)
    outprojh_kernel<<<dim3(Dm / 128, Mrows / 128), 256, PROJ_SMEM>>>(bo, out);
}

// round 15
// speedup vs baseline: 6.2430x; 1.0048x over previous
#include <cuda_runtime.h>
#include <cuda_fp16.h>
#include <cstdint>
#include <cstddef>

#define Sq 1024
#define Bb 4
#define Dm 1024
#define Hh 16
#define DK 64
#define NR 65
#define WPAD 128
#define BH (Bb*Hh)
#define Mrows (Bb*Sq)

// ---------------- scratch (device globals; no allocation) ----------------
__device__ __align__(128) __half g_attnh[(size_t)BH * Sq * Sq];   // fp16 probs, 128 MB
__device__ __align__(128) __half g_Qh[(size_t)Mrows * Dm];
__device__ __align__(128) __half g_Kh[(size_t)Mrows * Dm];
__device__ __align__(128) __half g_Vh[(size_t)Mrows * Dm];
__device__ __align__(128) __half g_ctxh[(size_t)Mrows * Dm];
__device__ __align__(128) __half g_Xh[(size_t)3 * Mrows * Dm];    // fp16 inputs q,k,v
__device__ __align__(128) __half g_Wth[(size_t)4 * Dm * Dm];      // W^T fp16: q,k,v,o
__device__ __align__(128) __half g_Wh[(size_t)BH * Sq * WPAD];    // bucket sums fp16 (128-wide, zero tail)
__device__ __align__(128) __half g_relvh[128 * DK];               // rel_v fp16, zero-padded to 128 rows
__device__ __align__(128) float  g_Rt[(size_t)BH * NR * Sq];      // rel_k bias, transposed

// ---------------- helpers ----------------
__device__ __forceinline__ void mma16(float4& d, const uint32_t* a, const uint32_t* b) {
    asm volatile("mma.sync.aligned.m16n8k16.row.col.f32.f16.f16.f32 "
                 "{%0,%1,%2,%3},{%4,%5,%6,%7},{%8,%9},{%0,%1,%2,%3};"
                 : "+f"(d.x), "+f"(d.y), "+f"(d.z), "+f"(d.w)
                 : "r"(a[0]), "r"(a[1]), "r"(a[2]), "r"(a[3]), "r"(b[0]), "r"(b[1]));
}
__device__ __forceinline__ void ldm_x4(uint32_t* r, uint32_t a) {
    asm volatile("ldmatrix.sync.aligned.m8n8.x4.shared.b16 {%0,%1,%2,%3}, [%4];"
                 : "=r"(r[0]), "=r"(r[1]), "=r"(r[2]), "=r"(r[3]) : "r"(a));
}
__device__ __forceinline__ void ldm_x4_t(uint32_t* r, uint32_t a) {
    asm volatile("ldmatrix.sync.aligned.m8n8.x4.trans.shared.b16 {%0,%1,%2,%3}, [%4];"
                 : "=r"(r[0]), "=r"(r[1]), "=r"(r[2]), "=r"(r[3]) : "r"(a));
}
__device__ __forceinline__ void cp16(void* dst, const void* src) {
    uint32_t d = (uint32_t)__cvta_generic_to_shared(dst);
    asm volatile("cp.async.cg.shared.global [%0], [%1], 16;" :: "r"(d), "l"(src) : "memory");
}
__device__ __forceinline__ void cp16s(uint32_t dst, const void* src) {
    asm volatile("cp.async.cg.shared.global [%0], [%1], 16;" :: "r"(dst), "l"(src) : "memory");
}
#define CP_COMMIT() asm volatile("cp.async.commit_group;" ::: "memory")
#define CP_WAIT1()  asm volatile("cp.async.wait_group 1;" ::: "memory")
#define CP_WAIT0()  asm volatile("cp.async.wait_group 0;" ::: "memory")

// ---------------- prep kernels ----------------
__global__ __launch_bounds__(256) void cvt_inputs_kernel(
    const float* __restrict__ q, const float* __restrict__ k, const float* __restrict__ v)
{
    const int z = blockIdx.y;
    const float4* s = (const float4*)(z == 0 ? q : z == 1 ? k : v);
    const int idx = blockIdx.x * 256 + threadIdx.x;
    float4 a = s[idx];
    __half2* d = (__half2*)(g_Xh + (size_t)z * Mrows * Dm);
    d[idx * 2]     = __floats2half2_rn(a.x, a.y);
    d[idx * 2 + 1] = __floats2half2_rn(a.z, a.w);
}

__global__ __launch_bounds__(256) void cvt_w_kernel(
    const float* __restrict__ Wq, const float* __restrict__ Wk,
    const float* __restrict__ Wv, const float* __restrict__ Wo)
{
    __shared__ float t[32][33];
    const int z = blockIdx.z;
    const float* W = (z == 0) ? Wq : (z == 1) ? Wk : (z == 2) ? Wv : Wo;
    __half* Wt = g_Wth + (size_t)z * Dm * Dm;
    const int x0 = blockIdx.x * 32, y0 = blockIdx.y * 32;
    const int tx = threadIdx.x & 31, ty = threadIdx.x >> 5;
    #pragma unroll
    for (int i = 0; i < 4; i++)
        t[ty + 8 * i][tx] = W[(size_t)(y0 + ty + 8 * i) * Dm + x0 + tx];
    __syncthreads();
    #pragma unroll
    for (int i = 0; i < 4; i++)
        Wt[(size_t)(x0 + ty + 8 * i) * Dm + y0 + tx] = __float2half(t[tx][ty + 8 * i]);
}

__global__ __launch_bounds__(256) void cvt_relv_kernel(const float* __restrict__ rel_v)
{
    for (int idx = threadIdx.x; idx < 128 * DK; idx += 256) {
        const int row = idx / DK, col = idx % DK;
        g_relvh[idx] = __float2half(row < NR ? rel_v[row * DK + col] : 0.f);
    }
}

// =====================================================================
// fp16 GEMM: C[4096,1024](tile 128x128) = A[m][k] @ Bt[n][k]^T (+bias)
// BM=128, BN=128, BK=64; 3-stage cp.async ring; 8 warps 2x4; warp 64x32
// =====================================================================
struct ProjStage { __half As[128][72]; __half Bs[128][72]; };
#define PROJ_STAGE_SZ ((int)sizeof(ProjStage))   // 36864
#define PROJ_SMEM (3 * PROJ_STAGE_SZ)            // 110592

template<bool HALF_OUT>
__device__ __forceinline__ void gemm_h_body(const __half* __restrict__ A,
                                            const __half* __restrict__ Bt,
                                            const float* __restrict__ bias,
                                            void* __restrict__ Cv)
{
    extern __shared__ ProjStage pstages[];
    const int tid = threadIdx.x, lane = tid & 31, wid = tid >> 5;
    const int g = lane >> 2, t = lane & 3;
    const int wm = (wid >> 2) * 64, wn = (wid & 3) * 32;
    const int row0 = blockIdx.y * 128, col0 = blockIdx.x * 128;

    const uint32_t sb = (uint32_t)__cvta_generic_to_shared(pstages);
    const uint32_t laneA = (uint32_t)(((lane & 7) + ((lane >> 3) & 1) * 8) * 144 + (lane >> 4) * 16);
    const uint32_t laneB = (uint32_t)((lane & 7) * 144 + ((lane >> 3) & 1) * 16 + (lane >> 4) * 1152);
    const uint32_t warpA = (uint32_t)(wm * 144) + laneA;
    const uint32_t warpB = (uint32_t)(18432 + wn * 144) + laneB;

    auto issue = [&](int kt, int s) {
        ProjStage& st = pstages[s];
        const int kb = kt * 64;
        #pragma unroll
        for (int it = 0; it < 4; it++) {
            const int id = it * 256 + tid;
            const int row = id >> 3, seg = id & 7;
            cp16(&st.As[row][seg * 8], &A[(size_t)(row0 + row) * 1024 + kb + seg * 8]);
            cp16(&st.Bs[row][seg * 8], &Bt[(size_t)(col0 + row) * 1024 + kb + seg * 8]);
        }
    };

    float4 acc[4][4];
    #pragma unroll
    for (int i = 0; i < 4; i++)
        #pragma unroll
        for (int j = 0; j < 4; j++) acc[i][j] = make_float4(0.f, 0.f, 0.f, 0.f);

    issue(0, 0); CP_COMMIT();
    issue(1, 1); CP_COMMIT();

    int scur = 0, snxt = 2;
    #pragma unroll 1
    for (int kt = 0; kt < 16; kt++) {
        CP_WAIT1();
        __syncthreads();
        if (kt + 2 < 16) issue(kt + 2, snxt);
        CP_COMMIT();

        const uint32_t stb = sb + scur * PROJ_STAGE_SZ;
        #pragma unroll
        for (int ks = 0; ks < 4; ks++) {
            const uint32_t k0b = ks * 32;
            uint32_t af[4][4], bf[4][2];
            #pragma unroll
            for (int ma = 0; ma < 4; ma++)
                ldm_x4(af[ma], stb + warpA + ma * 2304 + k0b);
            #pragma unroll
            for (int p = 0; p < 2; p++) {
                uint32_t bq[4];
                ldm_x4(bq, stb + warpB + p * 2304 + k0b);
                bf[2 * p][0] = bq[0]; bf[2 * p][1] = bq[1];
                bf[2 * p + 1][0] = bq[2]; bf[2 * p + 1][1] = bq[3];
            }
            #pragma unroll
            for (int ma = 0; ma < 4; ma++)
                #pragma unroll
                for (int na = 0; na < 4; na++)
                    mma16(acc[ma][na], af[ma], bf[na]);
        }
        scur = (scur + 1 == 3) ? 0 : scur + 1;
        snxt = (snxt + 1 == 3) ? 0 : snxt + 1;
    }

    #pragma unroll
    for (int ma = 0; ma < 4; ma++) {
        const int r = row0 + wm + ma * 16 + g;
        #pragma unroll
        for (int na = 0; na < 4; na++) {
            const int c = col0 + wn + na * 8 + 2 * t;
            if (HALF_OUT) {
                __half* Ch = (__half*)Cv;
                *(__half2*)&Ch[(size_t)r * 1024 + c]       = __floats2half2_rn(acc[ma][na].x, acc[ma][na].y);
                *(__half2*)&Ch[(size_t)(r + 8) * 1024 + c] = __floats2half2_rn(acc[ma][na].z, acc[ma][na].w);
            } else {
                float* Cf = (float*)Cv;
                const float bx = bias[c], by = bias[c + 1];
                *(float2*)&Cf[(size_t)r * 1024 + c]       = make_float2(acc[ma][na].x + bx, acc[ma][na].y + by);
                *(float2*)&Cf[(size_t)(r + 8) * 1024 + c] = make_float2(acc[ma][na].z + bx, acc[ma][na].w + by);
            }
        }
    }
}

__global__ __launch_bounds__(256, 2) void proj3h_kernel()
{
    const int z = blockIdx.z;
    const __half* A = g_Xh + (size_t)z * Mrows * Dm;
    const __half* Bt = g_Wth + (size_t)z * Dm * Dm;
    __half* C = (z == 0) ? g_Qh : (z == 1) ? g_Kh : g_Vh;
    gemm_h_body<true>(A, Bt, nullptr, C);
}

__global__ __launch_bounds__(256, 2) void outprojh_kernel(
    const float* __restrict__ bo, float* __restrict__ out)
{
    gemm_h_body<false>(g_ctxh, g_Wth + (size_t)3 * Dm * Dm, bo, out);
}

// =====================================================================
// relk: Rt[bh][r][i] = dot(Q[b,i,h*64:], rel_k[r,:])
// =====================================================================
__global__ __launch_bounds__(128) void relk_kernel(const float* __restrict__ rel_k)
{
    __shared__ float4 RK[NR][16];
    const int bh = blockIdx.y;
    const int b = bh >> 4, h = bh & 15;
    const int i0 = blockIdx.x * 128;
    const int tid = threadIdx.x;

    for (int idx = tid; idx < NR * 16; idx += 128)
        RK[idx / 16][idx % 16] = ((const float4*)rel_k)[idx];
    __syncthreads();

    float2 q[32];
    const __half2* qrow = (const __half2*)&g_Qh[(size_t)(b * Sq + i0 + tid) * Dm + h * DK];
    #pragma unroll
    for (int d = 0; d < 32; d++) q[d] = __half22float2(qrow[d]);

    float* outp = &g_Rt[(size_t)bh * NR * Sq + i0 + tid];
    #pragma unroll 1
    for (int r = 0; r < NR; r++) {
        float s = 0.f;
        #pragma unroll
        for (int d = 0; d < 16; d++) {
            float4 rk = RK[r][d];
            s += q[2 * d].x * rk.x + q[2 * d].y * rk.y + q[2 * d + 1].x * rk.z + q[2 * d + 1].y * rk.w;
        }
        outp[(size_t)r * Sq] = s;
    }
}

// =====================================================================
// FUSED scores+softmax: logits live in registers only.
// Block = 32 query rows x 1 head x all 1024 keys. 512 threads (16 warps).
// =====================================================================
#define SMX_K    0
#define SMX_Q    131072
#define SMX_PMAX 135168
#define SMX_PSUM 137216
#define SMX_PLOW 139264
#define SMX_PHI  141312
#define SMX_FMAX 143360
#define SMX_FINV 143488
#define SMX_SW   143616
#define SMX_SMEM 160000

__global__ __launch_bounds__(512, 1) void scoresmax_kernel()
{
    extern __shared__ char smx[];
    float* pmax = (float*)(smx + SMX_PMAX);
    float* psum = (float*)(smx + SMX_PSUM);
    float* plow = (float*)(smx + SMX_PLOW);
    float* phi  = (float*)(smx + SMX_PHI);
    float* fmax = (float*)(smx + SMX_FMAX);
    float* finv = (float*)(smx + SMX_FINV);
    float* sW   = (float*)(smx + SMX_SW);

    const int bh = blockIdx.y;
    const int b = bh >> 4, h = bh & 15;
    const int i0 = blockIdx.x * 32;
    const int tid = threadIdx.x;
    const int lane = tid & 31, wp = tid >> 5;
    const int g = lane >> 2, t = lane & 3;

    const uint32_t sbK = (uint32_t)__cvta_generic_to_shared(smx + SMX_K);
    const uint32_t sbQ = (uint32_t)__cvta_generic_to_shared(smx + SMX_Q);

    for (int idx = tid; idx < 32 * 128; idx += 512) sW[idx] = 0.f;

    for (int id = tid; id < 8192; id += 512) {
        const int row = id >> 3, seg = id & 7;
        const uint32_t dst = sbK + row * 128 + ((seg * 16) ^ ((row & 7) << 4));
        cp16s(dst, &g_Kh[(size_t)(b * Sq + row) * Dm + h * DK + seg * 8]);
    }
    if (tid < 256) {
        const int row = tid >> 3, seg = tid & 7;
        const uint32_t dst = sbQ + row * 128 + ((seg * 16) ^ ((row & 7) << 4));
        cp16s(dst, &g_Qh[(size_t)(b * Sq + i0 + row) * Dm + h * DK + seg * 8]);
    }
    CP_COMMIT(); CP_WAIT0();
    __syncthreads();

    float4 acc[2][8];
    #pragma unroll
    for (int mt = 0; mt < 2; mt++)
        #pragma unroll
        for (int nt = 0; nt < 8; nt++) acc[mt][nt] = make_float4(0.f, 0.f, 0.f, 0.f);

    const int arow = (lane & 7) + ((lane >> 3) & 1) * 8;
    const int acolsel = (lane >> 4) * 16;
    const int brow7 = lane & 7;
    const int brow = (lane & 7) + ((lane >> 4) << 3);
    const int bcolsel = ((lane >> 3) & 1) * 16;

    #pragma unroll
    for (int ks = 0; ks < 4; ks++) {
        const int kb2 = ks * 32;
        uint32_t af[2][4];
        #pragma unroll
        for (int mt = 0; mt < 2; mt++) {
            const int row = mt * 16 + arow;
            const uint32_t col = (uint32_t)((kb2 + acolsel) ^ ((arow & 7) << 4));
            ldm_x4(af[mt], sbQ + row * 128 + col);
        }
        #pragma unroll
        for (int nt2 = 0; nt2 < 4; nt2++) {
            const int n0 = wp * 64 + nt2 * 16;
            const uint32_t colb = (uint32_t)((kb2 + bcolsel) ^ (brow7 << 4));
            uint32_t bq[4];
            ldm_x4(bq, sbK + (n0 + brow) * 128 + colb);
            uint32_t bf0[2] = { bq[0], bq[1] }, bf1[2] = { bq[2], bq[3] };
            #pragma unroll
            for (int mt = 0; mt < 2; mt++) {
                mma16(acc[mt][2 * nt2],     af[mt], bf0);
                mma16(acc[mt][2 * nt2 + 1], af[mt], bf1);
            }
        }
    }

    const float* RtB = &g_Rt[(size_t)bh * NR * Sq];
    float mxa[2] = { -1e30f, -1e30f }, mxb[2] = { -1e30f, -1e30f };
    #pragma unroll
    for (int mt = 0; mt < 2; mt++) {
        const int ia = i0 + mt * 16 + g, ib = ia + 8;
        #pragma unroll
        for (int nt = 0; nt < 8; nt++) {
            const int j0 = wp * 64 + nt * 8 + 2 * t;
            float4& a = acc[mt][nt];
            int r0 = j0 - ia;     r0 = (r0 < -32 ? -32 : (r0 > 32 ? 32 : r0)) + 32;
            int r1 = j0 + 1 - ia; r1 = (r1 < -32 ? -32 : (r1 > 32 ? 32 : r1)) + 32;
            int r2 = j0 - ib;     r2 = (r2 < -32 ? -32 : (r2 > 32 ? 32 : r2)) + 32;
            int r3 = j0 + 1 - ib; r3 = (r3 < -32 ? -32 : (r3 > 32 ? 32 : r3)) + 32;
            a.x = a.x * 0.125f + RtB[(size_t)r0 * Sq + ia];
            a.y = a.y * 0.125f + RtB[(size_t)r1 * Sq + ia];
            a.z = a.z * 0.125f + RtB[(size_t)r2 * Sq + ib];
            a.w = a.w * 0.125f + RtB[(size_t)r3 * Sq + ib];
            mxa[mt] = fmaxf(mxa[mt], fmaxf(a.x, a.y));
            mxb[mt] = fmaxf(mxb[mt], fmaxf(a.z, a.w));
        }
    }
    #pragma unroll
    for (int o = 1; o <= 2; o <<= 1) {
        #pragma unroll
        for (int mt = 0; mt < 2; mt++) {
            mxa[mt] = fmaxf(mxa[mt], __shfl_xor_sync(0xFFFFFFFFu, mxa[mt], o));
            mxb[mt] = fmaxf(mxb[mt], __shfl_xor_sync(0xFFFFFFFFu, mxb[mt], o));
        }
    }
    if (t == 0) {
        #pragma unroll
        for (int mt = 0; mt < 2; mt++) {
            pmax[(mt * 16 + g) * 16 + wp]     = mxa[mt];
            pmax[(mt * 16 + g + 8) * 16 + wp] = mxb[mt];
        }
    }
    __syncthreads();
    if (tid < 32) {
        float m = -1e30f;
        #pragma unroll
        for (int ww = 0; ww < 16; ww++) m = fmaxf(m, pmax[tid * 16 + ww]);
        fmax[tid] = m;
    }
    __syncthreads();

    float sa[2] = {0.f, 0.f}, sb2[2] = {0.f, 0.f};
    float la[2] = {0.f, 0.f}, lb[2] = {0.f, 0.f};
    float ha[2] = {0.f, 0.f}, hb[2] = {0.f, 0.f};
    #pragma unroll
    for (int mt = 0; mt < 2; mt++) {
        const float ma2 = fmax[mt * 16 + g], mb2 = fmax[mt * 16 + g + 8];
        const int ia = i0 + mt * 16 + g, ib = ia + 8;
        #pragma unroll
        for (int nt = 0; nt < 8; nt++) {
            const int j0 = wp * 64 + nt * 8 + 2 * t;
            float4& a = acc[mt][nt];
            a.x = __expf(a.x - ma2); a.y = __expf(a.y - ma2);
            a.z = __expf(a.z - mb2); a.w = __expf(a.w - mb2);
            sa[mt] += a.x + a.y; sb2[mt] += a.z + a.w;
            const int d0 = j0 - ia, d1 = d0 + 1, d2 = j0 - ib, d3 = d2 + 1;
            if (d0 <= -32) la[mt] += a.x; else if (d0 >= 32) ha[mt] += a.x;
            if (d1 <= -32) la[mt] += a.y; else if (d1 >= 32) ha[mt] += a.y;
            if (d2 <= -32) lb[mt] += a.z; else if (d2 >= 32) hb[mt] += a.z;
            if (d3 <= -32) lb[mt] += a.w; else if (d3 >= 32) hb[mt] += a.w;
        }
    }
    #pragma unroll
    for (int o = 1; o <= 2; o <<= 1) {
        #pragma unroll
        for (int mt = 0; mt < 2; mt++) {
            sa[mt] += __shfl_xor_sync(0xFFFFFFFFu, sa[mt], o);
            sb2[mt] += __shfl_xor_sync(0xFFFFFFFFu, sb2[mt], o);
            la[mt] += __shfl_xor_sync(0xFFFFFFFFu, la[mt], o);
            lb[mt] += __shfl_xor_sync(0xFFFFFFFFu, lb[mt], o);
            ha[mt] += __shfl_xor_sync(0xFFFFFFFFu, ha[mt], o);
            hb[mt] += __shfl_xor_sync(0xFFFFFFFFu, hb[mt], o);
        }
    }
    if (t == 0) {
        #pragma unroll
        for (int mt = 0; mt < 2; mt++) {
            const int ra = (mt * 16 + g) * 16 + wp, rb = (mt * 16 + g + 8) * 16 + wp;
            psum[ra] = sa[mt]; psum[rb] = sb2[mt];
            plow[ra] = la[mt]; plow[rb] = lb[mt];
            phi[ra]  = ha[mt]; phi[rb]  = hb[mt];
        }
    }
    __syncthreads();
    if (tid < 32) {
        float s = 0.f, l = 0.f, hh = 0.f;
        #pragma unroll
        for (int ww = 0; ww < 16; ww++) {
            s += psum[tid * 16 + ww]; l += plow[tid * 16 + ww]; hh += phi[tid * 16 + ww];
        }
        const float inv = 1.f / s;
        finv[tid] = inv;
        sW[tid * 128 + 0]  = l * inv;
        sW[tid * 128 + 64] = hh * inv;
    }
    __syncthreads();

    #pragma unroll
    for (int mt = 0; mt < 2; mt++) {
        const int ra = mt * 16 + g, rb = ra + 8;
        const int ia = i0 + ra, ib = i0 + rb;
        const float inva = finv[ra], invb = finv[rb];
        __half* rowa = &g_attnh[((size_t)bh * Sq + ia) * Sq];
        __half* rowb2 = &g_attnh[((size_t)bh * Sq + ib) * Sq];
        #pragma unroll
        for (int nt = 0; nt < 8; nt++) {
            const int j0 = wp * 64 + nt * 8 + 2 * t;
            float4& a = acc[mt][nt];
            a.x *= inva; a.y *= inva; a.z *= invb; a.w *= invb;
            *(__half2*)&rowa[j0]  = __floats2half2_rn(a.x, a.y);
            *(__half2*)&rowb2[j0] = __floats2half2_rn(a.z, a.w);
            const int d0 = j0 - ia, d1 = d0 + 1, d2 = j0 - ib, d3 = d2 + 1;
            if (d0 > -32 && d0 < 32) sW[ra * 128 + d0 + 32] = a.x;
            if (d1 > -32 && d1 < 32) sW[ra * 128 + d1 + 32] = a.y;
            if (d2 > -32 && d2 < 32) sW[rb * 128 + d2 + 32] = a.z;
            if (d3 > -32 && d3 < 32) sW[rb * 128 + d3 + 32] = a.w;
        }
    }
    __syncthreads();

    for (int idx = tid; idx < 32 * 128; idx += 512) {
        const int r = idx >> 7, c = idx & 127;
        g_Wh[(size_t)(bh * Sq + i0 + r) * WPAD + c] = __float2half(sW[idx]);
    }
}

// =====================================================================
// FAT kernel: blocks [0,512) run ctx GEMM; blocks [512,2560) run head-mean.
// ctx: attn @ V + W @ rel_v (fp16 mma + ldmatrix/.trans; BM=128,BN=64,BK=64)
// mean: out_attn[b,i,j] = (1/16) sum_h probs  (DRAM-bound, fills idle BW)
// =====================================================================
struct CtxStage { __half As[128][72]; __half Bs[64][72]; };
#define CTX_STAGE_SZ ((int)sizeof(CtxStage))   // 27648
#define CTX_SMEM (3 * CTX_STAGE_SZ)            // 82944
#define CTX_BLOCKS 512                          // 8 x 64
#define MEAN_BLOCKS 2048

__global__ __launch_bounds__(256, 2) void ctxmean_kernel(float* __restrict__ out_attn)
{
    const int tid = threadIdx.x;

    if (blockIdx.x >= CTX_BLOCKS) {
        // ---------------- mean path ----------------
        const int mb = blockIdx.x - CTX_BLOCKS;
        const size_t idx = (size_t)mb * 256 + tid;
        const size_t per_b = (size_t)Sq * Sq / 8;
        const int b = (int)(idx / per_b);
        const size_t rem = idx % per_b;
        const uint4* base = (const uint4*)(g_attnh + (size_t)b * Hh * Sq * Sq) + rem;

        float s[8] = {0.f, 0.f, 0.f, 0.f, 0.f, 0.f, 0.f, 0.f};
        #pragma unroll
        for (int h2 = 0; h2 < Hh; h2++) {
            const uint4 u = base[(size_t)h2 * per_b];
            float2 f;
            f = __half22float2(*(const __half2*)&u.x); s[0] += f.x; s[1] += f.y;
            f = __half22float2(*(const __half2*)&u.y); s[2] += f.x; s[3] += f.y;
            f = __half22float2(*(const __half2*)&u.z); s[4] += f.x; s[5] += f.y;
            f = __half22float2(*(const __half2*)&u.w); s[6] += f.x; s[7] += f.y;
        }
        float* o = &out_attn[(size_t)b * Sq * Sq + rem * 8];
        const float c = 1.0f / Hh;
        *(float4*)&o[0] = make_float4(s[0] * c, s[1] * c, s[2] * c, s[3] * c);
        *(float4*)&o[4] = make_float4(s[4] * c, s[5] * c, s[6] * c, s[7] * c);
        return;
    }

    // ---------------- ctx path ----------------
    extern __shared__ CtxStage cstages[];
    const int bh = blockIdx.x >> 3;
    const int b = bh >> 4, h = bh & 15;
    const int i0 = (blockIdx.x & 7) * 128;
    const int lane = tid & 31, wid = tid >> 5;
    const int g = lane >> 2, t = lane & 3;
    const int wm = (wid >> 2) * 64;
    const int wn = (wid & 3) * 16;

    const uint32_t sb = (uint32_t)__cvta_generic_to_shared(cstages);
    const uint32_t laneA = (uint32_t)(((lane & 7) + ((lane >> 3) & 1) * 8) * 144 + (lane >> 4) * 16);
    const uint32_t laneBt = (uint32_t)(((lane & 7) + ((lane >> 3) & 1) * 8) * 144 + (lane >> 4) * 16);
    const uint32_t warpA  = (uint32_t)(wm * 144) + laneA;
    const uint32_t warpBt = (uint32_t)(18432 + wn * 2) + laneBt;

    auto issue = [&](int kt, int s) {
        CtxStage& st = cstages[s];
        if (kt < 16) {
            const int kb = kt * 64;
            #pragma unroll
            for (int it = 0; it < 4; it++) {
                const int id = it * 256 + tid;
                const int row = id >> 3, seg = id & 7;
                cp16(&st.As[row][seg * 8],
                     &g_attnh[((size_t)bh * Sq + i0 + row) * Sq + kb + seg * 8]);
            }
            #pragma unroll
            for (int it = 0; it < 2; it++) {
                const int id = it * 256 + tid;
                const int vr = id >> 3, vs = id & 7;
                cp16(&st.Bs[vr][vs * 8],
                     &g_Vh[(size_t)(b * Sq + kb + vr) * Dm + h * DK + vs * 8]);
            }
        } else {
            const int kk = (kt - 16) * 64;
            #pragma unroll
            for (int it = 0; it < 4; it++) {
                const int id = it * 256 + tid;
                const int row = id >> 3, seg = id & 7;
                cp16(&st.As[row][seg * 8],
                     &g_Wh[(size_t)(bh * Sq + i0 + row) * WPAD + kk + seg * 8]);
            }
            #pragma unroll
            for (int it = 0; it < 2; it++) {
                const int id = it * 256 + tid;
                const int vr = id >> 3, vs = id & 7;
                cp16(&st.Bs[vr][vs * 8], &g_relvh[(kk + vr) * DK + vs * 8]);
            }
        }
    };

    float4 acc[4][2];
    #pragma unroll
    for (int i = 0; i < 4; i++)
        #pragma unroll
        for (int j = 0; j < 2; j++) acc[i][j] = make_float4(0.f, 0.f, 0.f, 0.f);

    issue(0, 0); CP_COMMIT();
    issue(1, 1); CP_COMMIT();

    int scur = 0, snxt = 2;
    #pragma unroll 1
    for (int kt = 0; kt < 18; kt++) {
        CP_WAIT1();
        __syncthreads();
        if (kt + 2 < 18) issue(kt + 2, snxt);
        CP_COMMIT();

        const uint32_t stb = sb + scur * CTX_STAGE_SZ;
        #pragma unroll
        for (int ks = 0; ks < 4; ks++) {
            uint32_t af[4][4], bf[2][2];
            #pragma unroll
            for (int ma = 0; ma < 4; ma++)
                ldm_x4(af[ma], stb + warpA + ma * 2304 + ks * 32);
            {
                uint32_t bq[4];
                ldm_x4_t(bq, stb + warpBt + ks * 16 * 144);
                bf[0][0] = bq[0]; bf[0][1] = bq[1]; bf[1][0] = bq[2]; bf[1][1] = bq[3];
            }
            #pragma unroll
            for (int ma = 0; ma < 4; ma++)
                #pragma unroll
                for (int na = 0; na < 2; na++)
                    mma16(acc[ma][na], af[ma], bf[na]);
        }
        scur = (scur + 1 == 3) ? 0 : scur + 1;
        snxt = (snxt + 1 == 3) ? 0 : snxt + 1;
    }

    #pragma unroll
    for (int ma = 0; ma < 4; ma++) {
        const int r = i0 + wm + ma * 16 + g;
        #pragma unroll
        for (int na = 0; na < 2; na++) {
            const int c = wn + na * 8 + 2 * t;
            *(__half2*)&g_ctxh[(size_t)(b * Sq + r) * Dm + h * DK + c] =
                __floats2half2_rn(acc[ma][na].x, acc[ma][na].y);
            *(__half2*)&g_ctxh[(size_t)(b * Sq + r + 8) * Dm + h * DK + c] =
                __floats2half2_rn(acc[ma][na].z, acc[ma][na].w);
        }
    }
}

// ---------------- launch ----------------
extern "C" void kernel_launch(void* const* d_in, const int* in_sizes, int n_in,
                              void* d_out, int out_size)
{
    const float* query = (const float*)d_in[0];
    const float* key   = (const float*)d_in[1];
    const float* value = (const float*)d_in[2];
    const float* Wq    = (const float*)d_in[3];
    const float* Wk    = (const float*)d_in[4];
    const float* Wv    = (const float*)d_in[5];
    const float* Wo    = (const float*)d_in[6];
    const float* bo    = (const float*)d_in[7];
    const float* rel_k = (const float*)d_in[8];
    const float* rel_v = (const float*)d_in[9];

    float* out      = (float*)d_out;                 // [B,S,D]
    float* out_attn = out + (size_t)Bb * Sq * Dm;    // [B,S,S]

    static bool attr_set = false;
    if (!attr_set) {
        cudaFuncSetAttribute(proj3h_kernel,
                             cudaFuncAttributeMaxDynamicSharedMemorySize, PROJ_SMEM);
        cudaFuncSetAttribute(outprojh_kernel,
                             cudaFuncAttributeMaxDynamicSharedMemorySize, PROJ_SMEM);
        cudaFuncSetAttribute(ctxmean_kernel,
                             cudaFuncAttributeMaxDynamicSharedMemorySize, CTX_SMEM);
        cudaFuncSetAttribute(scoresmax_kernel,
                             cudaFuncAttributeMaxDynamicSharedMemorySize, SMX_SMEM);
        attr_set = true;
    }

    // 0. prep: fp16 conversions
    cvt_inputs_kernel<<<dim3(Mrows * Dm / 4 / 256, 3), 256>>>(query, key, value);
    cvt_w_kernel<<<dim3(Dm / 32, Dm / 32, 4), 256>>>(Wq, Wk, Wv, Wo);
    cvt_relv_kernel<<<1, 256>>>(rel_v);

    // 1. projections (fp16 mma + ldmatrix, BK=64)
    proj3h_kernel<<<dim3(Dm / 128, Mrows / 128, 3), 256, PROJ_SMEM>>>();

    // 2. rel_k dot products
    relk_kernel<<<dim3(Sq / 128, BH), 128>>>(rel_k);

    // 3. fused scores + softmax (512 thr, 16 warps)
    scoresmax_kernel<<<dim3(Sq / 32, BH), 512, SMX_SMEM>>>();

    // 4+5. FAT kernel: ctx GEMM blocks + head-mean blocks run concurrently
    ctxmean_kernel<<<CTX_BLOCKS + MEAN_BLOCKS, 256, CTX_SMEM>>>(out_attn);

    // 6. output projection + bias (fp16 mma + ldmatrix, BK=64)
    outprojh_kernel<<<dim3(Dm / 128, Mrows / 128), 256, PROJ_SMEM>>>(bo, out);
}

// round 17
// speedup vs baseline: 6.4038x; 1.0258x over previous
#include <cuda_runtime.h>
#include <cuda_fp16.h>
#include <cstdint>
#include <cstddef>

#define Sq 1024
#define Bb 4
#define Dm 1024
#define Hh 16
#define DK 64
#define NR 65
#define WPAD 128
#define BH (Bb*Hh)
#define Mrows (Bb*Sq)

// ---------------- scratch (device globals; no allocation) ----------------
__device__ __align__(128) __half g_attnh[(size_t)BH * Sq * Sq];   // fp16 probs, 128 MB
__device__ __align__(128) __half g_Qh[(size_t)Mrows * Dm];
__device__ __align__(128) __half g_Kh[(size_t)Mrows * Dm];
__device__ __align__(128) __half g_Vh[(size_t)Mrows * Dm];
__device__ __align__(128) __half g_ctxh[(size_t)Mrows * Dm];
__device__ __align__(128) __half g_Xh[(size_t)3 * Mrows * Dm];    // fp16 inputs q,k,v
__device__ __align__(128) __half g_Wth[(size_t)4 * Dm * Dm];      // W^T fp16: q,k,v,o
__device__ __align__(128) __half g_Wh[(size_t)BH * Sq * WPAD];    // bucket sums fp16 (128-wide, zero tail)
__device__ __align__(128) __half g_relvh[128 * DK];               // rel_v fp16, zero-padded to 128 rows
__device__ __align__(128) float  g_Rt[(size_t)BH * NR * Sq];      // rel_k bias, transposed

// ---------------- helpers ----------------
__device__ __forceinline__ void mma16(float4& d, const uint32_t* a, const uint32_t* b) {
    asm volatile("mma.sync.aligned.m16n8k16.row.col.f32.f16.f16.f32 "
                 "{%0,%1,%2,%3},{%4,%5,%6,%7},{%8,%9},{%0,%1,%2,%3};"
                 : "+f"(d.x), "+f"(d.y), "+f"(d.z), "+f"(d.w)
                 : "r"(a[0]), "r"(a[1]), "r"(a[2]), "r"(a[3]), "r"(b[0]), "r"(b[1]));
}
__device__ __forceinline__ void ldm_x4(uint32_t* r, uint32_t a) {
    asm volatile("ldmatrix.sync.aligned.m8n8.x4.shared.b16 {%0,%1,%2,%3}, [%4];"
                 : "=r"(r[0]), "=r"(r[1]), "=r"(r[2]), "=r"(r[3]) : "r"(a));
}
__device__ __forceinline__ void ldm_x4_t(uint32_t* r, uint32_t a) {
    asm volatile("ldmatrix.sync.aligned.m8n8.x4.trans.shared.b16 {%0,%1,%2,%3}, [%4];"
                 : "=r"(r[0]), "=r"(r[1]), "=r"(r[2]), "=r"(r[3]) : "r"(a));
}
__device__ __forceinline__ void cp16(void* dst, const void* src) {
    uint32_t d = (uint32_t)__cvta_generic_to_shared(dst);
    asm volatile("cp.async.cg.shared.global [%0], [%1], 16;" :: "r"(d), "l"(src) : "memory");
}
__device__ __forceinline__ void cp16s(uint32_t dst, const void* src) {
    asm volatile("cp.async.cg.shared.global [%0], [%1], 16;" :: "r"(dst), "l"(src) : "memory");
}
#define CP_COMMIT() asm volatile("cp.async.commit_group;" ::: "memory")
#define CP_WAIT1()  asm volatile("cp.async.wait_group 1;" ::: "memory")
#define CP_WAIT0()  asm volatile("cp.async.wait_group 0;" ::: "memory")

// ---------------- prep kernels ----------------
__global__ __launch_bounds__(256) void cvt_inputs_kernel(
    const float* __restrict__ q, const float* __restrict__ k, const float* __restrict__ v)
{
    const int z = blockIdx.y;
    const float4* s = (const float4*)(z == 0 ? q : z == 1 ? k : v);
    const int idx = blockIdx.x * 256 + threadIdx.x;
    float4 a = s[idx];
    __half2* d = (__half2*)(g_Xh + (size_t)z * Mrows * Dm);
    d[idx * 2]     = __floats2half2_rn(a.x, a.y);
    d[idx * 2 + 1] = __floats2half2_rn(a.z, a.w);
}

__global__ __launch_bounds__(256) void cvt_w_kernel(
    const float* __restrict__ Wq, const float* __restrict__ Wk,
    const float* __restrict__ Wv, const float* __restrict__ Wo)
{
    __shared__ float t[32][33];
    const int z = blockIdx.z;
    const float* W = (z == 0) ? Wq : (z == 1) ? Wk : (z == 2) ? Wv : Wo;
    __half* Wt = g_Wth + (size_t)z * Dm * Dm;
    const int x0 = blockIdx.x * 32, y0 = blockIdx.y * 32;
    const int tx = threadIdx.x & 31, ty = threadIdx.x >> 5;
    #pragma unroll
    for (int i = 0; i < 4; i++)
        t[ty + 8 * i][tx] = W[(size_t)(y0 + ty + 8 * i) * Dm + x0 + tx];
    __syncthreads();
    #pragma unroll
    for (int i = 0; i < 4; i++)
        Wt[(size_t)(x0 + ty + 8 * i) * Dm + y0 + tx] = __float2half(t[tx][ty + 8 * i]);
}

__global__ __launch_bounds__(256) void cvt_relv_kernel(const float* __restrict__ rel_v)
{
    for (int idx = threadIdx.x; idx < 128 * DK; idx += 256) {
        const int row = idx / DK, col = idx % DK;
        g_relvh[idx] = __float2half(row < NR ? rel_v[row * DK + col] : 0.f);
    }
}

// =====================================================================
// fp16 GEMM: C[4096,1024](tile 128x128) = A[m][k] @ Bt[n][k]^T (+bias)
// BM=128, BN=128, BK=64; 3-stage cp.async ring; 8 warps 2x4; warp 64x32
// =====================================================================
struct ProjStage { __half As[128][72]; __half Bs[128][72]; };
#define PROJ_STAGE_SZ ((int)sizeof(ProjStage))   // 36864
#define PROJ_SMEM (3 * PROJ_STAGE_SZ)            // 110592

template<bool HALF_OUT>
__device__ __forceinline__ void gemm_h_body(const __half* __restrict__ A,
                                            const __half* __restrict__ Bt,
                                            const float* __restrict__ bias,
                                            void* __restrict__ Cv)
{
    extern __shared__ ProjStage pstages[];
    const int tid = threadIdx.x, lane = tid & 31, wid = tid >> 5;
    const int g = lane >> 2, t = lane & 3;
    const int wm = (wid >> 2) * 64, wn = (wid & 3) * 32;
    const int row0 = blockIdx.y * 128, col0 = blockIdx.x * 128;

    const uint32_t sb = (uint32_t)__cvta_generic_to_shared(pstages);
    const uint32_t laneA = (uint32_t)(((lane & 7) + ((lane >> 3) & 1) * 8) * 144 + (lane >> 4) * 16);
    const uint32_t laneB = (uint32_t)((lane & 7) * 144 + ((lane >> 3) & 1) * 16 + (lane >> 4) * 1152);
    const uint32_t warpA = (uint32_t)(wm * 144) + laneA;
    const uint32_t warpB = (uint32_t)(18432 + wn * 144) + laneB;

    auto issue = [&](int kt, int s) {
        ProjStage& st = pstages[s];
        const int kb = kt * 64;
        #pragma unroll
        for (int it = 0; it < 4; it++) {
            const int id = it * 256 + tid;
            const int row = id >> 3, seg = id & 7;
            cp16(&st.As[row][seg * 8], &A[(size_t)(row0 + row) * 1024 + kb + seg * 8]);
            cp16(&st.Bs[row][seg * 8], &Bt[(size_t)(col0 + row) * 1024 + kb + seg * 8]);
        }
    };

    float4 acc[4][4];
    #pragma unroll
    for (int i = 0; i < 4; i++)
        #pragma unroll
        for (int j = 0; j < 4; j++) acc[i][j] = make_float4(0.f, 0.f, 0.f, 0.f);

    issue(0, 0); CP_COMMIT();
    issue(1, 1); CP_COMMIT();

    int scur = 0, snxt = 2;
    #pragma unroll 1
    for (int kt = 0; kt < 16; kt++) {
        CP_WAIT1();
        __syncthreads();
        if (kt + 2 < 16) issue(kt + 2, snxt);
        CP_COMMIT();

        const uint32_t stb = sb + scur * PROJ_STAGE_SZ;
        #pragma unroll
        for (int ks = 0; ks < 4; ks++) {
            const uint32_t k0b = ks * 32;
            uint32_t af[4][4], bf[4][2];
            #pragma unroll
            for (int ma = 0; ma < 4; ma++)
                ldm_x4(af[ma], stb + warpA + ma * 2304 + k0b);
            #pragma unroll
            for (int p = 0; p < 2; p++) {
                uint32_t bq[4];
                ldm_x4(bq, stb + warpB + p * 2304 + k0b);
                bf[2 * p][0] = bq[0]; bf[2 * p][1] = bq[1];
                bf[2 * p + 1][0] = bq[2]; bf[2 * p + 1][1] = bq[3];
            }
            #pragma unroll
            for (int ma = 0; ma < 4; ma++)
                #pragma unroll
                for (int na = 0; na < 4; na++)
                    mma16(acc[ma][na], af[ma], bf[na]);
        }
        scur = (scur + 1 == 3) ? 0 : scur + 1;
        snxt = (snxt + 1 == 3) ? 0 : snxt + 1;
    }

    #pragma unroll
    for (int ma = 0; ma < 4; ma++) {
        const int r = row0 + wm + ma * 16 + g;
        #pragma unroll
        for (int na = 0; na < 4; na++) {
            const int c = col0 + wn + na * 8 + 2 * t;
            if (HALF_OUT) {
                __half* Ch = (__half*)Cv;
                *(__half2*)&Ch[(size_t)r * 1024 + c]       = __floats2half2_rn(acc[ma][na].x, acc[ma][na].y);
                *(__half2*)&Ch[(size_t)(r + 8) * 1024 + c] = __floats2half2_rn(acc[ma][na].z, acc[ma][na].w);
            } else {
                float* Cf = (float*)Cv;
                const float bx = bias[c], by = bias[c + 1];
                *(float2*)&Cf[(size_t)r * 1024 + c]       = make_float2(acc[ma][na].x + bx, acc[ma][na].y + by);
                *(float2*)&Cf[(size_t)(r + 8) * 1024 + c] = make_float2(acc[ma][na].z + bx, acc[ma][na].w + by);
            }
        }
    }
}

__global__ __launch_bounds__(256, 2) void proj3h_kernel()
{
    const int z = blockIdx.z;
    const __half* A = g_Xh + (size_t)z * Mrows * Dm;
    const __half* Bt = g_Wth + (size_t)z * Dm * Dm;
    __half* C = (z == 0) ? g_Qh : (z == 1) ? g_Kh : g_Vh;
    gemm_h_body<true>(A, Bt, nullptr, C);
}

__global__ __launch_bounds__(256, 2) void outprojh_kernel(
    const float* __restrict__ bo, float* __restrict__ out)
{
    gemm_h_body<false>(g_ctxh, g_Wth + (size_t)3 * Dm * Dm, bo, out);
}

// =====================================================================
// relk: Rt[bh][r][i] = dot(Q[b,i,h*64:], rel_k[r,:])
// =====================================================================
__global__ __launch_bounds__(128) void relk_kernel(const float* __restrict__ rel_k)
{
    __shared__ float4 RK[NR][16];
    const int bh = blockIdx.y;
    const int b = bh >> 4, h = bh & 15;
    const int i0 = blockIdx.x * 128;
    const int tid = threadIdx.x;

    for (int idx = tid; idx < NR * 16; idx += 128)
        RK[idx / 16][idx % 16] = ((const float4*)rel_k)[idx];
    __syncthreads();

    float2 q[32];
    const __half2* qrow = (const __half2*)&g_Qh[(size_t)(b * Sq + i0 + tid) * Dm + h * DK];
    #pragma unroll
    for (int d = 0; d < 32; d++) q[d] = __half22float2(qrow[d]);

    float* outp = &g_Rt[(size_t)bh * NR * Sq + i0 + tid];
    #pragma unroll 1
    for (int r = 0; r < NR; r++) {
        float s = 0.f;
        #pragma unroll
        for (int d = 0; d < 16; d++) {
            float4 rk = RK[r][d];
            s += q[2 * d].x * rk.x + q[2 * d].y * rk.y + q[2 * d + 1].x * rk.z + q[2 * d + 1].y * rk.w;
        }
        outp[(size_t)r * Sq] = s;
    }
}

// =====================================================================
// FUSED scores+softmax: logits live in registers only.
// Block = 32 query rows x 1 head x all 1024 keys. 512 threads (16 warps).
// Rt bias slab staged in smem (65 rows, pitch 144B).
// =====================================================================
#define SMX_K    0          // 1024 x 128B = 131072
#define SMX_Q    131072     // 32 x 128B = 4096
#define SMX_PMAX 135168
#define SMX_PSUM 137216
#define SMX_PLOW 139264
#define SMX_PHI  141312
#define SMX_FMAX 143360
#define SMX_FINV 143488
#define SMX_SW   143616     // [32][128] floats = 16384
#define SMX_RB   160000     // [65] rows x 144B = 9360
#define SMX_SMEM 169360

__global__ __launch_bounds__(512, 1) void scoresmax_kernel()
{
    extern __shared__ char smx[];
    float* pmax = (float*)(smx + SMX_PMAX);
    float* psum = (float*)(smx + SMX_PSUM);
    float* plow = (float*)(smx + SMX_PLOW);
    float* phi  = (float*)(smx + SMX_PHI);
    float* fmax = (float*)(smx + SMX_FMAX);
    float* finv = (float*)(smx + SMX_FINV);
    float* sW   = (float*)(smx + SMX_SW);
    float* Rb   = (float*)(smx + SMX_RB);     // Rb[r*36 + il], il = i - i0

    const int bh = blockIdx.y;
    const int b = bh >> 4, h = bh & 15;
    const int i0 = blockIdx.x * 32;
    const int tid = threadIdx.x;
    const int lane = tid & 31, wp = tid >> 5;
    const int g = lane >> 2, t = lane & 3;

    const uint32_t sbK  = (uint32_t)__cvta_generic_to_shared(smx + SMX_K);
    const uint32_t sbQ  = (uint32_t)__cvta_generic_to_shared(smx + SMX_Q);
    const uint32_t sbRb = (uint32_t)__cvta_generic_to_shared(smx + SMX_RB);

    for (int idx = tid; idx < 32 * 128; idx += 512) sW[idx] = 0.f;

    // stage K: 1024 rows x 128B, swizzled
    for (int id = tid; id < 8192; id += 512) {
        const int row = id >> 3, seg = id & 7;
        const uint32_t dst = sbK + row * 128 + ((seg * 16) ^ ((row & 7) << 4));
        cp16s(dst, &g_Kh[(size_t)(b * Sq + row) * Dm + h * DK + seg * 8]);
    }
    // stage Q: 32 rows x 128B
    if (tid < 256) {
        const int row = tid >> 3, seg = tid & 7;
        const uint32_t dst = sbQ + row * 128 + ((seg * 16) ^ ((row & 7) << 4));
        cp16s(dst, &g_Qh[(size_t)(b * Sq + i0 + row) * Dm + h * DK + seg * 8]);
    }
    // stage Rt slab: 65 rows x 32 floats (128B each), pitch 144B in smem
    // (grid-stride: 520 segments > 512 threads; threads 0..7 also load row 64)
    {
        const float* RtB = &g_Rt[(size_t)bh * NR * Sq + i0];
        for (int id = tid; id < 520; id += 512) {
            const int r = id >> 3, seg = id & 7;
            cp16s(sbRb + (uint32_t)(r * 144 + seg * 16), RtB + (size_t)r * Sq + seg * 4);
        }
    }
    CP_COMMIT(); CP_WAIT0();
    __syncthreads();

    // ---- phase 1: QK^T (dk=64, 4 k-steps) ----
    float4 acc[2][8];
    #pragma unroll
    for (int mt = 0; mt < 2; mt++)
        #pragma unroll
        for (int nt = 0; nt < 8; nt++) acc[mt][nt] = make_float4(0.f, 0.f, 0.f, 0.f);

    const int arow = (lane & 7) + ((lane >> 3) & 1) * 8;
    const int acolsel = (lane >> 4) * 16;
    const int brow7 = lane & 7;
    const int brow = (lane & 7) + ((lane >> 4) << 3);
    const int bcolsel = ((lane >> 3) & 1) * 16;

    #pragma unroll
    for (int ks = 0; ks < 4; ks++) {
        const int kb2 = ks * 32;
        uint32_t af[2][4];
        #pragma unroll
        for (int mt = 0; mt < 2; mt++) {
            const int row = mt * 16 + arow;
            const uint32_t col = (uint32_t)((kb2 + acolsel) ^ ((arow & 7) << 4));
            ldm_x4(af[mt], sbQ + row * 128 + col);
        }
        #pragma unroll
        for (int nt2 = 0; nt2 < 4; nt2++) {
            const int n0 = wp * 64 + nt2 * 16;
            const uint32_t colb = (uint32_t)((kb2 + bcolsel) ^ (brow7 << 4));
            uint32_t bq[4];
            ldm_x4(bq, sbK + (n0 + brow) * 128 + colb);
            uint32_t bf0[2] = { bq[0], bq[1] }, bf1[2] = { bq[2], bq[3] };
            #pragma unroll
            for (int mt = 0; mt < 2; mt++) {
                mma16(acc[mt][2 * nt2],     af[mt], bf0);
                mma16(acc[mt][2 * nt2 + 1], af[mt], bf1);
            }
        }
    }

    // ---- phase 2: bias (from smem slab) + scale + row max ----
    float mxa[2] = { -1e30f, -1e30f }, mxb[2] = { -1e30f, -1e30f };
    #pragma unroll
    for (int mt = 0; mt < 2; mt++) {
        const int ila = mt * 16 + g, ilb = ila + 8;
        const int ia = i0 + ila, ib = i0 + ilb;
        #pragma unroll
        for (int nt = 0; nt < 8; nt++) {
            const int j0 = wp * 64 + nt * 8 + 2 * t;
            float4& a = acc[mt][nt];
            int r0 = j0 - ia;     r0 = (r0 < -32 ? -32 : (r0 > 32 ? 32 : r0)) + 32;
            int r1 = j0 + 1 - ia; r1 = (r1 < -32 ? -32 : (r1 > 32 ? 32 : r1)) + 32;
            int r2 = j0 - ib;     r2 = (r2 < -32 ? -32 : (r2 > 32 ? 32 : r2)) + 32;
            int r3 = j0 + 1 - ib; r3 = (r3 < -32 ? -32 : (r3 > 32 ? 32 : r3)) + 32;
            a.x = a.x * 0.125f + Rb[r0 * 36 + ila];
            a.y = a.y * 0.125f + Rb[r1 * 36 + ila];
            a.z = a.z * 0.125f + Rb[r2 * 36 + ilb];
            a.w = a.w * 0.125f + Rb[r3 * 36 + ilb];
            mxa[mt] = fmaxf(mxa[mt], fmaxf(a.x, a.y));
            mxb[mt] = fmaxf(mxb[mt], fmaxf(a.z, a.w));
        }
    }
    #pragma unroll
    for (int o = 1; o <= 2; o <<= 1) {
        #pragma unroll
        for (int mt = 0; mt < 2; mt++) {
            mxa[mt] = fmaxf(mxa[mt], __shfl_xor_sync(0xFFFFFFFFu, mxa[mt], o));
            mxb[mt] = fmaxf(mxb[mt], __shfl_xor_sync(0xFFFFFFFFu, mxb[mt], o));
        }
    }
    if (t == 0) {
        #pragma unroll
        for (int mt = 0; mt < 2; mt++) {
            pmax[(mt * 16 + g) * 16 + wp]     = mxa[mt];
            pmax[(mt * 16 + g + 8) * 16 + wp] = mxb[mt];
        }
    }
    __syncthreads();
    if (tid < 32) {
        float m = -1e30f;
        #pragma unroll
        for (int ww = 0; ww < 16; ww++) m = fmaxf(m, pmax[tid * 16 + ww]);
        fmax[tid] = m;
    }
    __syncthreads();

    // ---- phase 3: exp + partial sums / low / high ----
    float sa[2] = {0.f, 0.f}, sb2[2] = {0.f, 0.f};
    float la[2] = {0.f, 0.f}, lb[2] = {0.f, 0.f};
    float ha[2] = {0.f, 0.f}, hb[2] = {0.f, 0.f};
    #pragma unroll
    for (int mt = 0; mt < 2; mt++) {
        const float ma2 = fmax[mt * 16 + g], mb2 = fmax[mt * 16 + g + 8];
        const int ia = i0 + mt * 16 + g, ib = ia + 8;
        #pragma unroll
        for (int nt = 0; nt < 8; nt++) {
            const int j0 = wp * 64 + nt * 8 + 2 * t;
            float4& a = acc[mt][nt];
            a.x = __expf(a.x - ma2); a.y = __expf(a.y - ma2);
            a.z = __expf(a.z - mb2); a.w = __expf(a.w - mb2);
            sa[mt] += a.x + a.y; sb2[mt] += a.z + a.w;
            const int d0 = j0 - ia, d1 = d0 + 1, d2 = j0 - ib, d3 = d2 + 1;
            if (d0 <= -32) la[mt] += a.x; else if (d0 >= 32) ha[mt] += a.x;
            if (d1 <= -32) la[mt] += a.y; else if (d1 >= 32) ha[mt] += a.y;
            if (d2 <= -32) lb[mt] += a.z; else if (d2 >= 32) hb[mt] += a.z;
            if (d3 <= -32) lb[mt] += a.w; else if (d3 >= 32) hb[mt] += a.w;
        }
    }
    #pragma unroll
    for (int o = 1; o <= 2; o <<= 1) {
        #pragma unroll
        for (int mt = 0; mt < 2; mt++) {
            sa[mt] += __shfl_xor_sync(0xFFFFFFFFu, sa[mt], o);
            sb2[mt] += __shfl_xor_sync(0xFFFFFFFFu, sb2[mt], o);
            la[mt] += __shfl_xor_sync(0xFFFFFFFFu, la[mt], o);
            lb[mt] += __shfl_xor_sync(0xFFFFFFFFu, lb[mt], o);
            ha[mt] += __shfl_xor_sync(0xFFFFFFFFu, ha[mt], o);
            hb[mt] += __shfl_xor_sync(0xFFFFFFFFu, hb[mt], o);
        }
    }
    if (t == 0) {
        #pragma unroll
        for (int mt = 0; mt < 2; mt++) {
            const int ra = (mt * 16 + g) * 16 + wp, rb = (mt * 16 + g + 8) * 16 + wp;
            psum[ra] = sa[mt]; psum[rb] = sb2[mt];
            plow[ra] = la[mt]; plow[rb] = lb[mt];
            phi[ra]  = ha[mt]; phi[rb]  = hb[mt];
        }
    }
    __syncthreads();
    if (tid < 32) {
        float s = 0.f, l = 0.f, hh = 0.f;
        #pragma unroll
        for (int ww = 0; ww < 16; ww++) {
            s += psum[tid * 16 + ww]; l += plow[tid * 16 + ww]; hh += phi[tid * 16 + ww];
        }
        const float inv = 1.f / s;
        finv[tid] = inv;
        sW[tid * 128 + 0]  = l * inv;
        sW[tid * 128 + 64] = hh * inv;
    }
    __syncthreads();

    // ---- phase 4: normalize, store probs, band buckets ----
    #pragma unroll
    for (int mt = 0; mt < 2; mt++) {
        const int ra = mt * 16 + g, rb = ra + 8;
        const int ia = i0 + ra, ib = i0 + rb;
        const float inva = finv[ra], invb = finv[rb];
        __half* rowa = &g_attnh[((size_t)bh * Sq + ia) * Sq];
        __half* rowb2 = &g_attnh[((size_t)bh * Sq + ib) * Sq];
        #pragma unroll
        for (int nt = 0; nt < 8; nt++) {
            const int j0 = wp * 64 + nt * 8 + 2 * t;
            float4& a = acc[mt][nt];
            a.x *= inva; a.y *= inva; a.z *= invb; a.w *= invb;
            *(__half2*)&rowa[j0]  = __floats2half2_rn(a.x, a.y);
            *(__half2*)&rowb2[j0] = __floats2half2_rn(a.z, a.w);
            const int d0 = j0 - ia, d1 = d0 + 1, d2 = j0 - ib, d3 = d2 + 1;
            if (d0 > -32 && d0 < 32) sW[ra * 128 + d0 + 32] = a.x;
            if (d1 > -32 && d1 < 32) sW[ra * 128 + d1 + 32] = a.y;
            if (d2 > -32 && d2 < 32) sW[rb * 128 + d2 + 32] = a.z;
            if (d3 > -32 && d3 < 32) sW[rb * 128 + d3 + 32] = a.w;
        }
    }
    __syncthreads();

    // ---- phase 5: store W ----
    for (int idx = tid; idx < 32 * 128; idx += 512) {
        const int r = idx >> 7, c = idx & 127;
        g_Wh[(size_t)(bh * Sq + i0 + r) * WPAD + c] = __float2half(sW[idx]);
    }
}

// =====================================================================
// FAT kernel: blocks [0,512) run ctx GEMM; blocks [512,2560) run head-mean.
// =====================================================================
struct CtxStage { __half As[128][72]; __half Bs[64][72]; };
#define CTX_STAGE_SZ ((int)sizeof(CtxStage))   // 27648
#define CTX_SMEM (3 * CTX_STAGE_SZ)            // 82944
#define CTX_BLOCKS 512
#define MEAN_BLOCKS 2048

__global__ __launch_bounds__(256, 2) void ctxmean_kernel(float* __restrict__ out_attn)
{
    const int tid = threadIdx.x;

    if (blockIdx.x >= CTX_BLOCKS) {
        // ---------------- mean path ----------------
        const int mb = blockIdx.x - CTX_BLOCKS;
        const size_t idx = (size_t)mb * 256 + tid;
        const size_t per_b = (size_t)Sq * Sq / 8;
        const int b = (int)(idx / per_b);
        const size_t rem = idx % per_b;
        const uint4* base = (const uint4*)(g_attnh + (size_t)b * Hh * Sq * Sq) + rem;

        float s[8] = {0.f, 0.f, 0.f, 0.f, 0.f, 0.f, 0.f, 0.f};
        #pragma unroll
        for (int h2 = 0; h2 < Hh; h2++) {
            const uint4 u = base[(size_t)h2 * per_b];
            float2 f;
            f = __half22float2(*(const __half2*)&u.x); s[0] += f.x; s[1] += f.y;
            f = __half22float2(*(const __half2*)&u.y); s[2] += f.x; s[3] += f.y;
            f = __half22float2(*(const __half2*)&u.z); s[4] += f.x; s[5] += f.y;
            f = __half22float2(*(const __half2*)&u.w); s[6] += f.x; s[7] += f.y;
        }
        float* o = &out_attn[(size_t)b * Sq * Sq + rem * 8];
        const float c = 1.0f / Hh;
        *(float4*)&o[0] = make_float4(s[0] * c, s[1] * c, s[2] * c, s[3] * c);
        *(float4*)&o[4] = make_float4(s[4] * c, s[5] * c, s[6] * c, s[7] * c);
        return;
    }

    // ---------------- ctx path ----------------
    extern __shared__ CtxStage cstages[];
    const int bh = blockIdx.x >> 3;
    const int b = bh >> 4, h = bh & 15;
    const int i0 = (blockIdx.x & 7) * 128;
    const int lane = tid & 31, wid = tid >> 5;
    const int g = lane >> 2, t = lane & 3;
    const int wm = (wid >> 2) * 64;
    const int wn = (wid & 3) * 16;

    const uint32_t sb = (uint32_t)__cvta_generic_to_shared(cstages);
    const uint32_t laneA = (uint32_t)(((lane & 7) + ((lane >> 3) & 1) * 8) * 144 + (lane >> 4) * 16);
    const uint32_t laneBt = (uint32_t)(((lane & 7) + ((lane >> 3) & 1) * 8) * 144 + (lane >> 4) * 16);
    const uint32_t warpA  = (uint32_t)(wm * 144) + laneA;
    const uint32_t warpBt = (uint32_t)(18432 + wn * 2) + laneBt;

    auto issue = [&](int kt, int s) {
        CtxStage& st = cstages[s];
        if (kt < 16) {
            const int kb = kt * 64;
            #pragma unroll
            for (int it = 0; it < 4; it++) {
                const int id = it * 256 + tid;
                const int row = id >> 3, seg = id & 7;
                cp16(&st.As[row][seg * 8],
                     &g_attnh[((size_t)bh * Sq + i0 + row) * Sq + kb + seg * 8]);
            }
            #pragma unroll
            for (int it = 0; it < 2; it++) {
                const int id = it * 256 + tid;
                const int vr = id >> 3, vs = id & 7;
                cp16(&st.Bs[vr][vs * 8],
                     &g_Vh[(size_t)(b * Sq + kb + vr) * Dm + h * DK + vs * 8]);
            }
        } else {
            const int kk = (kt - 16) * 64;
            #pragma unroll
            for (int it = 0; it < 4; it++) {
                const int id = it * 256 + tid;
                const int row = id >> 3, seg = id & 7;
                cp16(&st.As[row][seg * 8],
                     &g_Wh[(size_t)(bh * Sq + i0 + row) * WPAD + kk + seg * 8]);
            }
            #pragma unroll
            for (int it = 0; it < 2; it++) {
                const int id = it * 256 + tid;
                const int vr = id >> 3, vs = id & 7;
                cp16(&st.Bs[vr][vs * 8], &g_relvh[(kk + vr) * DK + vs * 8]);
            }
        }
    };

    float4 acc[4][2];
    #pragma unroll
    for (int i = 0; i < 4; i++)
        #pragma unroll
        for (int j = 0; j < 2; j++) acc[i][j] = make_float4(0.f, 0.f, 0.f, 0.f);

    issue(0, 0); CP_COMMIT();
    issue(1, 1); CP_COMMIT();

    int scur = 0, snxt = 2;
    #pragma unroll 1
    for (int kt = 0; kt < 18; kt++) {
        CP_WAIT1();
        __syncthreads();
        if (kt + 2 < 18) issue(kt + 2, snxt);
        CP_COMMIT();

        const uint32_t stb = sb + scur * CTX_STAGE_SZ;
        #pragma unroll
        for (int ks = 0; ks < 4; ks++) {
            uint32_t af[4][4], bf[2][2];
            #pragma unroll
            for (int ma = 0; ma < 4; ma++)
                ldm_x4(af[ma], stb + warpA + ma * 2304 + ks * 32);
            {
                uint32_t bq[4];
                ldm_x4_t(bq, stb + warpBt + ks * 16 * 144);
                bf[0][0] = bq[0]; bf[0][1] = bq[1]; bf[1][0] = bq[2]; bf[1][1] = bq[3];
            }
            #pragma unroll
            for (int ma = 0; ma < 4; ma++)
                #pragma unroll
                for (int na = 0; na < 2; na++)
                    mma16(acc[ma][na], af[ma], bf[na]);
        }
        scur = (scur + 1 == 3) ? 0 : scur + 1;
        snxt = (snxt + 1 == 3) ? 0 : snxt + 1;
    }

    #pragma unroll
    for (int ma = 0; ma < 4; ma++) {
        const int r = i0 + wm + ma * 16 + g;
        #pragma unroll
        for (int na = 0; na < 2; na++) {
            const int c = wn + na * 8 + 2 * t;
            *(__half2*)&g_ctxh[(size_t)(b * Sq + r) * Dm + h * DK + c] =
                __floats2half2_rn(acc[ma][na].x, acc[ma][na].y);
            *(__half2*)&g_ctxh[(size_t)(b * Sq + r + 8) * Dm + h * DK + c] =
                __floats2half2_rn(acc[ma][na].z, acc[ma][na].w);
        }
    }
}

// ---------------- launch ----------------
extern "C" void kernel_launch(void* const* d_in, const int* in_sizes, int n_in,
                              void* d_out, int out_size)
{
    const float* query = (const float*)d_in[0];
    const float* key   = (const float*)d_in[1];
    const float* value = (const float*)d_in[2];
    const float* Wq    = (const float*)d_in[3];
    const float* Wk    = (const float*)d_in[4];
    const float* Wv    = (const float*)d_in[5];
    const float* Wo    = (const float*)d_in[6];
    const float* bo    = (const float*)d_in[7];
    const float* rel_k = (const float*)d_in[8];
    const float* rel_v = (const float*)d_in[9];

    float* out      = (float*)d_out;                 // [B,S,D]
    float* out_attn = out + (size_t)Bb * Sq * Dm;    // [B,S,S]

    static bool attr_set = false;
    if (!attr_set) {
        cudaFuncSetAttribute(proj3h_kernel,
                             cudaFuncAttributeMaxDynamicSharedMemorySize, PROJ_SMEM);
        cudaFuncSetAttribute(outprojh_kernel,
                             cudaFuncAttributeMaxDynamicSharedMemorySize, PROJ_SMEM);
        cudaFuncSetAttribute(ctxmean_kernel,
                             cudaFuncAttributeMaxDynamicSharedMemorySize, CTX_SMEM);
        cudaFuncSetAttribute(scoresmax_kernel,
                             cudaFuncAttributeMaxDynamicSharedMemorySize, SMX_SMEM);
        attr_set = true;
    }

    // 0. prep: fp16 conversions
    cvt_inputs_kernel<<<dim3(Mrows * Dm / 4 / 256, 3), 256>>>(query, key, value);
    cvt_w_kernel<<<dim3(Dm / 32, Dm / 32, 4), 256>>>(Wq, Wk, Wv, Wo);
    cvt_relv_kernel<<<1, 256>>>(rel_v);

    // 1. projections (fp16 mma + ldmatrix, BK=64)
    proj3h_kernel<<<dim3(Dm / 128, Mrows / 128, 3), 256, PROJ_SMEM>>>();

    // 2. rel_k dot products
    relk_kernel<<<dim3(Sq / 128, BH), 128>>>(rel_k);

    // 3. fused scores + softmax (512 thr; Rt bias staged to smem)
    scoresmax_kernel<<<dim3(Sq / 32, BH), 512, SMX_SMEM>>>();

    // 4+5. FAT kernel: ctx GEMM blocks + head-mean blocks run concurrently
    ctxmean_kernel<<<CTX_BLOCKS + MEAN_BLOCKS, 256, CTX_SMEM>>>(out_attn);

    // 6. output projection + bias (fp16 mma + ldmatrix, BK=64)
    outprojh_kernel<<<dim3(Dm / 128, Mrows / 128), 256, PROJ_SMEM>>>(bo, out);
}